// round 1
// baseline (speedup 1.0000x reference)
#include <cuda_runtime.h>
#include <math.h>

#define Bb 8
#define Ss 1024
#define Hh 1536
#define NHh 8
#define HDd 96
#define AHh 768
#define KW 7
#define IMm 3072
#define Tt (Bb*Ss)

// ---------------- scratch (device globals; no runtime allocation) ----------
__device__ float g_q[Tt*AHh];
__device__ float g_k[Tt*AHh];
__device__ float g_v[Tt*AHh];
__device__ float g_co[Tt*AHh];
__device__ float g_sep[Tt*AHh];
__device__ float g_dconv[Tt*Hh];
__device__ float g_ck[Tt*NHh*KW];
__device__ float g_ctx[Tt*Hh];
__device__ float g_attn[Tt*Hh];
__device__ float g_pre[Tt*Hh];
__device__ float g_inter[Tt*IMm];
__device__ float g_scores[(long long)Bb*NHh*Ss*Ss];
__device__ float g_lo[Tt*Hh];
__device__ float g_pool[Bb*Hh];

// ---------------- generic tiled SGEMM: C = A[MxK] @ B[KxN] (+bias)(+resid)(gelu) ----
#define BM 64
#define BN 64
#define BK 16

__global__ void gemm_nn(const float* __restrict__ A, const float* __restrict__ Bm,
                        const float* __restrict__ bias, const float* __restrict__ resid,
                        float* __restrict__ C, int M, int N, int Kd,
                        int lda, int ldb, int ldc, int gelu)
{
    __shared__ float As[BK][BM + 1];
    __shared__ float Bs[BK][BN + 1];
    int tid = threadIdx.x;
    int tx = tid & 15, ty = tid >> 4;
    int row0 = blockIdx.y * BM, col0 = blockIdx.x * BN;

    float acc[4][4] = {};

    for (int k0 = 0; k0 < Kd; k0 += BK) {
        #pragma unroll
        for (int i = 0; i < 4; i++) {
            int idx = i * 256 + tid;           // 0..1023
            int r = idx >> 4, c = idx & 15;    // r:0..63 c:0..15
            As[c][r] = A[(long long)(row0 + r) * lda + (k0 + c)];
        }
        #pragma unroll
        for (int i = 0; i < 4; i++) {
            int idx = i * 256 + tid;
            int r = idx >> 6, c = idx & 63;    // r:0..15 c:0..63
            int col = col0 + c;
            Bs[r][c] = (col < N) ? Bm[(long long)(k0 + r) * ldb + col] : 0.f;
        }
        __syncthreads();
        #pragma unroll
        for (int kk = 0; kk < BK; kk++) {
            float a[4], b[4];
            #pragma unroll
            for (int i = 0; i < 4; i++) a[i] = As[kk][ty * 4 + i];
            #pragma unroll
            for (int j = 0; j < 4; j++) b[j] = Bs[kk][tx * 4 + j];
            #pragma unroll
            for (int i = 0; i < 4; i++)
                #pragma unroll
                for (int j = 0; j < 4; j++)
                    acc[i][j] = fmaf(a[i], b[j], acc[i][j]);
        }
        __syncthreads();
    }

    #pragma unroll
    for (int i = 0; i < 4; i++) {
        int r = row0 + ty * 4 + i;
        #pragma unroll
        for (int j = 0; j < 4; j++) {
            int c = col0 + tx * 4 + j;
            if (c < N) {
                float v = acc[i][j];
                if (bias)  v += bias[c];
                if (resid) v += resid[(long long)r * ldc + c];
                if (gelu)  v = v * normcdff(v);
                C[(long long)r * ldc + c] = v;
            }
        }
    }
}

// ---------------- attention scores: S[bh,q,k] = scale * q_h . k_h (NT) ----------
__global__ void attn_scores(const float* __restrict__ q, const float* __restrict__ k,
                            float* __restrict__ scores, float scale)
{
    int bh = blockIdx.z;
    int b = bh / NHh, h = bh % NHh;
    const float* Ap = q + (long long)b * Ss * AHh + h * HDd;
    const float* Bp = k + (long long)b * Ss * AHh + h * HDd;

    __shared__ float As[BK][BM + 1];
    __shared__ float Bs[BK][BN + 1];
    int tid = threadIdx.x;
    int tx = tid & 15, ty = tid >> 4;
    int row0 = blockIdx.y * BM, col0 = blockIdx.x * BN;

    float acc[4][4] = {};

    for (int d0 = 0; d0 < HDd; d0 += BK) {
        #pragma unroll
        for (int i = 0; i < 4; i++) {
            int idx = i * 256 + tid;
            int r = idx >> 4, c = idx & 15;
            As[c][r] = Ap[(long long)(row0 + r) * AHh + (d0 + c)];
        }
        #pragma unroll
        for (int i = 0; i < 4; i++) {
            int idx = i * 256 + tid;
            int r = idx >> 4, c = idx & 15;
            Bs[c][r] = Bp[(long long)(col0 + r) * AHh + (d0 + c)];
        }
        __syncthreads();
        #pragma unroll
        for (int kk = 0; kk < BK; kk++) {
            float a[4], b[4];
            #pragma unroll
            for (int i = 0; i < 4; i++) a[i] = As[kk][ty * 4 + i];
            #pragma unroll
            for (int j = 0; j < 4; j++) b[j] = Bs[kk][tx * 4 + j];
            #pragma unroll
            for (int i = 0; i < 4; i++)
                #pragma unroll
                for (int j = 0; j < 4; j++)
                    acc[i][j] = fmaf(a[i], b[j], acc[i][j]);
        }
        __syncthreads();
    }

    float* Cp = scores + (long long)bh * Ss * Ss;
    #pragma unroll
    for (int i = 0; i < 4; i++) {
        int r = row0 + ty * 4 + i;
        #pragma unroll
        for (int j = 0; j < 4; j++) {
            int c = col0 + tx * 4 + j;
            Cp[(long long)r * Ss + c] = acc[i][j] * scale;
        }
    }
}

// ---------------- attention context: ctx[b,q,h*96+d] = probs @ v_h (NN) ------
__global__ void attn_ctx(const float* __restrict__ probs, const float* __restrict__ v,
                         float* __restrict__ ctx)
{
    int bh = blockIdx.z;
    int b = bh / NHh, h = bh % NHh;
    const float* Ap = probs + (long long)bh * Ss * Ss;                 // lda = Ss
    const float* Bp = v + (long long)b * Ss * AHh + h * HDd;           // ldb = AHh
    float* Cp = ctx + (long long)b * Ss * Hh + h * HDd;                // ldc = Hh

    __shared__ float As[BK][BM + 1];
    __shared__ float Bs[BK][BN + 1];
    int tid = threadIdx.x;
    int tx = tid & 15, ty = tid >> 4;
    int row0 = blockIdx.y * BM, col0 = blockIdx.x * BN;

    float acc[4][4] = {};

    for (int k0 = 0; k0 < Ss; k0 += BK) {
        #pragma unroll
        for (int i = 0; i < 4; i++) {
            int idx = i * 256 + tid;
            int r = idx >> 4, c = idx & 15;
            As[c][r] = Ap[(long long)(row0 + r) * Ss + (k0 + c)];
        }
        #pragma unroll
        for (int i = 0; i < 4; i++) {
            int idx = i * 256 + tid;
            int r = idx >> 6, c = idx & 63;
            int col = col0 + c;
            Bs[r][c] = (col < HDd) ? Bp[(long long)(k0 + r) * AHh + col] : 0.f;
        }
        __syncthreads();
        #pragma unroll
        for (int kk = 0; kk < BK; kk++) {
            float a[4], b[4];
            #pragma unroll
            for (int i = 0; i < 4; i++) a[i] = As[kk][ty * 4 + i];
            #pragma unroll
            for (int j = 0; j < 4; j++) b[j] = Bs[kk][tx * 4 + j];
            #pragma unroll
            for (int i = 0; i < 4; i++)
                #pragma unroll
                for (int j = 0; j < 4; j++)
                    acc[i][j] = fmaf(a[i], b[j], acc[i][j]);
        }
        __syncthreads();
    }

    #pragma unroll
    for (int i = 0; i < 4; i++) {
        int r = row0 + ty * 4 + i;
        #pragma unroll
        for (int j = 0; j < 4; j++) {
            int c = col0 + tx * 4 + j;
            if (c < HDd)
                Cp[(long long)r * Hh + c] = acc[i][j];
        }
    }
}

// ---------------- depthwise conv (k=7, same padding) -------------------------
__global__ void dconv_kernel(const float* __restrict__ e, const float* __restrict__ dw)
{
    int i = blockIdx.x * blockDim.x + threadIdx.x;
    if (i >= Tt * Hh) return;
    int c = i % Hh, t = i / Hh;
    int s = t % Ss, b = t / Ss;
    float acc = 0.f;
    #pragma unroll
    for (int j = 0; j < KW; j++) {
        int ss = s + j - 3;
        if (ss >= 0 && ss < Ss)
            acc = fmaf(e[((long long)(b * Ss + ss)) * Hh + c], dw[c * KW + j], acc);
    }
    g_dconv[i] = acc;
}

// ---------------- conv_attn = sep * q (in place into g_sep) -----------------
__global__ void mul_kernel()
{
    int i = blockIdx.x * blockDim.x + threadIdx.x;
    if (i < Tt * AHh) g_sep[i] *= g_q[i];
}

// ---------------- span-kernel softmax over K=7 -------------------------------
__global__ void ck_softmax()
{
    int r = blockIdx.x * blockDim.x + threadIdx.x;
    if (r >= Tt * NHh) return;
    float* p = g_ck + (long long)r * KW;
    float m = p[0];
    #pragma unroll
    for (int j = 1; j < KW; j++) m = fmaxf(m, p[j]);
    float s = 0.f;
    float e[KW];
    #pragma unroll
    for (int j = 0; j < KW; j++) { e[j] = expf(p[j] - m); s += e[j]; }
    float inv = 1.f / s;
    #pragma unroll
    for (int j = 0; j < KW; j++) p[j] = e[j] * inv;
}

// ---------------- dynamic conv heads -> right half of ctx -------------------
__global__ void conv_out_kernel()
{
    int i = blockIdx.x * blockDim.x + threadIdx.x;
    if (i >= Tt * AHh) return;
    int c = i % AHh, t = i / AHh;
    int h = c / HDd;
    int s = t % Ss, b = t / Ss;
    const float* ckp = g_ck + (long long)t * (NHh * KW) + h * KW;
    float acc = 0.f;
    #pragma unroll
    for (int j = 0; j < KW; j++) {
        int ss = s + j - 3;
        if (ss >= 0 && ss < Ss)
            acc = fmaf(g_co[((long long)(b * Ss + ss)) * AHh + c], ckp[j], acc);
    }
    g_ctx[(long long)t * Hh + AHh + c] = acc;
}

// ---------------- row softmax (length n) -------------------------------------
__global__ void softmax_rows(float* __restrict__ p, int n)
{
    long long row = blockIdx.x;
    float* x = p + row * (long long)n;
    __shared__ float red[256];
    int tid = threadIdx.x;
    float m = -3.4e38f;
    for (int i = tid; i < n; i += 256) m = fmaxf(m, x[i]);
    red[tid] = m; __syncthreads();
    for (int o = 128; o > 0; o >>= 1) { if (tid < o) red[tid] = fmaxf(red[tid], red[tid + o]); __syncthreads(); }
    m = red[0]; __syncthreads();
    float s = 0.f;
    for (int i = tid; i < n; i += 256) { float e = expf(x[i] - m); x[i] = e; s += e; }
    red[tid] = s; __syncthreads();
    for (int o = 128; o > 0; o >>= 1) { if (tid < o) red[tid] += red[tid + o]; __syncthreads(); }
    float inv = 1.f / red[0];
    for (int i = tid; i < n; i += 256) x[i] *= inv;
}

// ---------------- two-pass layernorm over H ----------------------------------
__global__ void layernorm(const float* __restrict__ x, const float* __restrict__ g,
                          const float* __restrict__ bb, float* __restrict__ y)
{
    long long row = blockIdx.x;
    const float* p = x + row * Hh;
    __shared__ float red[256];
    int tid = threadIdx.x;
    float s = 0.f;
    for (int i = tid; i < Hh; i += 256) s += p[i];
    red[tid] = s; __syncthreads();
    for (int o = 128; o > 0; o >>= 1) { if (tid < o) red[tid] += red[tid + o]; __syncthreads(); }
    float m = red[0] / Hh; __syncthreads();
    float v = 0.f;
    for (int i = tid; i < Hh; i += 256) { float d = p[i] - m; v += d * d; }
    red[tid] = v; __syncthreads();
    for (int o = 128; o > 0; o >>= 1) { if (tid < o) red[tid] += red[tid + o]; __syncthreads(); }
    float inv = rsqrtf(red[0] / Hh + 1e-12f);
    for (int i = tid; i < Hh; i += 256)
        y[row * Hh + i] = (p[i] - m) * inv * g[i] + bb[i];
}

// ---------------- max pool over sequence -------------------------------------
__global__ void maxpool_kernel()
{
    int i = blockIdx.x * blockDim.x + threadIdx.x;
    if (i >= Bb * Hh) return;
    int c = i % Hh, b = i / Hh;
    float m = -3.4e38f;
    for (int s = 0; s < Ss; s++)
        m = fmaxf(m, g_lo[((long long)(b * Ss + s)) * Hh + c]);
    g_pool[i] = m;
}

// ---------------- decoder: logits[b] = pooled . wd + bd ----------------------
__global__ void decoder_kernel(const float* __restrict__ wd, const float* __restrict__ bd,
                               float* __restrict__ out)
{
    int b = blockIdx.x;
    __shared__ float red[256];
    int tid = threadIdx.x;
    float s = 0.f;
    for (int i = tid; i < Hh; i += 256) s += g_pool[b * Hh + i] * wd[i];
    red[tid] = s; __syncthreads();
    for (int o = 128; o > 0; o >>= 1) { if (tid < o) red[tid] += red[tid + o]; __syncthreads(); }
    if (tid == 0) out[b] = red[0] + bd[0];
}

// =============================================================================
extern "C" void kernel_launch(void* const* d_in, const int* in_sizes, int n_in,
                              void* d_out, int out_size)
{
    const float* embed = (const float*)d_in[0];
    const float* wq  = (const float*)d_in[1];  const float* bq  = (const float*)d_in[2];
    const float* wk  = (const float*)d_in[3];  const float* bk  = (const float*)d_in[4];
    const float* wv  = (const float*)d_in[5];  const float* bv  = (const float*)d_in[6];
    const float* dw  = (const float*)d_in[7];
    const float* pw  = (const float*)d_in[8];  const float* sep_b = (const float*)d_in[9];
    const float* wck = (const float*)d_in[10]; const float* bck = (const float*)d_in[11];
    const float* wco = (const float*)d_in[12]; const float* bco = (const float*)d_in[13];
    const float* wso = (const float*)d_in[14]; const float* bso = (const float*)d_in[15];
    const float* ln1_g = (const float*)d_in[16]; const float* ln1_b = (const float*)d_in[17];
    const float* wi  = (const float*)d_in[18]; const float* bi  = (const float*)d_in[19];
    const float* wo  = (const float*)d_in[20]; const float* bo  = (const float*)d_in[21];
    const float* ln2_g = (const float*)d_in[22]; const float* ln2_b = (const float*)d_in[23];
    const float* wd  = (const float*)d_in[24]; const float* bd  = (const float*)d_in[25];
    float* out = (float*)d_out;

    float *pq, *pk, *pv, *pco, *psep, *pdconv, *pck, *pctx, *pattn, *ppre, *pinter, *pscores, *plo;
    cudaGetSymbolAddress((void**)&pq, g_q);
    cudaGetSymbolAddress((void**)&pk, g_k);
    cudaGetSymbolAddress((void**)&pv, g_v);
    cudaGetSymbolAddress((void**)&pco, g_co);
    cudaGetSymbolAddress((void**)&psep, g_sep);
    cudaGetSymbolAddress((void**)&pdconv, g_dconv);
    cudaGetSymbolAddress((void**)&pck, g_ck);
    cudaGetSymbolAddress((void**)&pctx, g_ctx);
    cudaGetSymbolAddress((void**)&pattn, g_attn);
    cudaGetSymbolAddress((void**)&ppre, g_pre);
    cudaGetSymbolAddress((void**)&pinter, g_inter);
    cudaGetSymbolAddress((void**)&pscores, g_scores);
    cudaGetSymbolAddress((void**)&plo, g_lo);

    dim3 blk(256);
    auto gg = [](int N) { return dim3((N + BN - 1) / BN, Tt / BM); };

    // projections
    gemm_nn<<<gg(AHh), blk>>>(embed, wq, bq, nullptr, pq,  Tt, AHh, Hh, Hh, AHh, AHh, 0);
    gemm_nn<<<gg(AHh), blk>>>(embed, wk, bk, nullptr, pk,  Tt, AHh, Hh, Hh, AHh, AHh, 0);
    gemm_nn<<<gg(AHh), blk>>>(embed, wv, bv, nullptr, pv,  Tt, AHh, Hh, Hh, AHh, AHh, 0);
    gemm_nn<<<gg(AHh), blk>>>(embed, wco, bco, nullptr, pco, Tt, AHh, Hh, Hh, AHh, AHh, 0);

    // separable conv: depthwise then pointwise
    dconv_kernel<<<(Tt * Hh + 255) / 256, blk>>>(embed, dw);
    gemm_nn<<<gg(AHh), blk>>>(pdconv, pw, sep_b, nullptr, psep, Tt, AHh, Hh, Hh, AHh, AHh, 0);

    // span dynamic conv kernels
    mul_kernel<<<(Tt * AHh + 255) / 256, blk>>>();
    gemm_nn<<<gg(NHh * KW), blk>>>(psep, wck, bck, nullptr, pck, Tt, NHh * KW, AHh, AHh, NHh * KW, NHh * KW, 0);
    ck_softmax<<<(Tt * NHh + 255) / 256, blk>>>();
    conv_out_kernel<<<(Tt * AHh + 255) / 256, blk>>>();

    // self attention
    attn_scores<<<dim3(Ss / BN, Ss / BM, Bb * NHh), blk>>>(pq, pk, pscores, rsqrtf((float)HDd));
    softmax_rows<<<Bb * NHh * Ss, blk>>>(pscores, Ss);
    attn_ctx<<<dim3((HDd + BN - 1) / BN, Ss / BM, Bb * NHh), blk>>>(pscores, pv, pctx);

    // self output + LN1
    gemm_nn<<<gg(Hh), blk>>>(pctx, wso, bso, embed, ppre, Tt, Hh, Hh, Hh, Hh, Hh, 0);
    layernorm<<<Tt, blk>>>(ppre, ln1_g, ln1_b, pattn);

    // FFN
    gemm_nn<<<gg(IMm), blk>>>(pattn, wi, bi, nullptr, pinter, Tt, IMm, Hh, Hh, IMm, IMm, 1);
    gemm_nn<<<gg(Hh), blk>>>(pinter, wo, bo, pattn, ppre, Tt, Hh, IMm, IMm, Hh, Hh, 0);
    layernorm<<<Tt, blk>>>(ppre, ln2_g, ln2_b, plo);

    // pool + decode
    maxpool_kernel<<<(Bb * Hh + 255) / 256, blk>>>();
    decoder_kernel<<<Bb, blk>>>(wd, bd, out);
}

// round 3
// speedup vs baseline: 2.5458x; 2.5458x over previous
#include <cuda_runtime.h>
#include <cuda_bf16.h>
#include <math.h>
#include <stdint.h>

#define Bb 8
#define Ss 1024
#define Hh 1536
#define NHh 8
#define HDd 96
#define AHh 768
#define KW 7
#define IMm 3072
#define Tt (Bb*Ss)

typedef __nv_bfloat16 bf16;
typedef __nv_bfloat162 bf162;

// ======================= device scratch (no runtime alloc) ==================
#define DEVARR(ty, nm, sz) __device__ __align__(256) ty nm[sz]
// fp32
DEVARR(float, g_q, Tt*AHh);
DEVARR(float, g_v, Tt*AHh);
DEVARR(float, g_co, Tt*AHh);
DEVARR(float, g_sep, Tt*AHh);
DEVARR(float, g_dconv, Tt*Hh);
DEVARR(float, g_ck, Tt*NHh*KW);
__device__ __align__(256) float g_scores[(long long)Bb*NHh*Ss*Ss];
DEVARR(float, g_ctx, Tt*Hh);
DEVARR(float, g_attn, Tt*Hh);
DEVARR(float, g_pre, Tt*Hh);
DEVARR(float, g_lo, Tt*Hh);
DEVARR(float, g_pool, Bb*Hh);
// bf16 pairs: activations
DEVARR(bf16, g_ehi, Tt*Hh);  DEVARR(bf16, g_elo, Tt*Hh);
DEVARR(bf16, g_qhi, Tt*AHh); DEVARR(bf16, g_qlo, Tt*AHh);
DEVARR(bf16, g_khi, Tt*AHh); DEVARR(bf16, g_klo, Tt*AHh);
DEVARR(bf16, g_vThi, Tt*AHh); DEVARR(bf16, g_vTlo, Tt*AHh);   // [B][AH][S]
DEVARR(bf16, g_dchi, Tt*Hh); DEVARR(bf16, g_dclo, Tt*Hh);
DEVARR(bf16, g_cahi, Tt*AHh); DEVARR(bf16, g_calo, Tt*AHh);
__device__ __align__(256) bf16 g_phi[(long long)Bb*NHh*Ss*Ss];
__device__ __align__(256) bf16 g_plo[(long long)Bb*NHh*Ss*Ss];
DEVARR(bf16, g_cthi, Tt*Hh); DEVARR(bf16, g_ctlo, Tt*Hh);
DEVARR(bf16, g_athi, Tt*Hh); DEVARR(bf16, g_atlo, Tt*Hh);
DEVARR(bf16, g_inhi, Tt*IMm); DEVARR(bf16, g_inlo, Tt*IMm);
// bf16 pairs: transposed weights [N][K]
DEVARR(bf16, g_wqThi, AHh*Hh); DEVARR(bf16, g_wqTlo, AHh*Hh);
DEVARR(bf16, g_wkThi, AHh*Hh); DEVARR(bf16, g_wkTlo, AHh*Hh);
DEVARR(bf16, g_wvThi, AHh*Hh); DEVARR(bf16, g_wvTlo, AHh*Hh);
DEVARR(bf16, g_wcoThi, AHh*Hh); DEVARR(bf16, g_wcoTlo, AHh*Hh);
DEVARR(bf16, g_pwThi, AHh*Hh); DEVARR(bf16, g_pwTlo, AHh*Hh);
DEVARR(bf16, g_wckThi, (NHh*KW)*AHh); DEVARR(bf16, g_wckTlo, (NHh*KW)*AHh);
DEVARR(bf16, g_wsoThi, Hh*Hh); DEVARR(bf16, g_wsoTlo, Hh*Hh);
__device__ __align__(256) bf16 g_wiThi[(long long)IMm*Hh];
__device__ __align__(256) bf16 g_wiTlo[(long long)IMm*Hh];
__device__ __align__(256) bf16 g_woThi[(long long)Hh*IMm];
__device__ __align__(256) bf16 g_woTlo[(long long)Hh*IMm];

// ============================ helpers ====================================
__device__ __forceinline__ uint32_t smem_u32(const void* p) {
    uint32_t a;
    asm("{ .reg .u64 t; cvta.to.shared.u64 t, %1; cvt.u32.u64 %0, t; }" : "=r"(a) : "l"(p));
    return a;
}
__device__ __forceinline__ void cpasync16(uint32_t saddr, const void* g) {
    asm volatile("cp.async.cg.shared.global [%0], [%1], 16;" :: "r"(saddr), "l"(g));
}
__device__ __forceinline__ void ldm_x4(uint32_t* r, uint32_t addr) {
    asm volatile("ldmatrix.sync.aligned.m8n8.x4.shared.b16 {%0,%1,%2,%3}, [%4];"
                 : "=r"(r[0]), "=r"(r[1]), "=r"(r[2]), "=r"(r[3]) : "r"(addr));
}
__device__ __forceinline__ void mma_bf16(float* c, const uint32_t* a, const uint32_t* b) {
    asm volatile("mma.sync.aligned.m16n8k16.row.col.f32.bf16.bf16.f32 "
                 "{%0,%1,%2,%3}, {%4,%5,%6,%7}, {%8,%9}, {%0,%1,%2,%3};"
                 : "+f"(c[0]), "+f"(c[1]), "+f"(c[2]), "+f"(c[3])
                 : "r"(a[0]), "r"(a[1]), "r"(a[2]), "r"(a[3]), "r"(b[0]), "r"(b[1]));
}
__device__ __forceinline__ void split_bf(float v, bf16& h, bf16& l) {
    h = __float2bfloat16(v);
    l = __float2bfloat16(v - __bfloat162float(h));
}

// =================== bf16x3-split mma.sync GEMM ==============================
// D = scale * A @ B^T (+bias)(+resid)(gelu); A:[M,K] bf16 pair, B:[N,K] bf16 pair.
// per-z offsets: off = (z/zdiv)*o + (z%zdiv)*i   (elements)
#define ASTR 40                 // padded bf16 elems per smem row (32 data + 8 pad)
#define TILE_E (128*ASTR)       // elems per tile buffer

__global__ void __launch_bounds__(256)
gemm_bf16s(const bf16* __restrict__ Ahi, const bf16* __restrict__ Alo,
           const bf16* __restrict__ Bhi, const bf16* __restrict__ Blo,
           const float* __restrict__ bias, const float* __restrict__ resid,
           float* __restrict__ Cf, bf16* __restrict__ Chi, bf16* __restrict__ Clo,
           int N, int Kd, int lda, int ldb, int ldc,
           long long oA, long long iA, long long oB, long long iB,
           long long oC, long long iC, int zdiv,
           float scale, int gelu)
{
    __shared__ __align__(16) bf16 sA[2][TILE_E];
    __shared__ __align__(16) bf16 sB[2][TILE_E];

    int tid = threadIdx.x, lane = tid & 31, warp = tid >> 5;
    int wm = warp >> 2, wn = warp & 3;          // 2 x 4 warp grid
    int row0 = blockIdx.y * 128, col0 = blockIdx.x * 128;
    int z = blockIdx.z;
    long long offA = (long long)(z / zdiv) * oA + (long long)(z % zdiv) * iA;
    long long offB = (long long)(z / zdiv) * oB + (long long)(z % zdiv) * iB;
    long long offC = (long long)(z / zdiv) * oC + (long long)(z % zdiv) * iC;
    const bf16* Ah = Ahi + offA; const bf16* Al = Alo + offA;
    const bf16* Bh = Bhi + offB; const bf16* Bl = Blo + offB;

    uint32_t sAu = smem_u32(&sA[0][0]);
    uint32_t sBu = smem_u32(&sB[0][0]);

    // zero-fill B buffers if this tile has invalid (>=N) rows
    if (N - col0 < 128) {
        for (int i = tid; i < 2 * TILE_E; i += 256) ((bf16*)sB)[i] = __float2bfloat16(0.f);
    }
    __syncthreads();

    // per-thread load chunks: 2 x 16B for A, 2 x 16B for B per tile
    int c0i = tid * 2, c1i = tid * 2 + 1;
    int ar0 = c0i >> 2, ac0 = (c0i & 3) * 8;
    int ar1 = c1i >> 2, ac1 = (c1i & 3) * 8;
    int nkb = Kd >> 5;
    int NS = 3 * nkb;

    auto load_tiles = [&](int buf, int s) {
        int term = s / nkb;
        int kk = s - term * nkb;
        const bf16* As = (term == 2) ? Al : Ah;
        const bf16* Bs = (term == 1) ? Bl : Bh;
        int k0 = kk << 5;
        uint32_t sa = sAu + buf * (TILE_E * 2);
        uint32_t sb = sBu + buf * (TILE_E * 2);
        cpasync16(sa + (ar0 * ASTR + ac0) * 2, As + (long long)(row0 + ar0) * lda + k0 + ac0);
        cpasync16(sa + (ar1 * ASTR + ac1) * 2, As + (long long)(row0 + ar1) * lda + k0 + ac1);
        if (col0 + ar0 < N)
            cpasync16(sb + (ar0 * ASTR + ac0) * 2, Bs + (long long)(col0 + ar0) * ldb + k0 + ac0);
        if (col0 + ar1 < N)
            cpasync16(sb + (ar1 * ASTR + ac1) * 2, Bs + (long long)(col0 + ar1) * ldb + k0 + ac1);
    };

    float acc[4][4][4] = {};

    load_tiles(0, 0);
    asm volatile("cp.async.commit_group;");

    for (int s = 0; s < NS; s++) {
        int cur = s & 1;
        if (s + 1 < NS) {
            load_tiles(cur ^ 1, s + 1);
            asm volatile("cp.async.commit_group;");
            asm volatile("cp.async.wait_group 1;");
        } else {
            asm volatile("cp.async.wait_group 0;");
        }
        __syncthreads();

        uint32_t aB = sAu + cur * (TILE_E * 2);
        uint32_t bB = sBu + cur * (TILE_E * 2);
        #pragma unroll
        for (int kf = 0; kf < 2; kf++) {
            uint32_t a[4][4];
            #pragma unroll
            for (int mi = 0; mi < 4; mi++) {
                int arow = wm * 64 + mi * 16 + (lane & 15);
                int acol = ((lane >> 4) << 3) + kf * 16;
                ldm_x4(a[mi], aB + (arow * ASTR + acol) * 2);
            }
            uint32_t b[4][2];
            #pragma unroll
            for (int nq = 0; nq < 2; nq++) {
                int brow = wn * 32 + nq * 16 + ((lane >> 4) & 1) * 8 + (lane & 7);
                int bcol = (((lane >> 3) & 1) << 3) + kf * 16;
                uint32_t r[4];
                ldm_x4(r, bB + (brow * ASTR + bcol) * 2);
                b[nq * 2][0] = r[0]; b[nq * 2][1] = r[1];
                b[nq * 2 + 1][0] = r[2]; b[nq * 2 + 1][1] = r[3];
            }
            #pragma unroll
            for (int mi = 0; mi < 4; mi++)
                #pragma unroll
                for (int ni = 0; ni < 4; ni++)
                    mma_bf16(acc[mi][ni], a[mi], b[ni]);
        }
        __syncthreads();
    }

    // -------- epilogue --------
    int g4 = lane >> 2, t4 = lane & 3;
    #pragma unroll
    for (int mi = 0; mi < 4; mi++) {
        #pragma unroll
        for (int half = 0; half < 2; half++) {
            int r = row0 + wm * 64 + mi * 16 + g4 + half * 8;
            long long crow = offC + (long long)r * ldc;
            #pragma unroll
            for (int ni = 0; ni < 4; ni++) {
                int col = col0 + wn * 32 + ni * 8 + t4 * 2;
                if (col >= N) continue;
                float v0 = acc[mi][ni][half * 2 + 0] * scale;
                float v1 = acc[mi][ni][half * 2 + 1] * scale;
                if (bias) {
                    float2 bb = *(const float2*)(bias + col);
                    v0 += bb.x; v1 += bb.y;
                }
                if (resid) {
                    float2 rr = *(const float2*)(resid + crow + col);
                    v0 += rr.x; v1 += rr.y;
                }
                if (gelu) { v0 *= normcdff(v0); v1 *= normcdff(v1); }
                if (Cf) *(float2*)(Cf + crow + col) = make_float2(v0, v1);
                if (Chi) {
                    bf16 h0, h1, l0, l1;
                    split_bf(v0, h0, l0); split_bf(v1, h1, l1);
                    bf162 hp; hp.x = h0; hp.y = h1;
                    bf162 lp; lp.x = l0; lp.y = l1;
                    *(bf162*)(Chi + crow + col) = hp;
                    *(bf162*)(Clo + crow + col) = lp;
                }
            }
        }
    }
}

// ===================== conversion / transpose kernels ========================
__global__ void cvt_pair(const float* __restrict__ x, bf16* __restrict__ hi,
                         bf16* __restrict__ lo, long long n)
{
    long long i = ((long long)blockIdx.x * 256 + threadIdx.x) * 4;
    if (i >= n) return;
    float4 v = *(const float4*)(x + i);
    bf16 h0, h1, h2, h3, l0, l1, l2, l3;
    split_bf(v.x, h0, l0); split_bf(v.y, h1, l1);
    split_bf(v.z, h2, l2); split_bf(v.w, h3, l3);
    bf162 a; a.x = h0; a.y = h1;
    bf162 b; b.x = h2; b.y = h3;
    bf162 c; c.x = l0; c.y = l1;
    bf162 d; d.x = l2; d.y = l3;
    *(bf162*)(hi + i) = a; *(bf162*)(hi + i + 2) = b;
    *(bf162*)(lo + i) = c; *(bf162*)(lo + i + 2) = d;
}

// src [R,C] f32 (+z*sSrc) -> dst [C,R] bf16 pair (+z*sDst)
__global__ void transpose_cvt(const float* __restrict__ src, bf16* __restrict__ hiT,
                              bf16* __restrict__ loT, int R, int C,
                              long long sSrc, long long sDst)
{
    __shared__ float t[32][33];
    src += (long long)blockIdx.z * sSrc;
    hiT += (long long)blockIdx.z * sDst;
    loT += (long long)blockIdx.z * sDst;
    int r0 = blockIdx.y * 32, c0 = blockIdx.x * 32;
    #pragma unroll
    for (int j = 0; j < 4; j++) {
        int rr = r0 + threadIdx.y + j * 8, cc = c0 + threadIdx.x;
        t[threadIdx.y + j * 8][threadIdx.x] =
            (rr < R && cc < C) ? src[(long long)rr * C + cc] : 0.f;
    }
    __syncthreads();
    #pragma unroll
    for (int j = 0; j < 4; j++) {
        int cc = c0 + threadIdx.y + j * 8, rr = r0 + threadIdx.x;
        if (cc < C && rr < R) {
            float v = t[threadIdx.x][threadIdx.y + j * 8];
            bf16 h, l; split_bf(v, h, l);
            hiT[(long long)cc * R + rr] = h;
            loT[(long long)cc * R + rr] = l;
        }
    }
}

// conv_attn = sep * q, emitted directly as bf16 pair
__global__ void mul_cvt()
{
    long long i = ((long long)blockIdx.x * 256 + threadIdx.x) * 4;
    if (i >= (long long)Tt * AHh) return;
    float4 s = *(const float4*)(g_sep + i);
    float4 q = *(const float4*)(g_q + i);
    float m0 = s.x * q.x, m1 = s.y * q.y, m2 = s.z * q.z, m3 = s.w * q.w;
    bf16 h0, h1, h2, h3, l0, l1, l2, l3;
    split_bf(m0, h0, l0); split_bf(m1, h1, l1);
    split_bf(m2, h2, l2); split_bf(m3, h3, l3);
    bf162 a; a.x = h0; a.y = h1;
    bf162 b; b.x = h2; b.y = h3;
    bf162 c; c.x = l0; c.y = l1;
    bf162 d; d.x = l2; d.y = l3;
    *(bf162*)(g_cahi + i) = a; *(bf162*)(g_cahi + i + 2) = b;
    *(bf162*)(g_calo + i) = c; *(bf162*)(g_calo + i + 2) = d;
}

// ======================= elementwise / reduction kernels =====================
__global__ void dconv_kernel(const float* __restrict__ e, const float* __restrict__ dw)
{
    int i = blockIdx.x * blockDim.x + threadIdx.x;
    if (i >= Tt * Hh) return;
    int c = i % Hh, t = i / Hh;
    int s = t % Ss, b = t / Ss;
    float acc = 0.f;
    #pragma unroll
    for (int j = 0; j < KW; j++) {
        int ss = s + j - 3;
        if (ss >= 0 && ss < Ss)
            acc = fmaf(e[((long long)(b * Ss + ss)) * Hh + c], dw[c * KW + j], acc);
    }
    g_dconv[i] = acc;
}

__global__ void ck_softmax()
{
    int r = blockIdx.x * blockDim.x + threadIdx.x;
    if (r >= Tt * NHh) return;
    float* p = g_ck + (long long)r * KW;
    float m = p[0];
    #pragma unroll
    for (int j = 1; j < KW; j++) m = fmaxf(m, p[j]);
    float s = 0.f, e[KW];
    #pragma unroll
    for (int j = 0; j < KW; j++) { e[j] = expf(p[j] - m); s += e[j]; }
    float inv = 1.f / s;
    #pragma unroll
    for (int j = 0; j < KW; j++) p[j] = e[j] * inv;
}

__global__ void conv_out_kernel()
{
    int i = blockIdx.x * blockDim.x + threadIdx.x;
    if (i >= Tt * AHh) return;
    int c = i % AHh, t = i / AHh;
    int h = c / HDd;
    int s = t % Ss, b = t / Ss;
    const float* ckp = g_ck + (long long)t * (NHh * KW) + h * KW;
    float acc = 0.f;
    #pragma unroll
    for (int j = 0; j < KW; j++) {
        int ss = s + j - 3;
        if (ss >= 0 && ss < Ss)
            acc = fmaf(g_co[((long long)(b * Ss + ss)) * AHh + c], ckp[j], acc);
    }
    g_ctx[(long long)t * Hh + AHh + c] = acc;
}

// softmax over rows of length n; emits bf16 pair
__global__ void softmax_rows(float* __restrict__ p, bf16* __restrict__ hi,
                             bf16* __restrict__ lo, int n)
{
    long long row = blockIdx.x;
    float* x = p + row * (long long)n;
    bf16* ho = hi + row * (long long)n;
    bf16* lo_ = lo + row * (long long)n;
    __shared__ float red[256];
    int tid = threadIdx.x;
    float m = -3.4e38f;
    for (int i = tid; i < n; i += 256) m = fmaxf(m, x[i]);
    red[tid] = m; __syncthreads();
    for (int o = 128; o > 0; o >>= 1) { if (tid < o) red[tid] = fmaxf(red[tid], red[tid + o]); __syncthreads(); }
    m = red[0]; __syncthreads();
    float s = 0.f;
    for (int i = tid; i < n; i += 256) { float e = expf(x[i] - m); x[i] = e; s += e; }
    red[tid] = s; __syncthreads();
    for (int o = 128; o > 0; o >>= 1) { if (tid < o) red[tid] += red[tid + o]; __syncthreads(); }
    float inv = 1.f / red[0];
    for (int i = tid; i < n; i += 256) {
        float v = x[i] * inv;
        bf16 h, l; split_bf(v, h, l);
        ho[i] = h; lo_[i] = l;
    }
}

__global__ void layernorm(const float* __restrict__ x, const float* __restrict__ g,
                          const float* __restrict__ bb, float* __restrict__ y,
                          bf16* __restrict__ hi, bf16* __restrict__ lo)
{
    long long row = blockIdx.x;
    const float* p = x + row * Hh;
    __shared__ float red[256];
    int tid = threadIdx.x;
    float s = 0.f;
    for (int i = tid; i < Hh; i += 256) s += p[i];
    red[tid] = s; __syncthreads();
    for (int o = 128; o > 0; o >>= 1) { if (tid < o) red[tid] += red[tid + o]; __syncthreads(); }
    float m = red[0] / Hh; __syncthreads();
    float v = 0.f;
    for (int i = tid; i < Hh; i += 256) { float d = p[i] - m; v += d * d; }
    red[tid] = v; __syncthreads();
    for (int o = 128; o > 0; o >>= 1) { if (tid < o) red[tid] += red[tid + o]; __syncthreads(); }
    float inv = rsqrtf(red[0] / Hh + 1e-12f);
    for (int i = tid; i < Hh; i += 256) {
        float o = (p[i] - m) * inv * g[i] + bb[i];
        y[row * Hh + i] = o;
        if (hi) { bf16 h, l; split_bf(o, h, l); hi[row * Hh + i] = h; lo[row * Hh + i] = l; }
    }
}

__global__ void maxpool_kernel()
{
    int i = blockIdx.x * blockDim.x + threadIdx.x;
    if (i >= Bb * Hh) return;
    int c = i % Hh, b = i / Hh;
    float m = -3.4e38f;
    for (int s = 0; s < Ss; s++)
        m = fmaxf(m, g_lo[((long long)(b * Ss + s)) * Hh + c]);
    g_pool[i] = m;
}

__global__ void decoder_kernel(const float* __restrict__ wd, const float* __restrict__ bd,
                               float* __restrict__ out)
{
    int b = blockIdx.x;
    __shared__ float red[256];
    int tid = threadIdx.x;
    float s = 0.f;
    for (int i = tid; i < Hh; i += 256) s += g_pool[b * Hh + i] * wd[i];
    red[tid] = s; __syncthreads();
    for (int o = 128; o > 0; o >>= 1) { if (tid < o) red[tid] += red[tid + o]; __syncthreads(); }
    if (tid == 0) out[b] = red[0] + bd[0];
}

// =============================================================================
extern "C" void kernel_launch(void* const* d_in, const int* in_sizes, int n_in,
                              void* d_out, int out_size)
{
    const float* embed = (const float*)d_in[0];
    const float* wq  = (const float*)d_in[1];  const float* bq  = (const float*)d_in[2];
    const float* wk  = (const float*)d_in[3];  const float* bk  = (const float*)d_in[4];
    const float* wv  = (const float*)d_in[5];  const float* bv  = (const float*)d_in[6];
    const float* dw  = (const float*)d_in[7];
    const float* pw  = (const float*)d_in[8];  const float* sep_b = (const float*)d_in[9];
    const float* wck = (const float*)d_in[10]; const float* bck = (const float*)d_in[11];
    const float* wco = (const float*)d_in[12]; const float* bco = (const float*)d_in[13];
    const float* wso = (const float*)d_in[14]; const float* bso = (const float*)d_in[15];
    const float* ln1_g = (const float*)d_in[16]; const float* ln1_b = (const float*)d_in[17];
    const float* wi  = (const float*)d_in[18]; const float* bi  = (const float*)d_in[19];
    const float* wo  = (const float*)d_in[20]; const float* bo  = (const float*)d_in[21];
    const float* ln2_g = (const float*)d_in[22]; const float* ln2_b = (const float*)d_in[23];
    const float* wd  = (const float*)d_in[24]; const float* bd  = (const float*)d_in[25];
    float* out = (float*)d_out;

    // symbol addresses
    #define SYM(p, s) void* p##_; cudaGetSymbolAddress(&p##_, s); auto p = (decltype(&s[0]))p##_
    SYM(pq, g_q); SYM(pv, g_v); SYM(pco, g_co); SYM(psep, g_sep); SYM(pdc, g_dconv);
    SYM(pck, g_ck); SYM(psc, g_scores); SYM(pctx, g_ctx); SYM(pattn, g_attn);
    SYM(ppre, g_pre); SYM(plo, g_lo); SYM(ppool, g_pool);
    SYM(ehi, g_ehi); SYM(elo, g_elo);
    SYM(qhi, g_qhi); SYM(qlo, g_qlo); SYM(khi, g_khi); SYM(klo, g_klo);
    SYM(vThi, g_vThi); SYM(vTlo, g_vTlo);
    SYM(dchi, g_dchi); SYM(dclo, g_dclo);
    SYM(cahi, g_cahi); SYM(calo, g_calo);
    SYM(phi, g_phi); SYM(plo2, g_plo);
    SYM(cthi, g_cthi); SYM(ctlo, g_ctlo);
    SYM(athi, g_athi); SYM(atlo, g_atlo);
    SYM(inhi, g_inhi); SYM(inlo, g_inlo);
    SYM(wqThi, g_wqThi); SYM(wqTlo, g_wqTlo);
    SYM(wkThi, g_wkThi); SYM(wkTlo, g_wkTlo);
    SYM(wvThi, g_wvThi); SYM(wvTlo, g_wvTlo);
    SYM(wcoThi, g_wcoThi); SYM(wcoTlo, g_wcoTlo);
    SYM(pwThi, g_pwThi); SYM(pwTlo, g_pwTlo);
    SYM(wckThi, g_wckThi); SYM(wckTlo, g_wckTlo);
    SYM(wsoThi, g_wsoThi); SYM(wsoTlo, g_wsoTlo);
    SYM(wiThi, g_wiThi); SYM(wiTlo, g_wiTlo);
    SYM(woThi, g_woThi); SYM(woTlo, g_woTlo);
    #undef SYM

    dim3 blk(256);
    auto gemm = [&](const bf16* Ah, const bf16* Al, const bf16* Bh, const bf16* Bl,
                    const float* bias, const float* resid,
                    float* Cf, bf16* Chi, bf16* Clo,
                    int M, int N, int K, int lda, int ldb, int ldc,
                    long long oA, long long iA, long long oB, long long iB,
                    long long oC, long long iC, int zdiv, int z,
                    float scale, int gelu) {
        dim3 grid((N + 127) / 128, M / 128, z);
        gemm_bf16s<<<grid, blk>>>(Ah, Al, Bh, Bl, bias, resid, Cf, Chi, Clo,
                                  N, K, lda, ldb, ldc, oA, iA, oB, iB, oC, iC,
                                  zdiv, scale, gelu);
    };
    auto tcvt = [&](const float* src, bf16* hiT, bf16* loT, int R, int C, long long sS, long long sD, int z) {
        dim3 g((C + 31) / 32, (R + 31) / 32, z);
        transpose_cvt<<<g, dim3(32, 8)>>>(src, hiT, loT, R, C, sS, sD);
    };

    // ---- conversions: inputs -> bf16 pairs -------------------------------
    cvt_pair<<<(Tt * Hh) / 1024, blk>>>(embed, ehi, elo, (long long)Tt * Hh);
    tcvt(wq, wqThi, wqTlo, Hh, AHh, 0, 0, 1);
    tcvt(wk, wkThi, wkTlo, Hh, AHh, 0, 0, 1);
    tcvt(wv, wvThi, wvTlo, Hh, AHh, 0, 0, 1);
    tcvt(wco, wcoThi, wcoTlo, Hh, AHh, 0, 0, 1);
    tcvt(pw, pwThi, pwTlo, Hh, AHh, 0, 0, 1);
    tcvt(wck, wckThi, wckTlo, AHh, NHh * KW, 0, 0, 1);
    tcvt(wso, wsoThi, wsoTlo, Hh, Hh, 0, 0, 1);
    tcvt(wi, wiThi, wiTlo, Hh, IMm, 0, 0, 1);
    tcvt(wo, woThi, woTlo, IMm, Hh, 0, 0, 1);

    // ---- projections ------------------------------------------------------
    gemm(ehi, elo, wqThi, wqTlo, bq, nullptr, pq, qhi, qlo,
         Tt, AHh, Hh, Hh, Hh, AHh, 0, 0, 0, 0, 0, 0, 1, 1, 1.f, 0);
    gemm(ehi, elo, wkThi, wkTlo, bk, nullptr, nullptr, khi, klo,
         Tt, AHh, Hh, Hh, Hh, AHh, 0, 0, 0, 0, 0, 0, 1, 1, 1.f, 0);
    gemm(ehi, elo, wvThi, wvTlo, bv, nullptr, pv, nullptr, nullptr,
         Tt, AHh, Hh, Hh, Hh, AHh, 0, 0, 0, 0, 0, 0, 1, 1, 1.f, 0);
    gemm(ehi, elo, wcoThi, wcoTlo, bco, nullptr, pco, nullptr, nullptr,
         Tt, AHh, Hh, Hh, Hh, AHh, 0, 0, 0, 0, 0, 0, 1, 1, 1.f, 0);

    // ---- separable conv ----------------------------------------------------
    dconv_kernel<<<(Tt * Hh + 255) / 256, blk>>>(embed, dw);
    cvt_pair<<<(Tt * Hh) / 1024, blk>>>(pdc, dchi, dclo, (long long)Tt * Hh);
    gemm(dchi, dclo, pwThi, pwTlo, sep_b, nullptr, psep, nullptr, nullptr,
         Tt, AHh, Hh, Hh, Hh, AHh, 0, 0, 0, 0, 0, 0, 1, 1, 1.f, 0);

    // ---- span dynamic conv kernels -----------------------------------------
    mul_cvt<<<(Tt * AHh) / 1024, blk>>>();
    gemm(cahi, calo, wckThi, wckTlo, bck, nullptr, pck, nullptr, nullptr,
         Tt, NHh * KW, AHh, AHh, AHh, NHh * KW, 0, 0, 0, 0, 0, 0, 1, 1, 1.f, 0);
    ck_softmax<<<(Tt * NHh + 255) / 256, blk>>>();
    conv_out_kernel<<<(Tt * AHh + 255) / 256, blk>>>();

    // ---- self attention -----------------------------------------------------
    tcvt(pv, vThi, vTlo, Ss, AHh, (long long)Ss * AHh, (long long)AHh * Ss, Bb);
    gemm(qhi, qlo, khi, klo, nullptr, nullptr, psc, nullptr, nullptr,
         Ss, Ss, HDd, AHh, AHh, Ss,
         (long long)Ss * AHh, HDd, (long long)Ss * AHh, HDd,
         (long long)NHh * Ss * Ss, (long long)Ss * Ss, NHh, Bb * NHh,
         rsqrtf((float)HDd), 0);
    softmax_rows<<<Bb * NHh * Ss, blk>>>(psc, phi, plo2, Ss);
    gemm(phi, plo2, vThi, vTlo, nullptr, nullptr, pctx, nullptr, nullptr,
         Ss, HDd, Ss, Ss, Ss, Hh,
         (long long)NHh * Ss * Ss, (long long)Ss * Ss,
         (long long)AHh * Ss, (long long)HDd * Ss,
         (long long)Ss * Hh, HDd, NHh, Bb * NHh, 1.f, 0);

    // ---- self output + LN1 --------------------------------------------------
    cvt_pair<<<(Tt * Hh) / 1024, blk>>>(pctx, cthi, ctlo, (long long)Tt * Hh);
    gemm(cthi, ctlo, wsoThi, wsoTlo, bso, embed, ppre, nullptr, nullptr,
         Tt, Hh, Hh, Hh, Hh, Hh, 0, 0, 0, 0, 0, 0, 1, 1, 1.f, 0);
    layernorm<<<Tt, blk>>>(ppre, ln1_g, ln1_b, pattn, athi, atlo);

    // ---- FFN ----------------------------------------------------------------
    gemm(athi, atlo, wiThi, wiTlo, bi, nullptr, nullptr, inhi, inlo,
         Tt, IMm, Hh, Hh, Hh, IMm, 0, 0, 0, 0, 0, 0, 1, 1, 1.f, 1);
    gemm(inhi, inlo, woThi, woTlo, bo, pattn, ppre, nullptr, nullptr,
         Tt, Hh, IMm, IMm, IMm, Hh, 0, 0, 0, 0, 0, 0, 1, 1, 1.f, 0);
    layernorm<<<Tt, blk>>>(ppre, ln2_g, ln2_b, plo, nullptr, nullptr);

    // ---- pool + decode ------------------------------------------------------
    maxpool_kernel<<<(Bb * Hh + 255) / 256, blk>>>();
    decoder_kernel<<<Bb, blk>>>(wd, bd, out);
}

// round 4
// speedup vs baseline: 2.6295x; 1.0329x over previous
#include <cuda_runtime.h>
#include <cuda_bf16.h>
#include <math.h>
#include <stdint.h>

#define Bb 8
#define Ss 1024
#define Hh 1536
#define NHh 8
#define HDd 96
#define AHh 768
#define KW 7
#define IMm 3072
#define Tt (Bb*Ss)

typedef __nv_bfloat16 bf16;
typedef __nv_bfloat162 bf162;

// ======================= device scratch (no runtime alloc) ==================
#define DEVARR(ty, nm, sz) __device__ __align__(256) ty nm[sz]
DEVARR(float, g_q, Tt*AHh);
DEVARR(float, g_v, Tt*AHh);
DEVARR(float, g_co, Tt*AHh);
DEVARR(float, g_sep, Tt*AHh);
DEVARR(float, g_dconv, Tt*Hh);
DEVARR(float, g_ck, Tt*NHh*KW);
__device__ __align__(256) float g_scores[(long long)Bb*NHh*Ss*Ss];
DEVARR(float, g_ctx, Tt*Hh);
DEVARR(float, g_attn, Tt*Hh);
DEVARR(float, g_pre, Tt*Hh);
DEVARR(float, g_lo, Tt*Hh);
DEVARR(float, g_pool, Bb*Hh);
DEVARR(bf16, g_ehi, Tt*Hh);  DEVARR(bf16, g_elo, Tt*Hh);
DEVARR(bf16, g_qhi, Tt*AHh); DEVARR(bf16, g_qlo, Tt*AHh);
DEVARR(bf16, g_khi, Tt*AHh); DEVARR(bf16, g_klo, Tt*AHh);
DEVARR(bf16, g_vThi, Tt*AHh); DEVARR(bf16, g_vTlo, Tt*AHh);   // [B][AH][S]
DEVARR(bf16, g_dchi, Tt*Hh); DEVARR(bf16, g_dclo, Tt*Hh);
DEVARR(bf16, g_cahi, Tt*AHh); DEVARR(bf16, g_calo, Tt*AHh);
__device__ __align__(256) bf16 g_phi[(long long)Bb*NHh*Ss*Ss];
__device__ __align__(256) bf16 g_plo[(long long)Bb*NHh*Ss*Ss];
DEVARR(bf16, g_cthi, Tt*Hh); DEVARR(bf16, g_ctlo, Tt*Hh);
DEVARR(bf16, g_athi, Tt*Hh); DEVARR(bf16, g_atlo, Tt*Hh);
DEVARR(bf16, g_inhi, Tt*IMm); DEVARR(bf16, g_inlo, Tt*IMm);
DEVARR(bf16, g_wqThi, AHh*Hh); DEVARR(bf16, g_wqTlo, AHh*Hh);
DEVARR(bf16, g_wkThi, AHh*Hh); DEVARR(bf16, g_wkTlo, AHh*Hh);
DEVARR(bf16, g_wvThi, AHh*Hh); DEVARR(bf16, g_wvTlo, AHh*Hh);
DEVARR(bf16, g_wcoThi, AHh*Hh); DEVARR(bf16, g_wcoTlo, AHh*Hh);
DEVARR(bf16, g_pwThi, AHh*Hh); DEVARR(bf16, g_pwTlo, AHh*Hh);
DEVARR(bf16, g_wckThi, (NHh*KW)*AHh); DEVARR(bf16, g_wckTlo, (NHh*KW)*AHh);
DEVARR(bf16, g_wsoThi, Hh*Hh); DEVARR(bf16, g_wsoTlo, Hh*Hh);
__device__ __align__(256) bf16 g_wiThi[(long long)IMm*Hh];
__device__ __align__(256) bf16 g_wiTlo[(long long)IMm*Hh];
__device__ __align__(256) bf16 g_woThi[(long long)Hh*IMm];
__device__ __align__(256) bf16 g_woTlo[(long long)Hh*IMm];

// ============================ helpers ====================================
__device__ __forceinline__ uint32_t smem_u32(const void* p) {
    uint32_t a;
    asm("{ .reg .u64 t; cvta.to.shared.u64 t, %1; cvt.u32.u64 %0, t; }" : "=r"(a) : "l"(p));
    return a;
}
__device__ __forceinline__ void cpasync16(uint32_t saddr, const void* g) {
    asm volatile("cp.async.cg.shared.global [%0], [%1], 16;" :: "r"(saddr), "l"(g));
}
__device__ __forceinline__ void ldm_x4(uint32_t* r, uint32_t addr) {
    asm volatile("ldmatrix.sync.aligned.m8n8.x4.shared.b16 {%0,%1,%2,%3}, [%4];"
                 : "=r"(r[0]), "=r"(r[1]), "=r"(r[2]), "=r"(r[3]) : "r"(addr));
}
__device__ __forceinline__ void mma_bf16(float* c, const uint32_t* a, const uint32_t* b) {
    asm volatile("mma.sync.aligned.m16n8k16.row.col.f32.bf16.bf16.f32 "
                 "{%0,%1,%2,%3}, {%4,%5,%6,%7}, {%8,%9}, {%0,%1,%2,%3};"
                 : "+f"(c[0]), "+f"(c[1]), "+f"(c[2]), "+f"(c[3])
                 : "r"(a[0]), "r"(a[1]), "r"(a[2]), "r"(a[3]), "r"(b[0]), "r"(b[1]));
}
__device__ __forceinline__ void split_bf(float v, bf16& h, bf16& l) {
    h = __float2bfloat16(v);
    l = __float2bfloat16(v - __bfloat162float(h));
}

// =================== fused bf16x3-split mma.sync GEMM ========================
// D = scale * A @ B^T (+bias)(+resid)(gelu); A:[M,K] bf16 pair, B:[N,K] bf16 pair.
// 3-stage cp.async pipeline; all 3 split terms per k-step.
#define ASTR 40                  // padded bf16 elems per smem row
#define TILE_B (128*ASTR*2)      // bytes per 128x32 tile = 10240
#define STG_B  (4*TILE_B)        // Ahi,Alo,Bhi,Blo per stage = 40960
#define GSMEM  (3*STG_B)         // 122880 bytes

__global__ void __launch_bounds__(256)
gemm_bf16s(const bf16* __restrict__ Ahi, const bf16* __restrict__ Alo,
           const bf16* __restrict__ Bhi, const bf16* __restrict__ Blo,
           const float* __restrict__ bias, const float* __restrict__ resid,
           float* __restrict__ Cf, bf16* __restrict__ Chi, bf16* __restrict__ Clo,
           int N, int Kd, int lda, int ldb, int ldc,
           long long oA, long long iA, long long oB, long long iB,
           long long oC, long long iC, int zdiv,
           float scale, int gelu)
{
    extern __shared__ __align__(16) char dsm[];
    uint32_t s0 = smem_u32(dsm);

    int tid = threadIdx.x, lane = tid & 31, warp = tid >> 5;
    int wm = warp >> 2, wn = warp & 3;          // 2 x 4 warp grid
    int row0 = blockIdx.y * 128, col0 = blockIdx.x * 128;
    int z = blockIdx.z;
    long long offA = (long long)(z / zdiv) * oA + (long long)(z % zdiv) * iA;
    long long offB = (long long)(z / zdiv) * oB + (long long)(z % zdiv) * iB;
    long long offC = (long long)(z / zdiv) * oC + (long long)(z % zdiv) * iC;
    const bf16* Ah = Ahi + offA; const bf16* Al = Alo + offA;
    const bf16* Bh = Bhi + offB; const bf16* Bl = Blo + offB;

    // zero-fill B regions of all stages when tile overhangs N
    if (N - col0 < 128) {
        const uint4 zz = make_uint4(0, 0, 0, 0);
        for (int c = tid; c < 3 * (2 * TILE_B / 16); c += 256) {
            int stg = c / (2 * TILE_B / 16);
            int idx = c % (2 * TILE_B / 16);
            *(uint4*)(dsm + stg * STG_B + 2 * TILE_B + idx * 16) = zz;
        }
        __syncthreads();
    }

    int c0i = tid * 2, c1i = tid * 2 + 1;
    int ar0 = c0i >> 2, ac0 = (c0i & 3) * 8;
    int ar1 = c1i >> 2, ac1 = (c1i & 3) * 8;
    int nkb = Kd >> 5;

    auto ld_stage = [&](int stg, int ks) {
        int k0 = ks << 5;
        uint32_t base = s0 + stg * STG_B;
        long long a0 = (long long)(row0 + ar0) * lda + k0;
        long long a1 = (long long)(row0 + ar1) * lda + k0;
        cpasync16(base + (ar0 * ASTR + ac0) * 2, Ah + a0 + ac0);
        cpasync16(base + (ar1 * ASTR + ac1) * 2, Ah + a1 + ac1);
        cpasync16(base + TILE_B + (ar0 * ASTR + ac0) * 2, Al + a0 + ac0);
        cpasync16(base + TILE_B + (ar1 * ASTR + ac1) * 2, Al + a1 + ac1);
        if (col0 + ar0 < N) {
            long long b0 = (long long)(col0 + ar0) * ldb + k0;
            cpasync16(base + 2 * TILE_B + (ar0 * ASTR + ac0) * 2, Bh + b0 + ac0);
            cpasync16(base + 3 * TILE_B + (ar0 * ASTR + ac0) * 2, Bl + b0 + ac0);
        }
        if (col0 + ar1 < N) {
            long long b1 = (long long)(col0 + ar1) * ldb + k0;
            cpasync16(base + 2 * TILE_B + (ar1 * ASTR + ac1) * 2, Bh + b1 + ac1);
            cpasync16(base + 3 * TILE_B + (ar1 * ASTR + ac1) * 2, Bl + b1 + ac1);
        }
    };

    float acc[4][4][4] = {};

    ld_stage(0, 0);
    asm volatile("cp.async.commit_group;");
    if (nkb > 1) ld_stage(1, 1);
    asm volatile("cp.async.commit_group;");

    for (int s = 0; s < nkb; s++) {
        if (s + 1 < nkb) asm volatile("cp.async.wait_group 1;");
        else             asm volatile("cp.async.wait_group 0;");
        __syncthreads();

        int stg = s % 3;
        uint32_t aH = s0 + stg * STG_B;
        uint32_t aL = aH + TILE_B;
        uint32_t bH = aH + 2 * TILE_B;
        uint32_t bL = aH + 3 * TILE_B;

        #pragma unroll
        for (int kf = 0; kf < 2; kf++) {
            int arow = wm * 64 + (lane & 15);
            int acol = ((lane >> 4) << 3) + kf * 16;
            uint32_t ah[4][4], al[4][4];
            #pragma unroll
            for (int mi = 0; mi < 4; mi++) {
                uint32_t aoff = ((arow + mi * 16) * ASTR + acol) * 2;
                ldm_x4(ah[mi], aH + aoff);
                ldm_x4(al[mi], aL + aoff);
            }
            int brow = wn * 32 + ((lane >> 4) & 1) * 8 + (lane & 7);
            int bcol = (((lane >> 3) & 1) << 3) + kf * 16;
            uint32_t bh[4][2], bl[4][2];
            #pragma unroll
            for (int nq = 0; nq < 2; nq++) {
                uint32_t boff = ((brow + nq * 16) * ASTR + bcol) * 2;
                uint32_t r[4];
                ldm_x4(r, bH + boff);
                bh[nq * 2][0] = r[0]; bh[nq * 2][1] = r[1];
                bh[nq * 2 + 1][0] = r[2]; bh[nq * 2 + 1][1] = r[3];
                ldm_x4(r, bL + boff);
                bl[nq * 2][0] = r[0]; bl[nq * 2][1] = r[1];
                bl[nq * 2 + 1][0] = r[2]; bl[nq * 2 + 1][1] = r[3];
            }
            #pragma unroll
            for (int mi = 0; mi < 4; mi++)
                #pragma unroll
                for (int ni = 0; ni < 4; ni++) {
                    mma_bf16(acc[mi][ni], ah[mi], bh[ni]);
                    mma_bf16(acc[mi][ni], ah[mi], bl[ni]);
                    mma_bf16(acc[mi][ni], al[mi], bh[ni]);
                }
        }
        __syncthreads();
        if (s + 2 < nkb) {
            ld_stage((s + 2) % 3, s + 2);
            asm volatile("cp.async.commit_group;");
        }
    }

    // -------- epilogue --------
    int g4 = lane >> 2, t4 = lane & 3;
    #pragma unroll
    for (int mi = 0; mi < 4; mi++) {
        #pragma unroll
        for (int half = 0; half < 2; half++) {
            int r = row0 + wm * 64 + mi * 16 + g4 + half * 8;
            long long crow = offC + (long long)r * ldc;
            #pragma unroll
            for (int ni = 0; ni < 4; ni++) {
                int col = col0 + wn * 32 + ni * 8 + t4 * 2;
                if (col >= N) continue;
                float v0 = acc[mi][ni][half * 2 + 0] * scale;
                float v1 = acc[mi][ni][half * 2 + 1] * scale;
                if (bias) {
                    float2 bb = *(const float2*)(bias + col);
                    v0 += bb.x; v1 += bb.y;
                }
                if (resid) {
                    float2 rr = *(const float2*)(resid + crow + col);
                    v0 += rr.x; v1 += rr.y;
                }
                if (gelu) { v0 *= normcdff(v0); v1 *= normcdff(v1); }
                if (Cf) *(float2*)(Cf + crow + col) = make_float2(v0, v1);
                if (Chi) {
                    bf16 h0, h1, l0, l1;
                    split_bf(v0, h0, l0); split_bf(v1, h1, l1);
                    bf162 hp; hp.x = h0; hp.y = h1;
                    bf162 lp; lp.x = l0; lp.y = l1;
                    *(bf162*)(Chi + crow + col) = hp;
                    *(bf162*)(Clo + crow + col) = lp;
                }
            }
        }
    }
}

// ===================== conversion / transpose kernels ========================
__global__ void cvt_pair(const float* __restrict__ x, bf16* __restrict__ hi,
                         bf16* __restrict__ lo, long long n)
{
    long long i = ((long long)blockIdx.x * 256 + threadIdx.x) * 4;
    if (i >= n) return;
    float4 v = *(const float4*)(x + i);
    bf16 h0, h1, h2, h3, l0, l1, l2, l3;
    split_bf(v.x, h0, l0); split_bf(v.y, h1, l1);
    split_bf(v.z, h2, l2); split_bf(v.w, h3, l3);
    bf162 a; a.x = h0; a.y = h1;
    bf162 b; b.x = h2; b.y = h3;
    bf162 c; c.x = l0; c.y = l1;
    bf162 d; d.x = l2; d.y = l3;
    *(bf162*)(hi + i) = a; *(bf162*)(hi + i + 2) = b;
    *(bf162*)(lo + i) = c; *(bf162*)(lo + i + 2) = d;
}

__global__ void transpose_cvt(const float* __restrict__ src, bf16* __restrict__ hiT,
                              bf16* __restrict__ loT, int R, int C,
                              long long sSrc, long long sDst)
{
    __shared__ float t[32][33];
    src += (long long)blockIdx.z * sSrc;
    hiT += (long long)blockIdx.z * sDst;
    loT += (long long)blockIdx.z * sDst;
    int r0 = blockIdx.y * 32, c0 = blockIdx.x * 32;
    #pragma unroll
    for (int j = 0; j < 4; j++) {
        int rr = r0 + threadIdx.y + j * 8, cc = c0 + threadIdx.x;
        t[threadIdx.y + j * 8][threadIdx.x] =
            (rr < R && cc < C) ? src[(long long)rr * C + cc] : 0.f;
    }
    __syncthreads();
    #pragma unroll
    for (int j = 0; j < 4; j++) {
        int cc = c0 + threadIdx.y + j * 8, rr = r0 + threadIdx.x;
        if (cc < C && rr < R) {
            float v = t[threadIdx.x][threadIdx.y + j * 8];
            bf16 h, l; split_bf(v, h, l);
            hiT[(long long)cc * R + rr] = h;
            loT[(long long)cc * R + rr] = l;
        }
    }
}

__global__ void mul_cvt()
{
    long long i = ((long long)blockIdx.x * 256 + threadIdx.x) * 4;
    if (i >= (long long)Tt * AHh) return;
    float4 s = *(const float4*)(g_sep + i);
    float4 q = *(const float4*)(g_q + i);
    float m0 = s.x * q.x, m1 = s.y * q.y, m2 = s.z * q.z, m3 = s.w * q.w;
    bf16 h0, h1, h2, h3, l0, l1, l2, l3;
    split_bf(m0, h0, l0); split_bf(m1, h1, l1);
    split_bf(m2, h2, l2); split_bf(m3, h3, l3);
    bf162 a; a.x = h0; a.y = h1;
    bf162 b; b.x = h2; b.y = h3;
    bf162 c; c.x = l0; c.y = l1;
    bf162 d; d.x = l2; d.y = l3;
    *(bf162*)(g_cahi + i) = a; *(bf162*)(g_cahi + i + 2) = b;
    *(bf162*)(g_calo + i) = c; *(bf162*)(g_calo + i + 2) = d;
}

// ======================= elementwise / reduction kernels =====================
__global__ void dconv_kernel(const float* __restrict__ e, const float* __restrict__ dw)
{
    int i = blockIdx.x * blockDim.x + threadIdx.x;
    if (i >= Tt * Hh) return;
    int c = i % Hh, t = i / Hh;
    int s = t % Ss, b = t / Ss;
    float acc = 0.f;
    #pragma unroll
    for (int j = 0; j < KW; j++) {
        int ss = s + j - 3;
        if (ss >= 0 && ss < Ss)
            acc = fmaf(e[((long long)(b * Ss + ss)) * Hh + c], dw[c * KW + j], acc);
    }
    g_dconv[i] = acc;
}

__global__ void ck_softmax()
{
    int r = blockIdx.x * blockDim.x + threadIdx.x;
    if (r >= Tt * NHh) return;
    float* p = g_ck + (long long)r * KW;
    float m = p[0];
    #pragma unroll
    for (int j = 1; j < KW; j++) m = fmaxf(m, p[j]);
    float s = 0.f, e[KW];
    #pragma unroll
    for (int j = 0; j < KW; j++) { e[j] = expf(p[j] - m); s += e[j]; }
    float inv = 1.f / s;
    #pragma unroll
    for (int j = 0; j < KW; j++) p[j] = e[j] * inv;
}

__global__ void conv_out_kernel()
{
    int i = blockIdx.x * blockDim.x + threadIdx.x;
    if (i >= Tt * AHh) return;
    int c = i % AHh, t = i / AHh;
    int h = c / HDd;
    int s = t % Ss, b = t / Ss;
    const float* ckp = g_ck + (long long)t * (NHh * KW) + h * KW;
    float acc = 0.f;
    #pragma unroll
    for (int j = 0; j < KW; j++) {
        int ss = s + j - 3;
        if (ss >= 0 && ss < Ss)
            acc = fmaf(g_co[((long long)(b * Ss + ss)) * AHh + c], ckp[j], acc);
    }
    g_ctx[(long long)t * Hh + AHh + c] = acc;
}

__global__ void softmax_rows(float* __restrict__ p, bf16* __restrict__ hi,
                             bf16* __restrict__ lo, int n)
{
    long long row = blockIdx.x;
    float* x = p + row * (long long)n;
    bf16* ho = hi + row * (long long)n;
    bf16* lo_ = lo + row * (long long)n;
    __shared__ float red[256];
    int tid = threadIdx.x;
    float m = -3.4e38f;
    for (int i = tid; i < n; i += 256) m = fmaxf(m, x[i]);
    red[tid] = m; __syncthreads();
    for (int o = 128; o > 0; o >>= 1) { if (tid < o) red[tid] = fmaxf(red[tid], red[tid + o]); __syncthreads(); }
    m = red[0]; __syncthreads();
    float s = 0.f;
    for (int i = tid; i < n; i += 256) { float e = expf(x[i] - m); x[i] = e; s += e; }
    red[tid] = s; __syncthreads();
    for (int o = 128; o > 0; o >>= 1) { if (tid < o) red[tid] += red[tid + o]; __syncthreads(); }
    float inv = 1.f / red[0];
    for (int i = tid; i < n; i += 256) {
        float v = x[i] * inv;
        bf16 h, l; split_bf(v, h, l);
        ho[i] = h; lo_[i] = l;
    }
}

__global__ void layernorm(const float* __restrict__ x, const float* __restrict__ g,
                          const float* __restrict__ bb, float* __restrict__ y,
                          bf16* __restrict__ hi, bf16* __restrict__ lo)
{
    long long row = blockIdx.x;
    const float* p = x + row * Hh;
    __shared__ float red[256];
    int tid = threadIdx.x;
    float s = 0.f;
    for (int i = tid; i < Hh; i += 256) s += p[i];
    red[tid] = s; __syncthreads();
    for (int o = 128; o > 0; o >>= 1) { if (tid < o) red[tid] += red[tid + o]; __syncthreads(); }
    float m = red[0] / Hh; __syncthreads();
    float v = 0.f;
    for (int i = tid; i < Hh; i += 256) { float d = p[i] - m; v += d * d; }
    red[tid] = v; __syncthreads();
    for (int o = 128; o > 0; o >>= 1) { if (tid < o) red[tid] += red[tid + o]; __syncthreads(); }
    float inv = rsqrtf(red[0] / Hh + 1e-12f);
    for (int i = tid; i < Hh; i += 256) {
        float o = (p[i] - m) * inv * g[i] + bb[i];
        y[row * Hh + i] = o;
        if (hi) { bf16 h, l; split_bf(o, h, l); hi[row * Hh + i] = h; lo[row * Hh + i] = l; }
    }
}

__global__ void maxpool_kernel()
{
    int i = blockIdx.x * blockDim.x + threadIdx.x;
    if (i >= Bb * Hh) return;
    int c = i % Hh, b = i / Hh;
    float m = -3.4e38f;
    for (int s = 0; s < Ss; s++)
        m = fmaxf(m, g_lo[((long long)(b * Ss + s)) * Hh + c]);
    g_pool[i] = m;
}

__global__ void decoder_kernel(const float* __restrict__ wd, const float* __restrict__ bd,
                               float* __restrict__ out)
{
    int b = blockIdx.x;
    __shared__ float red[256];
    int tid = threadIdx.x;
    float s = 0.f;
    for (int i = tid; i < Hh; i += 256) s += g_pool[b * Hh + i] * wd[i];
    red[tid] = s; __syncthreads();
    for (int o = 128; o > 0; o >>= 1) { if (tid < o) red[tid] += red[tid + o]; __syncthreads(); }
    if (tid == 0) out[b] = red[0] + bd[0];
}

// =============================================================================
extern "C" void kernel_launch(void* const* d_in, const int* in_sizes, int n_in,
                              void* d_out, int out_size)
{
    const float* embed = (const float*)d_in[0];
    const float* wq  = (const float*)d_in[1];  const float* bq  = (const float*)d_in[2];
    const float* wk  = (const float*)d_in[3];  const float* bk  = (const float*)d_in[4];
    const float* wv  = (const float*)d_in[5];  const float* bv  = (const float*)d_in[6];
    const float* dw  = (const float*)d_in[7];
    const float* pw  = (const float*)d_in[8];  const float* sep_b = (const float*)d_in[9];
    const float* wck = (const float*)d_in[10]; const float* bck = (const float*)d_in[11];
    const float* wco = (const float*)d_in[12]; const float* bco = (const float*)d_in[13];
    const float* wso = (const float*)d_in[14]; const float* bso = (const float*)d_in[15];
    const float* ln1_g = (const float*)d_in[16]; const float* ln1_b = (const float*)d_in[17];
    const float* wi  = (const float*)d_in[18]; const float* bi  = (const float*)d_in[19];
    const float* wo  = (const float*)d_in[20]; const float* bo  = (const float*)d_in[21];
    const float* ln2_g = (const float*)d_in[22]; const float* ln2_b = (const float*)d_in[23];
    const float* wd  = (const float*)d_in[24]; const float* bd  = (const float*)d_in[25];
    float* out = (float*)d_out;

    cudaFuncSetAttribute(gemm_bf16s, cudaFuncAttributeMaxDynamicSharedMemorySize, GSMEM);

    #define SYM(p, s) void* p##_; cudaGetSymbolAddress(&p##_, s); auto p = (decltype(&s[0]))p##_
    SYM(pq, g_q); SYM(pv, g_v); SYM(pco, g_co); SYM(psep, g_sep); SYM(pdc, g_dconv);
    SYM(pck, g_ck); SYM(psc, g_scores); SYM(pctx, g_ctx); SYM(pattn, g_attn);
    SYM(ppre, g_pre); SYM(plo, g_lo); SYM(ppool, g_pool);
    SYM(ehi, g_ehi); SYM(elo, g_elo);
    SYM(qhi, g_qhi); SYM(qlo, g_qlo); SYM(khi, g_khi); SYM(klo, g_klo);
    SYM(vThi, g_vThi); SYM(vTlo, g_vTlo);
    SYM(dchi, g_dchi); SYM(dclo, g_dclo);
    SYM(cahi, g_cahi); SYM(calo, g_calo);
    SYM(phi, g_phi); SYM(plo2, g_plo);
    SYM(cthi, g_cthi); SYM(ctlo, g_ctlo);
    SYM(athi, g_athi); SYM(atlo, g_atlo);
    SYM(inhi, g_inhi); SYM(inlo, g_inlo);
    SYM(wqThi, g_wqThi); SYM(wqTlo, g_wqTlo);
    SYM(wkThi, g_wkThi); SYM(wkTlo, g_wkTlo);
    SYM(wvThi, g_wvThi); SYM(wvTlo, g_wvTlo);
    SYM(wcoThi, g_wcoThi); SYM(wcoTlo, g_wcoTlo);
    SYM(pwThi, g_pwThi); SYM(pwTlo, g_pwTlo);
    SYM(wckThi, g_wckThi); SYM(wckTlo, g_wckTlo);
    SYM(wsoThi, g_wsoThi); SYM(wsoTlo, g_wsoTlo);
    SYM(wiThi, g_wiThi); SYM(wiTlo, g_wiTlo);
    SYM(woThi, g_woThi); SYM(woTlo, g_woTlo);
    #undef SYM

    dim3 blk(256);
    auto gemm = [&](const bf16* Ah, const bf16* Al, const bf16* Bh, const bf16* Bl,
                    const float* bias, const float* resid,
                    float* Cf, bf16* Chi, bf16* Clo,
                    int M, int N, int K, int lda, int ldb, int ldc,
                    long long oA, long long iA, long long oB, long long iB,
                    long long oC, long long iC, int zdiv, int z,
                    float scale, int gelu) {
        dim3 grid((N + 127) / 128, M / 128, z);
        gemm_bf16s<<<grid, blk, GSMEM>>>(Ah, Al, Bh, Bl, bias, resid, Cf, Chi, Clo,
                                         N, K, lda, ldb, ldc, oA, iA, oB, iB, oC, iC,
                                         zdiv, scale, gelu);
    };
    auto tcvt = [&](const float* src, bf16* hiT, bf16* loT, int R, int C, long long sS, long long sD, int z) {
        dim3 g((C + 31) / 32, (R + 31) / 32, z);
        transpose_cvt<<<g, dim3(32, 8)>>>(src, hiT, loT, R, C, sS, sD);
    };

    // ---- conversions: inputs -> bf16 pairs -------------------------------
    cvt_pair<<<(Tt * Hh) / 1024, blk>>>(embed, ehi, elo, (long long)Tt * Hh);
    tcvt(wq, wqThi, wqTlo, Hh, AHh, 0, 0, 1);
    tcvt(wk, wkThi, wkTlo, Hh, AHh, 0, 0, 1);
    tcvt(wv, wvThi, wvTlo, Hh, AHh, 0, 0, 1);
    tcvt(wco, wcoThi, wcoTlo, Hh, AHh, 0, 0, 1);
    tcvt(pw, pwThi, pwTlo, Hh, AHh, 0, 0, 1);
    tcvt(wck, wckThi, wckTlo, AHh, NHh * KW, 0, 0, 1);
    tcvt(wso, wsoThi, wsoTlo, Hh, Hh, 0, 0, 1);
    tcvt(wi, wiThi, wiTlo, Hh, IMm, 0, 0, 1);
    tcvt(wo, woThi, woTlo, IMm, Hh, 0, 0, 1);

    // ---- projections ------------------------------------------------------
    gemm(ehi, elo, wqThi, wqTlo, bq, nullptr, pq, qhi, qlo,
         Tt, AHh, Hh, Hh, Hh, AHh, 0, 0, 0, 0, 0, 0, 1, 1, 1.f, 0);
    gemm(ehi, elo, wkThi, wkTlo, bk, nullptr, nullptr, khi, klo,
         Tt, AHh, Hh, Hh, Hh, AHh, 0, 0, 0, 0, 0, 0, 1, 1, 1.f, 0);
    gemm(ehi, elo, wvThi, wvTlo, bv, nullptr, pv, nullptr, nullptr,
         Tt, AHh, Hh, Hh, Hh, AHh, 0, 0, 0, 0, 0, 0, 1, 1, 1.f, 0);
    gemm(ehi, elo, wcoThi, wcoTlo, bco, nullptr, pco, nullptr, nullptr,
         Tt, AHh, Hh, Hh, Hh, AHh, 0, 0, 0, 0, 0, 0, 1, 1, 1.f, 0);

    // ---- separable conv ----------------------------------------------------
    dconv_kernel<<<(Tt * Hh + 255) / 256, blk>>>(embed, dw);
    cvt_pair<<<(Tt * Hh) / 1024, blk>>>(pdc, dchi, dclo, (long long)Tt * Hh);
    gemm(dchi, dclo, pwThi, pwTlo, sep_b, nullptr, psep, nullptr, nullptr,
         Tt, AHh, Hh, Hh, Hh, AHh, 0, 0, 0, 0, 0, 0, 1, 1, 1.f, 0);

    // ---- span dynamic conv kernels -----------------------------------------
    mul_cvt<<<(Tt * AHh) / 1024, blk>>>();
    gemm(cahi, calo, wckThi, wckTlo, bck, nullptr, pck, nullptr, nullptr,
         Tt, NHh * KW, AHh, AHh, AHh, NHh * KW, 0, 0, 0, 0, 0, 0, 1, 1, 1.f, 0);
    ck_softmax<<<(Tt * NHh + 255) / 256, blk>>>();
    conv_out_kernel<<<(Tt * AHh + 255) / 256, blk>>>();

    // ---- self attention -----------------------------------------------------
    tcvt(pv, vThi, vTlo, Ss, AHh, (long long)Ss * AHh, (long long)AHh * Ss, Bb);
    gemm(qhi, qlo, khi, klo, nullptr, nullptr, psc, nullptr, nullptr,
         Ss, Ss, HDd, AHh, AHh, Ss,
         (long long)Ss * AHh, HDd, (long long)Ss * AHh, HDd,
         (long long)NHh * Ss * Ss, (long long)Ss * Ss, NHh, Bb * NHh,
         rsqrtf((float)HDd), 0);
    softmax_rows<<<Bb * NHh * Ss, blk>>>(psc, phi, plo2, Ss);
    gemm(phi, plo2, vThi, vTlo, nullptr, nullptr, pctx, nullptr, nullptr,
         Ss, HDd, Ss, Ss, Ss, Hh,
         (long long)NHh * Ss * Ss, (long long)Ss * Ss,
         (long long)AHh * Ss, (long long)HDd * Ss,
         (long long)Ss * Hh, HDd, NHh, Bb * NHh, 1.f, 0);

    // ---- self output + LN1 --------------------------------------------------
    cvt_pair<<<(Tt * Hh) / 1024, blk>>>(pctx, cthi, ctlo, (long long)Tt * Hh);
    gemm(cthi, ctlo, wsoThi, wsoTlo, bso, embed, ppre, nullptr, nullptr,
         Tt, Hh, Hh, Hh, Hh, Hh, 0, 0, 0, 0, 0, 0, 1, 1, 1.f, 0);
    layernorm<<<Tt, blk>>>(ppre, ln1_g, ln1_b, pattn, athi, atlo);

    // ---- FFN ----------------------------------------------------------------
    gemm(athi, atlo, wiThi, wiTlo, bi, nullptr, nullptr, inhi, inlo,
         Tt, IMm, Hh, Hh, Hh, IMm, 0, 0, 0, 0, 0, 0, 1, 1, 1.f, 1);
    gemm(inhi, inlo, woThi, woTlo, bo, pattn, ppre, nullptr, nullptr,
         Tt, Hh, IMm, IMm, IMm, Hh, 0, 0, 0, 0, 0, 0, 1, 1, 1.f, 0);
    layernorm<<<Tt, blk>>>(ppre, ln2_g, ln2_b, plo, nullptr, nullptr);

    // ---- pool + decode ------------------------------------------------------
    maxpool_kernel<<<(Bb * Hh + 255) / 256, blk>>>();
    decoder_kernel<<<Bb, blk>>>(wd, bd, out);
}

// round 5
// speedup vs baseline: 2.8049x; 1.0667x over previous
#include <cuda_runtime.h>
#include <cuda_bf16.h>
#include <math.h>
#include <stdint.h>

#define Bb 8
#define Ss 1024
#define Hh 1536
#define NHh 8
#define HDd 96
#define AHh 768
#define KW 7
#define IMm 3072
#define Tt (Bb*Ss)

typedef __nv_bfloat16 bf16;
typedef __nv_bfloat162 bf162;

#define SLICE ((long long)Tt*AHh)

// ======================= device scratch (no runtime alloc) ==================
#define DEVARR(ty, nm, sz) __device__ __align__(256) ty nm[sz]
DEVARR(float, g_sep, Tt*AHh);
DEVARR(float, g_ck, Tt*NHh*KW);
DEVARR(float, g_attn, Tt*Hh);
DEVARR(float, g_pre, Tt*Hh);
DEVARR(float, g_lo, Tt*Hh);
DEVARR(float, g_pool, Bb*Hh);
// merged q/k/v/co outputs
__device__ __align__(256) float g_p4f[4ll*Tt*AHh];
__device__ __align__(256) bf16 g_p4hi[4ll*Tt*AHh];
__device__ __align__(256) bf16 g_p4lo[4ll*Tt*AHh];
// bf16 pair activations
DEVARR(bf16, g_ehi, Tt*Hh);  DEVARR(bf16, g_elo, Tt*Hh);
DEVARR(bf16, g_vThi, Tt*AHh); DEVARR(bf16, g_vTlo, Tt*AHh);   // [B][AH][S]
DEVARR(bf16, g_dchi, Tt*Hh); DEVARR(bf16, g_dclo, Tt*Hh);
DEVARR(bf16, g_cahi, Tt*AHh); DEVARR(bf16, g_calo, Tt*AHh);
DEVARR(bf16, g_cthi, Tt*Hh); DEVARR(bf16, g_ctlo, Tt*Hh);
DEVARR(bf16, g_athi, Tt*Hh); DEVARR(bf16, g_atlo, Tt*Hh);
DEVARR(bf16, g_inhi, Tt*IMm); DEVARR(bf16, g_inlo, Tt*IMm);
// transposed weights [N][K] bf16 pairs
__device__ __align__(256) bf16 g_w4Thi[4*AHh*Hh];
__device__ __align__(256) bf16 g_w4Tlo[4*AHh*Hh];
DEVARR(bf16, g_pwThi, AHh*Hh); DEVARR(bf16, g_pwTlo, AHh*Hh);
DEVARR(bf16, g_wckThi, (NHh*KW)*AHh); DEVARR(bf16, g_wckTlo, (NHh*KW)*AHh);
DEVARR(bf16, g_wsoThi, Hh*Hh); DEVARR(bf16, g_wsoTlo, Hh*Hh);
__device__ __align__(256) bf16 g_wiThi[(long long)IMm*Hh];
__device__ __align__(256) bf16 g_wiTlo[(long long)IMm*Hh];
__device__ __align__(256) bf16 g_woThi[(long long)Hh*IMm];
__device__ __align__(256) bf16 g_woTlo[(long long)Hh*IMm];

// ============================ helpers ====================================
__device__ __forceinline__ uint32_t smem_u32(const void* p) {
    uint32_t a;
    asm("{ .reg .u64 t; cvta.to.shared.u64 t, %1; cvt.u32.u64 %0, t; }" : "=r"(a) : "l"(p));
    return a;
}
__device__ __forceinline__ void cpasync16(uint32_t saddr, const void* g) {
    asm volatile("cp.async.cg.shared.global [%0], [%1], 16;" :: "r"(saddr), "l"(g));
}
__device__ __forceinline__ void ldm_x4(uint32_t* r, uint32_t addr) {
    asm volatile("ldmatrix.sync.aligned.m8n8.x4.shared.b16 {%0,%1,%2,%3}, [%4];"
                 : "=r"(r[0]), "=r"(r[1]), "=r"(r[2]), "=r"(r[3]) : "r"(addr));
}
__device__ __forceinline__ void mma_bf16(float* c, const uint32_t* a, const uint32_t* b) {
    asm volatile("mma.sync.aligned.m16n8k16.row.col.f32.bf16.bf16.f32 "
                 "{%0,%1,%2,%3}, {%4,%5,%6,%7}, {%8,%9}, {%0,%1,%2,%3};"
                 : "+f"(c[0]), "+f"(c[1]), "+f"(c[2]), "+f"(c[3])
                 : "r"(a[0]), "r"(a[1]), "r"(a[2]), "r"(a[3]), "r"(b[0]), "r"(b[1]));
}
__device__ __forceinline__ void split_bf(float v, bf16& h, bf16& l) {
    h = __float2bfloat16(v);
    l = __float2bfloat16(v - __bfloat162float(h));
}
__device__ __forceinline__ uint32_t pack_bf2(float a, float b) {
    bf162 p; p.x = __float2bfloat16(a); p.y = __float2bfloat16(b);
    return *(uint32_t*)&p;
}

struct Ptr4 { const float* p[4]; };

// =================== fused bf16x3-split mma.sync GEMM ========================
#define ASTR 40
#define TILE_B (128*ASTR*2)      // 10240
#define STG_B  (4*TILE_B)        // 40960
#define GSMEM  (3*STG_B)         // 122880

__global__ void __launch_bounds__(256)
gemm_bf16s(const bf16* __restrict__ Ahi, const bf16* __restrict__ Alo,
           const bf16* __restrict__ Bhi, const bf16* __restrict__ Blo,
           Ptr4 bs, int nbias, const float* __restrict__ resid,
           float* __restrict__ Cf, bf16* __restrict__ Chi, bf16* __restrict__ Clo,
           int N, int Kd, int lda, int ldb, int ldc,
           long long iA, long long iB, long long iC,
           float scale, int gelu)
{
    extern __shared__ __align__(16) char dsm[];
    uint32_t s0 = smem_u32(dsm);

    int tid = threadIdx.x, lane = tid & 31, warp = tid >> 5;
    int wm = warp >> 2, wn = warp & 3;
    int row0 = blockIdx.y * 128, col0 = blockIdx.x * 128;
    int z = blockIdx.z;
    const bf16* Ah = Ahi + (long long)z * iA; const bf16* Al = Alo + (long long)z * iA;
    const bf16* Bh = Bhi + (long long)z * iB; const bf16* Bl = Blo + (long long)z * iB;
    long long offC = (long long)z * iC;
    const float* bias = bs.p[nbias > 1 ? z : 0];

    if (N - col0 < 128) {
        const uint4 zz = make_uint4(0, 0, 0, 0);
        for (int c = tid; c < 3 * (2 * TILE_B / 16); c += 256) {
            int stg = c / (2 * TILE_B / 16);
            int idx = c % (2 * TILE_B / 16);
            *(uint4*)(dsm + stg * STG_B + 2 * TILE_B + idx * 16) = zz;
        }
        __syncthreads();
    }

    int c0i = tid * 2, c1i = tid * 2 + 1;
    int ar0 = c0i >> 2, ac0 = (c0i & 3) * 8;
    int ar1 = c1i >> 2, ac1 = (c1i & 3) * 8;
    int nkb = Kd >> 5;

    auto ld_stage = [&](int stg, int ks) {
        int k0 = ks << 5;
        uint32_t base = s0 + stg * STG_B;
        long long a0 = (long long)(row0 + ar0) * lda + k0;
        long long a1 = (long long)(row0 + ar1) * lda + k0;
        cpasync16(base + (ar0 * ASTR + ac0) * 2, Ah + a0 + ac0);
        cpasync16(base + (ar1 * ASTR + ac1) * 2, Ah + a1 + ac1);
        cpasync16(base + TILE_B + (ar0 * ASTR + ac0) * 2, Al + a0 + ac0);
        cpasync16(base + TILE_B + (ar1 * ASTR + ac1) * 2, Al + a1 + ac1);
        if (col0 + ar0 < N) {
            long long b0 = (long long)(col0 + ar0) * ldb + k0;
            cpasync16(base + 2 * TILE_B + (ar0 * ASTR + ac0) * 2, Bh + b0 + ac0);
            cpasync16(base + 3 * TILE_B + (ar0 * ASTR + ac0) * 2, Bl + b0 + ac0);
        }
        if (col0 + ar1 < N) {
            long long b1 = (long long)(col0 + ar1) * ldb + k0;
            cpasync16(base + 2 * TILE_B + (ar1 * ASTR + ac1) * 2, Bh + b1 + ac1);
            cpasync16(base + 3 * TILE_B + (ar1 * ASTR + ac1) * 2, Bl + b1 + ac1);
        }
    };

    float acc[4][4][4] = {};

    ld_stage(0, 0);
    asm volatile("cp.async.commit_group;");
    if (nkb > 1) ld_stage(1, 1);
    asm volatile("cp.async.commit_group;");

    for (int s = 0; s < nkb; s++) {
        if (s + 1 < nkb) asm volatile("cp.async.wait_group 1;");
        else             asm volatile("cp.async.wait_group 0;");
        __syncthreads();

        int stg = s % 3;
        uint32_t aH = s0 + stg * STG_B;
        uint32_t aL = aH + TILE_B;
        uint32_t bH = aH + 2 * TILE_B;
        uint32_t bL = aH + 3 * TILE_B;

        #pragma unroll
        for (int kf = 0; kf < 2; kf++) {
            int arow = wm * 64 + (lane & 15);
            int acol = ((lane >> 4) << 3) + kf * 16;
            uint32_t ah[4][4], al[4][4];
            #pragma unroll
            for (int mi = 0; mi < 4; mi++) {
                uint32_t aoff = ((arow + mi * 16) * ASTR + acol) * 2;
                ldm_x4(ah[mi], aH + aoff);
                ldm_x4(al[mi], aL + aoff);
            }
            int brow = wn * 32 + ((lane >> 4) & 1) * 8 + (lane & 7);
            int bcol = (((lane >> 3) & 1) << 3) + kf * 16;
            uint32_t bh[4][2], bl[4][2];
            #pragma unroll
            for (int nq = 0; nq < 2; nq++) {
                uint32_t boff = ((brow + nq * 16) * ASTR + bcol) * 2;
                uint32_t r[4];
                ldm_x4(r, bH + boff);
                bh[nq * 2][0] = r[0]; bh[nq * 2][1] = r[1];
                bh[nq * 2 + 1][0] = r[2]; bh[nq * 2 + 1][1] = r[3];
                ldm_x4(r, bL + boff);
                bl[nq * 2][0] = r[0]; bl[nq * 2][1] = r[1];
                bl[nq * 2 + 1][0] = r[2]; bl[nq * 2 + 1][1] = r[3];
            }
            #pragma unroll
            for (int mi = 0; mi < 4; mi++)
                #pragma unroll
                for (int ni = 0; ni < 4; ni++) {
                    mma_bf16(acc[mi][ni], ah[mi], bh[ni]);
                    mma_bf16(acc[mi][ni], ah[mi], bl[ni]);
                    mma_bf16(acc[mi][ni], al[mi], bh[ni]);
                }
        }
        __syncthreads();
        if (s + 2 < nkb) {
            ld_stage((s + 2) % 3, s + 2);
            asm volatile("cp.async.commit_group;");
        }
    }

    int g4 = lane >> 2, t4 = lane & 3;
    #pragma unroll
    for (int mi = 0; mi < 4; mi++) {
        #pragma unroll
        for (int half = 0; half < 2; half++) {
            int r = row0 + wm * 64 + mi * 16 + g4 + half * 8;
            long long crow = offC + (long long)r * ldc;
            #pragma unroll
            for (int ni = 0; ni < 4; ni++) {
                int col = col0 + wn * 32 + ni * 8 + t4 * 2;
                if (col >= N) continue;
                float v0 = acc[mi][ni][half * 2 + 0] * scale;
                float v1 = acc[mi][ni][half * 2 + 1] * scale;
                if (bias) {
                    float2 bb = *(const float2*)(bias + col);
                    v0 += bb.x; v1 += bb.y;
                }
                if (resid) {
                    float2 rr = *(const float2*)(resid + crow + col);
                    v0 += rr.x; v1 += rr.y;
                }
                if (gelu) { v0 *= normcdff(v0); v1 *= normcdff(v1); }
                if (Cf) *(float2*)(Cf + crow + col) = make_float2(v0, v1);
                if (Chi) {
                    bf16 h0, h1, l0, l1;
                    split_bf(v0, h0, l0); split_bf(v1, h1, l1);
                    bf162 hp; hp.x = h0; hp.y = h1;
                    bf162 lp; lp.x = l0; lp.y = l1;
                    *(bf162*)(Chi + crow + col) = hp;
                    *(bf162*)(Clo + crow + col) = lp;
                }
            }
        }
    }
}

// =================== fused flash attention (bf16x3 split) ====================
// grid (8 q-tiles, 64 b*h); 256 threads; out = softmax(QK^T/sqrt(96)) @ V
// K/V streamed in 64-seq chunks, 2-stage cp.async. Output: bf16 pairs into
// ctx left half (ldc = Hh, col base h*96).
#define FA_KSZ 5120              // one [64][40] bf16 subtile
#define FA_VSZ 7680              // one [96][40] bf16 subtile
#define FA_STAGE (6*FA_KSZ + 4*FA_VSZ)   // 61440
#define FA_SMEM (2*FA_STAGE)             // 122880

__global__ void __launch_bounds__(256)
flash_attn(const bf16* __restrict__ Qh, const bf16* __restrict__ Ql,
           const bf16* __restrict__ Kh, const bf16* __restrict__ Kl,
           const bf16* __restrict__ Vth, const bf16* __restrict__ Vtl,
           bf16* __restrict__ Ohi, bf16* __restrict__ Olo)
{
    extern __shared__ __align__(16) char dsm[];
    uint32_t s0 = smem_u32(dsm);
    int tid = threadIdx.x, lane = tid & 31, warp = tid >> 5;
    int q0 = blockIdx.x * 128;
    int bh = blockIdx.y; int b = bh >> 3, h = bh & 7;
    long long qkbase = (long long)b * Ss * AHh + h * HDd;
    long long vbase  = (long long)b * AHh * Ss + (long long)h * HDd * Ss;

    // ---- stage Q (6 subtiles [128][40]) into stage-0 region ----
    #pragma unroll
    for (int i = 0; i < 12; i++) {
        int v = tid + i * 256;
        int sub = v >> 9, idx = v & 511;
        int chunk = sub >> 1, hl = sub & 1;
        int row = idx >> 2, cv = idx & 3;
        const bf16* src = (hl ? Ql : Qh) + qkbase + (long long)(q0 + row) * AHh + chunk * 32 + cv * 8;
        cpasync16(s0 + sub * 10240 + (row * ASTR + cv * 8) * 2, src);
    }
    asm volatile("cp.async.commit_group;");
    asm volatile("cp.async.wait_group 0;");
    __syncthreads();

    // ---- extract Q fragments (each warp: 16 rows) ----
    uint32_t qfh[6][4], qfl[6][4];
    {
        int arow = warp * 16 + (lane & 15);
        int acolb = (lane >> 4) << 3;
        #pragma unroll
        for (int kf = 0; kf < 6; kf++) {
            int chunk = kf >> 1, f = kf & 1;
            uint32_t off = (arow * ASTR + acolb + f * 16) * 2;
            ldm_x4(qfh[kf], s0 + (chunk * 2 + 0) * 10240 + off);
            ldm_x4(qfl[kf], s0 + (chunk * 2 + 1) * 10240 + off);
        }
    }
    __syncthreads();

    auto ld_kv = [&](int stg, int it) {
        int sq = it * 64;
        uint32_t base = s0 + stg * FA_STAGE;
        #pragma unroll
        for (int i = 0; i < 12; i++) {
            int v = tid + i * 256;
            if (v < 1536) {
                int sub = v >> 8, idx = v & 255;
                int hl = sub & 1, chunk = sub >> 1;
                int row = idx >> 2, cv = idx & 3;
                const bf16* src = (hl ? Kl : Kh) + qkbase + (long long)(sq + row) * AHh + chunk * 32 + cv * 8;
                cpasync16(base + sub * FA_KSZ + (row * ASTR + cv * 8) * 2, src);
            } else {
                int v2 = v - 1536;
                int sub = v2 / 384, idx = v2 % 384;
                int hl = sub & 1, chunk = sub >> 1;
                int row = idx >> 2, cv = idx & 3;
                const bf16* src = (hl ? Vtl : Vth) + vbase + (long long)row * Ss + sq + chunk * 32 + cv * 8;
                cpasync16(base + 6 * FA_KSZ + sub * FA_VSZ + (row * ASTR + cv * 8) * 2, src);
            }
        }
    };

    float m_[2] = {-1e30f, -1e30f};
    float l_[2] = {0.f, 0.f};
    float acc_o[12][4] = {};
    const float isq = rsqrtf(96.f);

    ld_kv(0, 0);
    asm volatile("cp.async.commit_group;");
    ld_kv(1, 1);
    asm volatile("cp.async.commit_group;");

    int brow = ((lane >> 4) & 1) * 8 + (lane & 7);
    int bcol = ((lane >> 3) & 1) * 8;

    for (int it = 0; it < 16; it++) {
        if (it + 1 < 16) asm volatile("cp.async.wait_group 1;");
        else             asm volatile("cp.async.wait_group 0;");
        __syncthreads();
        uint32_t kb = s0 + (it & 1) * FA_STAGE;
        uint32_t vb = kb + 6 * FA_KSZ;

        // ---- S = Q K^T (3-term split) ----
        float s_[8][4] = {};
        #pragma unroll
        for (int kf = 0; kf < 6; kf++) {
            int chunk = kf >> 1, f = kf & 1;
            uint32_t bo = (brow * ASTR + bcol + f * 16) * 2;
            #pragma unroll
            for (int nq = 0; nq < 4; nq++) {
                uint32_t rh[4], rl[4];
                ldm_x4(rh, kb + (chunk * 2 + 0) * FA_KSZ + bo + nq * 16 * ASTR * 2);
                ldm_x4(rl, kb + (chunk * 2 + 1) * FA_KSZ + bo + nq * 16 * ASTR * 2);
                mma_bf16(s_[nq * 2],     qfh[kf], rh);
                mma_bf16(s_[nq * 2],     qfh[kf], rl);
                mma_bf16(s_[nq * 2],     qfl[kf], rh);
                mma_bf16(s_[nq * 2 + 1], qfh[kf], rh + 2);
                mma_bf16(s_[nq * 2 + 1], qfh[kf], rl + 2);
                mma_bf16(s_[nq * 2 + 1], qfl[kf], rh + 2);
            }
        }
        #pragma unroll
        for (int ni = 0; ni < 8; ni++)
            #pragma unroll
            for (int j = 0; j < 4; j++) s_[ni][j] *= isq;

        // ---- online softmax (rh=0: regs {0,1}; rh=1: regs {2,3}) ----
        #pragma unroll
        for (int rh = 0; rh < 2; rh++) {
            float mx = -1e30f;
            #pragma unroll
            for (int ni = 0; ni < 8; ni++)
                mx = fmaxf(mx, fmaxf(s_[ni][rh * 2], s_[ni][rh * 2 + 1]));
            mx = fmaxf(mx, __shfl_xor_sync(0xffffffffu, mx, 1));
            mx = fmaxf(mx, __shfl_xor_sync(0xffffffffu, mx, 2));
            float mnew = fmaxf(m_[rh], mx);
            float a = __expf(m_[rh] - mnew);
            m_[rh] = mnew;
            float rs = 0.f;
            #pragma unroll
            for (int ni = 0; ni < 8; ni++) {
                float p0 = __expf(s_[ni][rh * 2] - mnew);
                float p1 = __expf(s_[ni][rh * 2 + 1] - mnew);
                s_[ni][rh * 2] = p0; s_[ni][rh * 2 + 1] = p1;
                rs += p0 + p1;
            }
            rs += __shfl_xor_sync(0xffffffffu, rs, 1);
            rs += __shfl_xor_sync(0xffffffffu, rs, 2);
            l_[rh] = l_[rh] * a + rs;
            #pragma unroll
            for (int ni = 0; ni < 12; ni++) {
                acc_o[ni][rh * 2] *= a; acc_o[ni][rh * 2 + 1] *= a;
            }
        }

        // ---- P -> A fragments (hi/lo) ----
        uint32_t pfh[4][4], pfl[4][4];
        #pragma unroll
        for (int kp = 0; kp < 4; kp++) {
            #pragma unroll
            for (int q = 0; q < 2; q++) {
                int ni = kp * 2 + q;
                float x0 = s_[ni][0], x1 = s_[ni][1], x2 = s_[ni][2], x3 = s_[ni][3];
                bf16 h0, l0, h1, l1, h2, l2, h3, l3;
                split_bf(x0, h0, l0); split_bf(x1, h1, l1);
                split_bf(x2, h2, l2); split_bf(x3, h3, l3);
                bf162 t;
                t.x = h0; t.y = h1; pfh[kp][q * 2 + 0] = *(uint32_t*)&t;
                t.x = h2; t.y = h3; pfh[kp][q * 2 + 1] = *(uint32_t*)&t;
                t.x = l0; t.y = l1; pfl[kp][q * 2 + 0] = *(uint32_t*)&t;
                t.x = l2; t.y = l3; pfl[kp][q * 2 + 1] = *(uint32_t*)&t;
            }
        }

        // ---- O += P V (3-term split) ----
        #pragma unroll
        for (int kp = 0; kp < 4; kp++) {
            int chunk = kp >> 1, f = kp & 1;
            uint32_t bo = (brow * ASTR + bcol + f * 16) * 2;
            #pragma unroll
            for (int nq = 0; nq < 6; nq++) {
                uint32_t rh[4], rl[4];
                ldm_x4(rh, vb + (chunk * 2 + 0) * FA_VSZ + bo + nq * 16 * ASTR * 2);
                ldm_x4(rl, vb + (chunk * 2 + 1) * FA_VSZ + bo + nq * 16 * ASTR * 2);
                mma_bf16(acc_o[nq * 2],     pfh[kp], rh);
                mma_bf16(acc_o[nq * 2],     pfh[kp], rl);
                mma_bf16(acc_o[nq * 2],     pfl[kp], rh);
                mma_bf16(acc_o[nq * 2 + 1], pfh[kp], rh + 2);
                mma_bf16(acc_o[nq * 2 + 1], pfh[kp], rl + 2);
                mma_bf16(acc_o[nq * 2 + 1], pfl[kp], rh + 2);
            }
        }
        __syncthreads();
        if (it + 2 < 16) {
            ld_kv(it & 1, it + 2);
            asm volatile("cp.async.commit_group;");
        }
    }

    // ---- epilogue: out = acc_o / l ----
    int g4 = lane >> 2, t4 = lane & 3;
    #pragma unroll
    for (int rh = 0; rh < 2; rh++) {
        float inv = 1.f / l_[rh];
        int r = q0 + warp * 16 + g4 + rh * 8;
        long long orow = ((long long)b * Ss + r) * Hh + h * HDd;
        #pragma unroll
        for (int ni = 0; ni < 12; ni++) {
            int col = ni * 8 + t4 * 2;
            float v0 = acc_o[ni][rh * 2] * inv;
            float v1 = acc_o[ni][rh * 2 + 1] * inv;
            bf16 h0, l0, h1, l1;
            split_bf(v0, h0, l0); split_bf(v1, h1, l1);
            bf162 hp; hp.x = h0; hp.y = h1;
            bf162 lp; lp.x = l0; lp.y = l1;
            *(bf162*)(Ohi + orow + col) = hp;
            *(bf162*)(Olo + orow + col) = lp;
        }
    }
}

// ===================== conversion / transpose kernels ========================
__global__ void cvt_pair(const float* __restrict__ x, bf16* __restrict__ hi,
                         bf16* __restrict__ lo, long long n)
{
    long long i = ((long long)blockIdx.x * 256 + threadIdx.x) * 4;
    if (i >= n) return;
    float4 v = *(const float4*)(x + i);
    bf16 h0, h1, h2, h3, l0, l1, l2, l3;
    split_bf(v.x, h0, l0); split_bf(v.y, h1, l1);
    split_bf(v.z, h2, l2); split_bf(v.w, h3, l3);
    bf162 a; a.x = h0; a.y = h1;
    bf162 b; b.x = h2; b.y = h3;
    bf162 c; c.x = l0; c.y = l1;
    bf162 d; d.x = l2; d.y = l3;
    *(bf162*)(hi + i) = a; *(bf162*)(hi + i + 2) = b;
    *(bf162*)(lo + i) = c; *(bf162*)(lo + i + 2) = d;
}

__global__ void transpose_cvt(const float* __restrict__ src, bf16* __restrict__ hiT,
                              bf16* __restrict__ loT, int R, int C,
                              long long sSrc, long long sDst)
{
    __shared__ float t[32][33];
    src += (long long)blockIdx.z * sSrc;
    hiT += (long long)blockIdx.z * sDst;
    loT += (long long)blockIdx.z * sDst;
    int r0 = blockIdx.y * 32, c0 = blockIdx.x * 32;
    #pragma unroll
    for (int j = 0; j < 4; j++) {
        int rr = r0 + threadIdx.y + j * 8, cc = c0 + threadIdx.x;
        t[threadIdx.y + j * 8][threadIdx.x] =
            (rr < R && cc < C) ? src[(long long)rr * C + cc] : 0.f;
    }
    __syncthreads();
    #pragma unroll
    for (int j = 0; j < 4; j++) {
        int cc = c0 + threadIdx.y + j * 8, rr = r0 + threadIdx.x;
        if (cc < C && rr < R) {
            float v = t[threadIdx.x][threadIdx.y + j * 8];
            bf16 h, l; split_bf(v, h, l);
            hiT[(long long)cc * R + rr] = h;
            loT[(long long)cc * R + rr] = l;
        }
    }
}

__global__ void mul_cvt(const float* __restrict__ sep, const float* __restrict__ q,
                        bf16* __restrict__ chi, bf16* __restrict__ clo)
{
    long long i = ((long long)blockIdx.x * 256 + threadIdx.x) * 4;
    if (i >= (long long)Tt * AHh) return;
    float4 s = *(const float4*)(sep + i);
    float4 qq = *(const float4*)(q + i);
    float m0 = s.x * qq.x, m1 = s.y * qq.y, m2 = s.z * qq.z, m3 = s.w * qq.w;
    bf16 h0, h1, h2, h3, l0, l1, l2, l3;
    split_bf(m0, h0, l0); split_bf(m1, h1, l1);
    split_bf(m2, h2, l2); split_bf(m3, h3, l3);
    bf162 a; a.x = h0; a.y = h1;
    bf162 b; b.x = h2; b.y = h3;
    bf162 c; c.x = l0; c.y = l1;
    bf162 d; d.x = l2; d.y = l3;
    *(bf162*)(chi + i) = a; *(bf162*)(chi + i + 2) = b;
    *(bf162*)(clo + i) = c; *(bf162*)(clo + i + 2) = d;
}

// ======================= elementwise / reduction kernels =====================
__global__ void dconv_kernel(const float* __restrict__ e, const float* __restrict__ dw,
                             bf16* __restrict__ dh, bf16* __restrict__ dl)
{
    int i = blockIdx.x * blockDim.x + threadIdx.x;
    if (i >= Tt * Hh) return;
    int c = i % Hh, t = i / Hh;
    int s = t % Ss, b = t / Ss;
    float acc = 0.f;
    #pragma unroll
    for (int j = 0; j < KW; j++) {
        int ss = s + j - 3;
        if (ss >= 0 && ss < Ss)
            acc = fmaf(e[((long long)(b * Ss + ss)) * Hh + c], dw[c * KW + j], acc);
    }
    bf16 h, l; split_bf(acc, h, l);
    dh[i] = h; dl[i] = l;
}

__global__ void ck_softmax(float* __restrict__ ck)
{
    int r = blockIdx.x * blockDim.x + threadIdx.x;
    if (r >= Tt * NHh) return;
    float* p = ck + (long long)r * KW;
    float m = p[0];
    #pragma unroll
    for (int j = 1; j < KW; j++) m = fmaxf(m, p[j]);
    float s = 0.f, e[KW];
    #pragma unroll
    for (int j = 0; j < KW; j++) { e[j] = expf(p[j] - m); s += e[j]; }
    float inv = 1.f / s;
    #pragma unroll
    for (int j = 0; j < KW; j++) p[j] = e[j] * inv;
}

__global__ void conv_out_kernel(const float* __restrict__ co, const float* __restrict__ ck,
                                bf16* __restrict__ cthi, bf16* __restrict__ ctlo)
{
    int i = blockIdx.x * blockDim.x + threadIdx.x;
    if (i >= Tt * AHh) return;
    int c = i % AHh, t = i / AHh;
    int h = c / HDd;
    int s = t % Ss, b = t / Ss;
    const float* ckp = ck + (long long)t * (NHh * KW) + h * KW;
    float acc = 0.f;
    #pragma unroll
    for (int j = 0; j < KW; j++) {
        int ss = s + j - 3;
        if (ss >= 0 && ss < Ss)
            acc = fmaf(co[((long long)(b * Ss + ss)) * AHh + c], ckp[j], acc);
    }
    bf16 h_, l_; split_bf(acc, h_, l_);
    cthi[(long long)t * Hh + AHh + c] = h_;
    ctlo[(long long)t * Hh + AHh + c] = l_;
}

__global__ void layernorm(const float* __restrict__ x, const float* __restrict__ g,
                          const float* __restrict__ bb, float* __restrict__ y,
                          bf16* __restrict__ hi, bf16* __restrict__ lo)
{
    long long row = blockIdx.x;
    const float* p = x + row * Hh;
    __shared__ float red[256];
    int tid = threadIdx.x;
    float s = 0.f;
    for (int i = tid; i < Hh; i += 256) s += p[i];
    red[tid] = s; __syncthreads();
    for (int o = 128; o > 0; o >>= 1) { if (tid < o) red[tid] += red[tid + o]; __syncthreads(); }
    float m = red[0] / Hh; __syncthreads();
    float v = 0.f;
    for (int i = tid; i < Hh; i += 256) { float d = p[i] - m; v += d * d; }
    red[tid] = v; __syncthreads();
    for (int o = 128; o > 0; o >>= 1) { if (tid < o) red[tid] += red[tid + o]; __syncthreads(); }
    float inv = rsqrtf(red[0] / Hh + 1e-12f);
    for (int i = tid; i < Hh; i += 256) {
        float o = (p[i] - m) * inv * g[i] + bb[i];
        y[row * Hh + i] = o;
        if (hi) { bf16 h, l; split_bf(o, h, l); hi[row * Hh + i] = h; lo[row * Hh + i] = l; }
    }
}

__global__ void maxpool_kernel()
{
    int i = blockIdx.x * blockDim.x + threadIdx.x;
    if (i >= Bb * Hh) return;
    int c = i % Hh, b = i / Hh;
    float m = -3.4e38f;
    for (int s = 0; s < Ss; s++)
        m = fmaxf(m, g_lo[((long long)(b * Ss + s)) * Hh + c]);
    g_pool[i] = m;
}

__global__ void decoder_kernel(const float* __restrict__ wd, const float* __restrict__ bd,
                               float* __restrict__ out)
{
    int b = blockIdx.x;
    __shared__ float red[256];
    int tid = threadIdx.x;
    float s = 0.f;
    for (int i = tid; i < Hh; i += 256) s += g_pool[b * Hh + i] * wd[i];
    red[tid] = s; __syncthreads();
    for (int o = 128; o > 0; o >>= 1) { if (tid < o) red[tid] += red[tid + o]; __syncthreads(); }
    if (tid == 0) out[b] = red[0] + bd[0];
}

// =============================================================================
extern "C" void kernel_launch(void* const* d_in, const int* in_sizes, int n_in,
                              void* d_out, int out_size)
{
    const float* embed = (const float*)d_in[0];
    const float* wq  = (const float*)d_in[1];  const float* bq  = (const float*)d_in[2];
    const float* wk  = (const float*)d_in[3];  const float* bk  = (const float*)d_in[4];
    const float* wv  = (const float*)d_in[5];  const float* bv  = (const float*)d_in[6];
    const float* dw  = (const float*)d_in[7];
    const float* pw  = (const float*)d_in[8];  const float* sep_b = (const float*)d_in[9];
    const float* wck = (const float*)d_in[10]; const float* bck = (const float*)d_in[11];
    const float* wco = (const float*)d_in[12]; const float* bco = (const float*)d_in[13];
    const float* wso = (const float*)d_in[14]; const float* bso = (const float*)d_in[15];
    const float* ln1_g = (const float*)d_in[16]; const float* ln1_b = (const float*)d_in[17];
    const float* wi  = (const float*)d_in[18]; const float* bi  = (const float*)d_in[19];
    const float* wo  = (const float*)d_in[20]; const float* bo  = (const float*)d_in[21];
    const float* ln2_g = (const float*)d_in[22]; const float* ln2_b = (const float*)d_in[23];
    const float* wd  = (const float*)d_in[24]; const float* bd  = (const float*)d_in[25];
    float* out = (float*)d_out;

    cudaFuncSetAttribute(gemm_bf16s, cudaFuncAttributeMaxDynamicSharedMemorySize, GSMEM);
    cudaFuncSetAttribute(flash_attn, cudaFuncAttributeMaxDynamicSharedMemorySize, FA_SMEM);

    #define SYM(p, s) void* p##_; cudaGetSymbolAddress(&p##_, s); auto p = (decltype(&s[0]))p##_
    SYM(psep, g_sep); SYM(pck, g_ck); SYM(pattn, g_attn);
    SYM(ppre, g_pre); SYM(plo, g_lo);
    SYM(p4f, g_p4f); SYM(p4hi, g_p4hi); SYM(p4lo, g_p4lo);
    SYM(ehi, g_ehi); SYM(elo, g_elo);
    SYM(vThi, g_vThi); SYM(vTlo, g_vTlo);
    SYM(dchi, g_dchi); SYM(dclo, g_dclo);
    SYM(cahi, g_cahi); SYM(calo, g_calo);
    SYM(cthi, g_cthi); SYM(ctlo, g_ctlo);
    SYM(athi, g_athi); SYM(atlo, g_atlo);
    SYM(inhi, g_inhi); SYM(inlo, g_inlo);
    SYM(w4Thi, g_w4Thi); SYM(w4Tlo, g_w4Tlo);
    SYM(pwThi, g_pwThi); SYM(pwTlo, g_pwTlo);
    SYM(wckThi, g_wckThi); SYM(wckTlo, g_wckTlo);
    SYM(wsoThi, g_wsoThi); SYM(wsoTlo, g_wsoTlo);
    SYM(wiThi, g_wiThi); SYM(wiTlo, g_wiTlo);
    SYM(woThi, g_woThi); SYM(woTlo, g_woTlo);
    #undef SYM

    dim3 blk(256);
    auto gemm = [&](const bf16* Ah, const bf16* Al, const bf16* Bh, const bf16* Bl,
                    Ptr4 bs, int nbias, const float* resid,
                    float* Cf, bf16* Chi, bf16* Clo,
                    int M, int N, int K, int lda, int ldb, int ldc,
                    long long iA, long long iB, long long iC, int z,
                    float scale, int gelu) {
        dim3 grid((N + 127) / 128, M / 128, z);
        gemm_bf16s<<<grid, blk, GSMEM>>>(Ah, Al, Bh, Bl, bs, nbias, resid, Cf, Chi, Clo,
                                         N, K, lda, ldb, ldc, iA, iB, iC, scale, gelu);
    };
    auto tcvt = [&](const float* src, bf16* hiT, bf16* loT, int R, int C,
                    long long sS, long long sD, int z) {
        dim3 g((C + 31) / 32, (R + 31) / 32, z);
        transpose_cvt<<<g, dim3(32, 8)>>>(src, hiT, loT, R, C, sS, sD);
    };

    const long long WSL = (long long)AHh * Hh;

    // 1: embed -> pairs
    cvt_pair<<<(Tt * Hh) / 1024, blk>>>(embed, ehi, elo, (long long)Tt * Hh);
    // 2-5: qkvco weight transposes
    tcvt(wq, w4Thi + 0 * WSL, w4Tlo + 0 * WSL, Hh, AHh, 0, 0, 1);
    tcvt(wk, w4Thi + 1 * WSL, w4Tlo + 1 * WSL, Hh, AHh, 0, 0, 1);
    tcvt(wv, w4Thi + 2 * WSL, w4Tlo + 2 * WSL, Hh, AHh, 0, 0, 1);
    tcvt(wco, w4Thi + 3 * WSL, w4Tlo + 3 * WSL, Hh, AHh, 0, 0, 1);
    // 6: merged q/k/v/co projection GEMM (profiled by ncu -s 5 -c 1)
    gemm(ehi, elo, w4Thi, w4Tlo, Ptr4{{bq, bk, bv, bco}}, 4, nullptr,
         p4f, p4hi, p4lo, Tt, AHh, Hh, Hh, Hh, AHh,
         0, WSL, SLICE, 4, 1.f, 0);
    // remaining weight transposes
    tcvt(pw, pwThi, pwTlo, Hh, AHh, 0, 0, 1);
    tcvt(wck, wckThi, wckTlo, AHh, NHh * KW, 0, 0, 1);
    tcvt(wso, wsoThi, wsoTlo, Hh, Hh, 0, 0, 1);
    tcvt(wi, wiThi, wiTlo, Hh, IMm, 0, 0, 1);
    tcvt(wo, woThi, woTlo, IMm, Hh, 0, 0, 1);

    // separable conv: depthwise (pairs) -> pointwise GEMM
    dconv_kernel<<<(Tt * Hh + 255) / 256, blk>>>(embed, dw, dchi, dclo);
    gemm(dchi, dclo, pwThi, pwTlo, Ptr4{{sep_b}}, 1, nullptr,
         psep, nullptr, nullptr, Tt, AHh, Hh, Hh, Hh, AHh, 0, 0, 0, 1, 1.f, 0);

    // span dynamic conv
    mul_cvt<<<(Tt * AHh) / 1024, blk>>>(psep, p4f + 0 * SLICE, cahi, calo);
    gemm(cahi, calo, wckThi, wckTlo, Ptr4{{bck}}, 1, nullptr,
         pck, nullptr, nullptr, Tt, NHh * KW, AHh, AHh, AHh, NHh * KW, 0, 0, 0, 1, 1.f, 0);
    ck_softmax<<<(Tt * NHh + 255) / 256, blk>>>(pck);
    conv_out_kernel<<<(Tt * AHh + 255) / 256, blk>>>(p4f + 3 * SLICE, pck, cthi, ctlo);

    // attention: V^T pairs + fused flash kernel -> ctx left half (pairs)
    tcvt(p4f + 2 * SLICE, vThi, vTlo, Ss, AHh, (long long)Ss * AHh, (long long)AHh * Ss, Bb);
    flash_attn<<<dim3(Ss / 128, Bb * NHh), blk, FA_SMEM>>>(
        p4hi + 0 * SLICE, p4lo + 0 * SLICE, p4hi + 1 * SLICE, p4lo + 1 * SLICE,
        vThi, vTlo, cthi, ctlo);

    // self output + LN1
    gemm(cthi, ctlo, wsoThi, wsoTlo, Ptr4{{bso}}, 1, embed,
         ppre, nullptr, nullptr, Tt, Hh, Hh, Hh, Hh, Hh, 0, 0, 0, 1, 1.f, 0);
    layernorm<<<Tt, blk>>>(ppre, ln1_g, ln1_b, pattn, athi, atlo);

    // FFN
    gemm(athi, atlo, wiThi, wiTlo, Ptr4{{bi}}, 1, nullptr,
         nullptr, inhi, inlo, Tt, IMm, Hh, Hh, Hh, IMm, 0, 0, 0, 1, 1.f, 1);
    gemm(inhi, inlo, woThi, woTlo, Ptr4{{bo}}, 1, pattn,
         ppre, nullptr, nullptr, Tt, Hh, IMm, IMm, IMm, Hh, 0, 0, 0, 1, 1.f, 0);
    layernorm<<<Tt, blk>>>(ppre, ln2_g, ln2_b, plo, nullptr, nullptr);

    // pool + decode
    maxpool_kernel<<<(Bb * Hh + 255) / 256, blk>>>();
    decoder_kernel<<<Bb, blk>>>(wd, bd, out);
}

// round 6
// speedup vs baseline: 3.3450x; 1.1926x over previous
#include <cuda_runtime.h>
#include <cuda_bf16.h>
#include <math.h>
#include <stdint.h>

#define Bb 8
#define Ss 1024
#define Hh 1536
#define NHh 8
#define HDd 96
#define AHh 768
#define KW 7
#define IMm 3072
#define Tt (Bb*Ss)

typedef __nv_bfloat16 bf16;
typedef __nv_bfloat162 bf162;

#define SLICE ((long long)Tt*AHh)

// ======================= device scratch (no runtime alloc) ==================
#define DEVARR(ty, nm, sz) __device__ __align__(256) ty nm[sz]
DEVARR(float, g_sep, Tt*AHh);
DEVARR(float, g_ck, Tt*NHh*KW);
DEVARR(float, g_attn, Tt*Hh);
DEVARR(float, g_pre, Tt*Hh);
DEVARR(float, g_lo, Tt*Hh);
DEVARR(float, g_pool, Bb*Hh);
__device__ __align__(256) float g_p4f[4ll*Tt*AHh];
__device__ __align__(256) bf16 g_p4hi[4ll*Tt*AHh];
__device__ __align__(256) bf16 g_p4lo[4ll*Tt*AHh];
DEVARR(bf16, g_ehi, Tt*Hh);  DEVARR(bf16, g_elo, Tt*Hh);
DEVARR(bf16, g_vThi, Tt*AHh); DEVARR(bf16, g_vTlo, Tt*AHh);   // [B][AH][S]
DEVARR(bf16, g_dchi, Tt*Hh); DEVARR(bf16, g_dclo, Tt*Hh);
DEVARR(bf16, g_cahi, Tt*AHh); DEVARR(bf16, g_calo, Tt*AHh);
DEVARR(bf16, g_cthi, Tt*Hh); DEVARR(bf16, g_ctlo, Tt*Hh);
DEVARR(bf16, g_athi, Tt*Hh); DEVARR(bf16, g_atlo, Tt*Hh);
DEVARR(bf16, g_inhi, Tt*IMm); DEVARR(bf16, g_inlo, Tt*IMm);
__device__ __align__(256) bf16 g_w4Thi[4*AHh*Hh];
__device__ __align__(256) bf16 g_w4Tlo[4*AHh*Hh];
DEVARR(bf16, g_pwThi, AHh*Hh); DEVARR(bf16, g_pwTlo, AHh*Hh);
DEVARR(bf16, g_wckThi, (NHh*KW)*AHh); DEVARR(bf16, g_wckTlo, (NHh*KW)*AHh);
DEVARR(bf16, g_wsoThi, Hh*Hh); DEVARR(bf16, g_wsoTlo, Hh*Hh);
__device__ __align__(256) bf16 g_wiThi[(long long)IMm*Hh];
__device__ __align__(256) bf16 g_wiTlo[(long long)IMm*Hh];
__device__ __align__(256) bf16 g_woThi[(long long)Hh*IMm];
__device__ __align__(256) bf16 g_woTlo[(long long)Hh*IMm];

// ============================ helpers ====================================
__device__ __forceinline__ uint32_t smem_u32(const void* p) {
    uint32_t a;
    asm("{ .reg .u64 t; cvta.to.shared.u64 t, %1; cvt.u32.u64 %0, t; }" : "=r"(a) : "l"(p));
    return a;
}
__device__ __forceinline__ void cpasync16(uint32_t saddr, const void* g) {
    asm volatile("cp.async.cg.shared.global [%0], [%1], 16;" :: "r"(saddr), "l"(g));
}
__device__ __forceinline__ void ldm_x4(uint32_t* r, uint32_t addr) {
    asm volatile("ldmatrix.sync.aligned.m8n8.x4.shared.b16 {%0,%1,%2,%3}, [%4];"
                 : "=r"(r[0]), "=r"(r[1]), "=r"(r[2]), "=r"(r[3]) : "r"(addr));
}
__device__ __forceinline__ void mma_bf16(float* c, const uint32_t* a, const uint32_t* b) {
    asm volatile("mma.sync.aligned.m16n8k16.row.col.f32.bf16.bf16.f32 "
                 "{%0,%1,%2,%3}, {%4,%5,%6,%7}, {%8,%9}, {%0,%1,%2,%3};"
                 : "+f"(c[0]), "+f"(c[1]), "+f"(c[2]), "+f"(c[3])
                 : "r"(a[0]), "r"(a[1]), "r"(a[2]), "r"(a[3]), "r"(b[0]), "r"(b[1]));
}
__device__ __forceinline__ void split_bf(float v, bf16& h, bf16& l) {
    h = __float2bfloat16(v);
    l = __float2bfloat16(v - __bfloat162float(h));
}

struct Ptr4 { const float* p[4]; };

// =================== fused bf16x3-split mma.sync GEMM ========================
// 2-stage pipeline, 2 CTAs/SM.
#define ASTR 40
#define TILE_B (128*ASTR*2)      // 10240
#define STG_B  (4*TILE_B)        // 40960
#define GSMEM  (2*STG_B)         // 81920

__global__ void __launch_bounds__(256, 2)
gemm_bf16s(const bf16* __restrict__ Ahi, const bf16* __restrict__ Alo,
           const bf16* __restrict__ Bhi, const bf16* __restrict__ Blo,
           Ptr4 bs, int nbias, const float* __restrict__ resid,
           float* __restrict__ Cf, bf16* __restrict__ Chi, bf16* __restrict__ Clo,
           int N, int Kd, int lda, int ldb, int ldc,
           long long iA, long long iB, long long iC,
           float scale, int gelu)
{
    extern __shared__ __align__(16) char dsm[];
    uint32_t s0 = smem_u32(dsm);

    int tid = threadIdx.x, lane = tid & 31, warp = tid >> 5;
    int wm = warp >> 2, wn = warp & 3;
    int row0 = blockIdx.y * 128, col0 = blockIdx.x * 128;
    int z = blockIdx.z;
    const bf16* Ah = Ahi + (long long)z * iA; const bf16* Al = Alo + (long long)z * iA;
    const bf16* Bh = Bhi + (long long)z * iB; const bf16* Bl = Blo + (long long)z * iB;
    long long offC = (long long)z * iC;
    const float* bias = bs.p[nbias > 1 ? z : 0];

    if (N - col0 < 128) {
        const uint4 zz = make_uint4(0, 0, 0, 0);
        for (int c = tid; c < 2 * (2 * TILE_B / 16); c += 256) {
            int stg = c / (2 * TILE_B / 16);
            int idx = c % (2 * TILE_B / 16);
            *(uint4*)(dsm + stg * STG_B + 2 * TILE_B + idx * 16) = zz;
        }
        __syncthreads();
    }

    int c0i = tid * 2, c1i = tid * 2 + 1;
    int ar0 = c0i >> 2, ac0 = (c0i & 3) * 8;
    int ar1 = c1i >> 2, ac1 = (c1i & 3) * 8;
    int nkb = Kd >> 5;

    auto ld_stage = [&](int stg, int ks) {
        int k0 = ks << 5;
        uint32_t base = s0 + stg * STG_B;
        long long a0 = (long long)(row0 + ar0) * lda + k0;
        long long a1 = (long long)(row0 + ar1) * lda + k0;
        cpasync16(base + (ar0 * ASTR + ac0) * 2, Ah + a0 + ac0);
        cpasync16(base + (ar1 * ASTR + ac1) * 2, Ah + a1 + ac1);
        cpasync16(base + TILE_B + (ar0 * ASTR + ac0) * 2, Al + a0 + ac0);
        cpasync16(base + TILE_B + (ar1 * ASTR + ac1) * 2, Al + a1 + ac1);
        if (col0 + ar0 < N) {
            long long b0 = (long long)(col0 + ar0) * ldb + k0;
            cpasync16(base + 2 * TILE_B + (ar0 * ASTR + ac0) * 2, Bh + b0 + ac0);
            cpasync16(base + 3 * TILE_B + (ar0 * ASTR + ac0) * 2, Bl + b0 + ac0);
        }
        if (col0 + ar1 < N) {
            long long b1 = (long long)(col0 + ar1) * ldb + k0;
            cpasync16(base + 2 * TILE_B + (ar1 * ASTR + ac1) * 2, Bh + b1 + ac1);
            cpasync16(base + 3 * TILE_B + (ar1 * ASTR + ac1) * 2, Bl + b1 + ac1);
        }
    };

    float acc[4][4][4] = {};

    ld_stage(0, 0);
    asm volatile("cp.async.commit_group;");

    for (int s = 0; s < nkb; s++) {
        if (s + 1 < nkb) {
            ld_stage((s + 1) & 1, s + 1);
            asm volatile("cp.async.commit_group;");
            asm volatile("cp.async.wait_group 1;");
        } else {
            asm volatile("cp.async.wait_group 0;");
        }
        __syncthreads();

        uint32_t aH = s0 + (s & 1) * STG_B;
        uint32_t aL = aH + TILE_B;
        uint32_t bH = aH + 2 * TILE_B;
        uint32_t bL = aH + 3 * TILE_B;

        #pragma unroll
        for (int kf = 0; kf < 2; kf++) {
            int arow = wm * 64 + (lane & 15);
            int acol = ((lane >> 4) << 3) + kf * 16;
            uint32_t ah[4][4], al[4][4];
            #pragma unroll
            for (int mi = 0; mi < 4; mi++) {
                uint32_t aoff = ((arow + mi * 16) * ASTR + acol) * 2;
                ldm_x4(ah[mi], aH + aoff);
                ldm_x4(al[mi], aL + aoff);
            }
            int brow = wn * 32 + ((lane >> 4) & 1) * 8 + (lane & 7);
            int bcol = (((lane >> 3) & 1) << 3) + kf * 16;
            #pragma unroll
            for (int nq = 0; nq < 2; nq++) {
                uint32_t boff = ((brow + nq * 16) * ASTR + bcol) * 2;
                uint32_t r[4];
                // --- B-hi: ah*bh and al*bh ---
                ldm_x4(r, bH + boff);
                #pragma unroll
                for (int mi = 0; mi < 4; mi++) {
                    mma_bf16(acc[mi][nq * 2],     ah[mi], r);
                    mma_bf16(acc[mi][nq * 2],     al[mi], r);
                    mma_bf16(acc[mi][nq * 2 + 1], ah[mi], r + 2);
                    mma_bf16(acc[mi][nq * 2 + 1], al[mi], r + 2);
                }
                // --- B-lo: ah*bl ---
                ldm_x4(r, bL + boff);
                #pragma unroll
                for (int mi = 0; mi < 4; mi++) {
                    mma_bf16(acc[mi][nq * 2],     ah[mi], r);
                    mma_bf16(acc[mi][nq * 2 + 1], ah[mi], r + 2);
                }
            }
        }
        __syncthreads();
    }

    int g4 = lane >> 2, t4 = lane & 3;
    #pragma unroll
    for (int mi = 0; mi < 4; mi++) {
        #pragma unroll
        for (int half = 0; half < 2; half++) {
            int r = row0 + wm * 64 + mi * 16 + g4 + half * 8;
            long long crow = offC + (long long)r * ldc;
            #pragma unroll
            for (int ni = 0; ni < 4; ni++) {
                int col = col0 + wn * 32 + ni * 8 + t4 * 2;
                if (col >= N) continue;
                float v0 = acc[mi][ni][half * 2 + 0] * scale;
                float v1 = acc[mi][ni][half * 2 + 1] * scale;
                if (bias) {
                    float2 bb = *(const float2*)(bias + col);
                    v0 += bb.x; v1 += bb.y;
                }
                if (resid) {
                    float2 rr = *(const float2*)(resid + crow + col);
                    v0 += rr.x; v1 += rr.y;
                }
                if (gelu) { v0 *= normcdff(v0); v1 *= normcdff(v1); }
                if (Cf) *(float2*)(Cf + crow + col) = make_float2(v0, v1);
                if (Chi) {
                    bf16 h0, h1, l0, l1;
                    split_bf(v0, h0, l0); split_bf(v1, h1, l1);
                    bf162 hp; hp.x = h0; hp.y = h1;
                    bf162 lp; lp.x = l0; lp.y = l1;
                    *(bf162*)(Chi + crow + col) = hp;
                    *(bf162*)(Clo + crow + col) = lp;
                }
            }
        }
    }
}

// =================== fused flash attention (bf16x3 split) ====================
#define FA_KSZ 5120
#define FA_VSZ 7680
#define FA_STAGE (6*FA_KSZ + 4*FA_VSZ)   // 61440
#define FA_SMEM (2*FA_STAGE)             // 122880

__global__ void __launch_bounds__(256)
flash_attn(const bf16* __restrict__ Qh, const bf16* __restrict__ Ql,
           const bf16* __restrict__ Kh, const bf16* __restrict__ Kl,
           const bf16* __restrict__ Vth, const bf16* __restrict__ Vtl,
           bf16* __restrict__ Ohi, bf16* __restrict__ Olo)
{
    extern __shared__ __align__(16) char dsm[];
    uint32_t s0 = smem_u32(dsm);
    int tid = threadIdx.x, lane = tid & 31, warp = tid >> 5;
    int q0 = blockIdx.x * 128;
    int bh = blockIdx.y; int b = bh >> 3, h = bh & 7;
    long long qkbase = (long long)b * Ss * AHh + h * HDd;
    long long vbase  = (long long)b * AHh * Ss + (long long)h * HDd * Ss;

    #pragma unroll
    for (int i = 0; i < 12; i++) {
        int v = tid + i * 256;
        int sub = v >> 9, idx = v & 511;
        int chunk = sub >> 1, hl = sub & 1;
        int row = idx >> 2, cv = idx & 3;
        const bf16* src = (hl ? Ql : Qh) + qkbase + (long long)(q0 + row) * AHh + chunk * 32 + cv * 8;
        cpasync16(s0 + sub * 10240 + (row * ASTR + cv * 8) * 2, src);
    }
    asm volatile("cp.async.commit_group;");
    asm volatile("cp.async.wait_group 0;");
    __syncthreads();

    uint32_t qfh[6][4], qfl[6][4];
    {
        int arow = warp * 16 + (lane & 15);
        int acolb = (lane >> 4) << 3;
        #pragma unroll
        for (int kf = 0; kf < 6; kf++) {
            int chunk = kf >> 1, f = kf & 1;
            uint32_t off = (arow * ASTR + acolb + f * 16) * 2;
            ldm_x4(qfh[kf], s0 + (chunk * 2 + 0) * 10240 + off);
            ldm_x4(qfl[kf], s0 + (chunk * 2 + 1) * 10240 + off);
        }
    }
    __syncthreads();

    auto ld_kv = [&](int stg, int it) {
        int sq = it * 64;
        uint32_t base = s0 + stg * FA_STAGE;
        #pragma unroll
        for (int i = 0; i < 12; i++) {
            int v = tid + i * 256;
            if (v < 1536) {
                int sub = v >> 8, idx = v & 255;
                int hl = sub & 1, chunk = sub >> 1;
                int row = idx >> 2, cv = idx & 3;
                const bf16* src = (hl ? Kl : Kh) + qkbase + (long long)(sq + row) * AHh + chunk * 32 + cv * 8;
                cpasync16(base + sub * FA_KSZ + (row * ASTR + cv * 8) * 2, src);
            } else {
                int v2 = v - 1536;
                int sub = v2 / 384, idx = v2 % 384;
                int hl = sub & 1, chunk = sub >> 1;
                int row = idx >> 2, cv = idx & 3;
                const bf16* src = (hl ? Vtl : Vth) + vbase + (long long)row * Ss + sq + chunk * 32 + cv * 8;
                cpasync16(base + 6 * FA_KSZ + sub * FA_VSZ + (row * ASTR + cv * 8) * 2, src);
            }
        }
    };

    float m_[2] = {-1e30f, -1e30f};
    float l_[2] = {0.f, 0.f};
    float acc_o[12][4] = {};
    const float isq = rsqrtf(96.f);

    ld_kv(0, 0);
    asm volatile("cp.async.commit_group;");
    ld_kv(1, 1);
    asm volatile("cp.async.commit_group;");

    int brow = ((lane >> 4) & 1) * 8 + (lane & 7);
    int bcol = ((lane >> 3) & 1) * 8;

    for (int it = 0; it < 16; it++) {
        if (it + 1 < 16) asm volatile("cp.async.wait_group 1;");
        else             asm volatile("cp.async.wait_group 0;");
        __syncthreads();
        uint32_t kb = s0 + (it & 1) * FA_STAGE;
        uint32_t vb = kb + 6 * FA_KSZ;

        float s_[8][4] = {};
        #pragma unroll
        for (int kf = 0; kf < 6; kf++) {
            int chunk = kf >> 1, f = kf & 1;
            uint32_t bo = (brow * ASTR + bcol + f * 16) * 2;
            #pragma unroll
            for (int nq = 0; nq < 4; nq++) {
                uint32_t rh[4], rl[4];
                ldm_x4(rh, kb + (chunk * 2 + 0) * FA_KSZ + bo + nq * 16 * ASTR * 2);
                ldm_x4(rl, kb + (chunk * 2 + 1) * FA_KSZ + bo + nq * 16 * ASTR * 2);
                mma_bf16(s_[nq * 2],     qfh[kf], rh);
                mma_bf16(s_[nq * 2],     qfh[kf], rl);
                mma_bf16(s_[nq * 2],     qfl[kf], rh);
                mma_bf16(s_[nq * 2 + 1], qfh[kf], rh + 2);
                mma_bf16(s_[nq * 2 + 1], qfh[kf], rl + 2);
                mma_bf16(s_[nq * 2 + 1], qfl[kf], rh + 2);
            }
        }
        #pragma unroll
        for (int ni = 0; ni < 8; ni++)
            #pragma unroll
            for (int j = 0; j < 4; j++) s_[ni][j] *= isq;

        #pragma unroll
        for (int rh = 0; rh < 2; rh++) {
            float mx = -1e30f;
            #pragma unroll
            for (int ni = 0; ni < 8; ni++)
                mx = fmaxf(mx, fmaxf(s_[ni][rh * 2], s_[ni][rh * 2 + 1]));
            mx = fmaxf(mx, __shfl_xor_sync(0xffffffffu, mx, 1));
            mx = fmaxf(mx, __shfl_xor_sync(0xffffffffu, mx, 2));
            float mnew = fmaxf(m_[rh], mx);
            float a = __expf(m_[rh] - mnew);
            m_[rh] = mnew;
            float rs = 0.f;
            #pragma unroll
            for (int ni = 0; ni < 8; ni++) {
                float p0 = __expf(s_[ni][rh * 2] - mnew);
                float p1 = __expf(s_[ni][rh * 2 + 1] - mnew);
                s_[ni][rh * 2] = p0; s_[ni][rh * 2 + 1] = p1;
                rs += p0 + p1;
            }
            rs += __shfl_xor_sync(0xffffffffu, rs, 1);
            rs += __shfl_xor_sync(0xffffffffu, rs, 2);
            l_[rh] = l_[rh] * a + rs;
            #pragma unroll
            for (int ni = 0; ni < 12; ni++) {
                acc_o[ni][rh * 2] *= a; acc_o[ni][rh * 2 + 1] *= a;
            }
        }

        uint32_t pfh[4][4], pfl[4][4];
        #pragma unroll
        for (int kp = 0; kp < 4; kp++) {
            #pragma unroll
            for (int q = 0; q < 2; q++) {
                int ni = kp * 2 + q;
                float x0 = s_[ni][0], x1 = s_[ni][1], x2 = s_[ni][2], x3 = s_[ni][3];
                bf16 h0, l0, h1, l1, h2, l2, h3, l3;
                split_bf(x0, h0, l0); split_bf(x1, h1, l1);
                split_bf(x2, h2, l2); split_bf(x3, h3, l3);
                bf162 t;
                t.x = h0; t.y = h1; pfh[kp][q * 2 + 0] = *(uint32_t*)&t;
                t.x = h2; t.y = h3; pfh[kp][q * 2 + 1] = *(uint32_t*)&t;
                t.x = l0; t.y = l1; pfl[kp][q * 2 + 0] = *(uint32_t*)&t;
                t.x = l2; t.y = l3; pfl[kp][q * 2 + 1] = *(uint32_t*)&t;
            }
        }

        #pragma unroll
        for (int kp = 0; kp < 4; kp++) {
            int chunk = kp >> 1, f = kp & 1;
            uint32_t bo = (brow * ASTR + bcol + f * 16) * 2;
            #pragma unroll
            for (int nq = 0; nq < 6; nq++) {
                uint32_t rh[4], rl[4];
                ldm_x4(rh, vb + (chunk * 2 + 0) * FA_VSZ + bo + nq * 16 * ASTR * 2);
                ldm_x4(rl, vb + (chunk * 2 + 1) * FA_VSZ + bo + nq * 16 * ASTR * 2);
                mma_bf16(acc_o[nq * 2],     pfh[kp], rh);
                mma_bf16(acc_o[nq * 2],     pfh[kp], rl);
                mma_bf16(acc_o[nq * 2],     pfl[kp], rh);
                mma_bf16(acc_o[nq * 2 + 1], pfh[kp], rh + 2);
                mma_bf16(acc_o[nq * 2 + 1], pfh[kp], rl + 2);
                mma_bf16(acc_o[nq * 2 + 1], pfl[kp], rh + 2);
            }
        }
        __syncthreads();
        if (it + 2 < 16) {
            ld_kv(it & 1, it + 2);
            asm volatile("cp.async.commit_group;");
        }
    }

    int g4 = lane >> 2, t4 = lane & 3;
    #pragma unroll
    for (int rh = 0; rh < 2; rh++) {
        float inv = 1.f / l_[rh];
        int r = q0 + warp * 16 + g4 + rh * 8;
        long long orow = ((long long)b * Ss + r) * Hh + h * HDd;
        #pragma unroll
        for (int ni = 0; ni < 12; ni++) {
            int col = ni * 8 + t4 * 2;
            float v0 = acc_o[ni][rh * 2] * inv;
            float v1 = acc_o[ni][rh * 2 + 1] * inv;
            bf16 h0, l0, h1, l1;
            split_bf(v0, h0, l0); split_bf(v1, h1, l1);
            bf162 hp; hp.x = h0; hp.y = h1;
            bf162 lp; lp.x = l0; lp.y = l1;
            *(bf162*)(Ohi + orow + col) = hp;
            *(bf162*)(Olo + orow + col) = lp;
        }
    }
}

// ===================== conversion / transpose kernels ========================
__global__ void cvt_pair(const float* __restrict__ x, bf16* __restrict__ hi,
                         bf16* __restrict__ lo, long long n)
{
    long long i = ((long long)blockIdx.x * 256 + threadIdx.x) * 4;
    if (i >= n) return;
    float4 v = *(const float4*)(x + i);
    bf16 h0, h1, h2, h3, l0, l1, l2, l3;
    split_bf(v.x, h0, l0); split_bf(v.y, h1, l1);
    split_bf(v.z, h2, l2); split_bf(v.w, h3, l3);
    bf162 a; a.x = h0; a.y = h1;
    bf162 b; b.x = h2; b.y = h3;
    bf162 c; c.x = l0; c.y = l1;
    bf162 d; d.x = l2; d.y = l3;
    *(bf162*)(hi + i) = a; *(bf162*)(hi + i + 2) = b;
    *(bf162*)(lo + i) = c; *(bf162*)(lo + i + 2) = d;
}

__global__ void transpose_cvt(const float* __restrict__ src, bf16* __restrict__ hiT,
                              bf16* __restrict__ loT, int R, int C,
                              long long sSrc, long long sDst)
{
    __shared__ float t[32][33];
    src += (long long)blockIdx.z * sSrc;
    hiT += (long long)blockIdx.z * sDst;
    loT += (long long)blockIdx.z * sDst;
    int r0 = blockIdx.y * 32, c0 = blockIdx.x * 32;
    #pragma unroll
    for (int j = 0; j < 4; j++) {
        int rr = r0 + threadIdx.y + j * 8, cc = c0 + threadIdx.x;
        t[threadIdx.y + j * 8][threadIdx.x] =
            (rr < R && cc < C) ? src[(long long)rr * C + cc] : 0.f;
    }
    __syncthreads();
    #pragma unroll
    for (int j = 0; j < 4; j++) {
        int cc = c0 + threadIdx.y + j * 8, rr = r0 + threadIdx.x;
        if (cc < C && rr < R) {
            float v = t[threadIdx.x][threadIdx.y + j * 8];
            bf16 h, l; split_bf(v, h, l);
            hiT[(long long)cc * R + rr] = h;
            loT[(long long)cc * R + rr] = l;
        }
    }
}

__global__ void mul_cvt(const float* __restrict__ sep, const float* __restrict__ q,
                        bf16* __restrict__ chi, bf16* __restrict__ clo)
{
    long long i = ((long long)blockIdx.x * 256 + threadIdx.x) * 4;
    if (i >= (long long)Tt * AHh) return;
    float4 s = *(const float4*)(sep + i);
    float4 qq = *(const float4*)(q + i);
    float m0 = s.x * qq.x, m1 = s.y * qq.y, m2 = s.z * qq.z, m3 = s.w * qq.w;
    bf16 h0, h1, h2, h3, l0, l1, l2, l3;
    split_bf(m0, h0, l0); split_bf(m1, h1, l1);
    split_bf(m2, h2, l2); split_bf(m3, h3, l3);
    bf162 a; a.x = h0; a.y = h1;
    bf162 b; b.x = h2; b.y = h3;
    bf162 c; c.x = l0; c.y = l1;
    bf162 d; d.x = l2; d.y = l3;
    *(bf162*)(chi + i) = a; *(bf162*)(chi + i + 2) = b;
    *(bf162*)(clo + i) = c; *(bf162*)(clo + i + 2) = d;
}

// ======================= elementwise / reduction kernels =====================
__global__ void dconv_kernel(const float* __restrict__ e, const float* __restrict__ dw,
                             bf16* __restrict__ dh, bf16* __restrict__ dl)
{
    int i = blockIdx.x * blockDim.x + threadIdx.x;
    if (i >= Tt * Hh) return;
    int c = i % Hh, t = i / Hh;
    int s = t % Ss, b = t / Ss;
    float acc = 0.f;
    #pragma unroll
    for (int j = 0; j < KW; j++) {
        int ss = s + j - 3;
        if (ss >= 0 && ss < Ss)
            acc = fmaf(e[((long long)(b * Ss + ss)) * Hh + c], dw[c * KW + j], acc);
    }
    bf16 h, l; split_bf(acc, h, l);
    dh[i] = h; dl[i] = l;
}

__global__ void ck_softmax(float* __restrict__ ck)
{
    int r = blockIdx.x * blockDim.x + threadIdx.x;
    if (r >= Tt * NHh) return;
    float* p = ck + (long long)r * KW;
    float m = p[0];
    #pragma unroll
    for (int j = 1; j < KW; j++) m = fmaxf(m, p[j]);
    float s = 0.f, e[KW];
    #pragma unroll
    for (int j = 0; j < KW; j++) { e[j] = expf(p[j] - m); s += e[j]; }
    float inv = 1.f / s;
    #pragma unroll
    for (int j = 0; j < KW; j++) p[j] = e[j] * inv;
}

__global__ void conv_out_kernel(const float* __restrict__ co, const float* __restrict__ ck,
                                bf16* __restrict__ cthi, bf16* __restrict__ ctlo)
{
    int i = blockIdx.x * blockDim.x + threadIdx.x;
    if (i >= Tt * AHh) return;
    int c = i % AHh, t = i / AHh;
    int h = c / HDd;
    int s = t % Ss, b = t / Ss;
    const float* ckp = ck + (long long)t * (NHh * KW) + h * KW;
    float acc = 0.f;
    #pragma unroll
    for (int j = 0; j < KW; j++) {
        int ss = s + j - 3;
        if (ss >= 0 && ss < Ss)
            acc = fmaf(co[((long long)(b * Ss + ss)) * AHh + c], ckp[j], acc);
    }
    bf16 h_, l_; split_bf(acc, h_, l_);
    cthi[(long long)t * Hh + AHh + c] = h_;
    ctlo[(long long)t * Hh + AHh + c] = l_;
}

__global__ void layernorm(const float* __restrict__ x, const float* __restrict__ g,
                          const float* __restrict__ bb, float* __restrict__ y,
                          bf16* __restrict__ hi, bf16* __restrict__ lo)
{
    long long row = blockIdx.x;
    const float* p = x + row * Hh;
    __shared__ float red[256];
    int tid = threadIdx.x;
    float s = 0.f;
    for (int i = tid; i < Hh; i += 256) s += p[i];
    red[tid] = s; __syncthreads();
    for (int o = 128; o > 0; o >>= 1) { if (tid < o) red[tid] += red[tid + o]; __syncthreads(); }
    float m = red[0] / Hh; __syncthreads();
    float v = 0.f;
    for (int i = tid; i < Hh; i += 256) { float d = p[i] - m; v += d * d; }
    red[tid] = v; __syncthreads();
    for (int o = 128; o > 0; o >>= 1) { if (tid < o) red[tid] += red[tid + o]; __syncthreads(); }
    float inv = rsqrtf(red[0] / Hh + 1e-12f);
    for (int i = tid; i < Hh; i += 256) {
        float o = (p[i] - m) * inv * g[i] + bb[i];
        y[row * Hh + i] = o;
        if (hi) { bf16 h, l; split_bf(o, h, l); hi[row * Hh + i] = h; lo[row * Hh + i] = l; }
    }
}

__global__ void maxpool_kernel()
{
    int i = blockIdx.x * blockDim.x + threadIdx.x;
    if (i >= Bb * Hh) return;
    int c = i % Hh, b = i / Hh;
    float m = -3.4e38f;
    for (int s = 0; s < Ss; s++)
        m = fmaxf(m, g_lo[((long long)(b * Ss + s)) * Hh + c]);
    g_pool[i] = m;
}

__global__ void decoder_kernel(const float* __restrict__ wd, const float* __restrict__ bd,
                               float* __restrict__ out)
{
    int b = blockIdx.x;
    __shared__ float red[256];
    int tid = threadIdx.x;
    float s = 0.f;
    for (int i = tid; i < Hh; i += 256) s += g_pool[b * Hh + i] * wd[i];
    red[tid] = s; __syncthreads();
    for (int o = 128; o > 0; o >>= 1) { if (tid < o) red[tid] += red[tid + o]; __syncthreads(); }
    if (tid == 0) out[b] = red[0] + bd[0];
}

// =============================================================================
extern "C" void kernel_launch(void* const* d_in, const int* in_sizes, int n_in,
                              void* d_out, int out_size)
{
    const float* embed = (const float*)d_in[0];
    const float* wq  = (const float*)d_in[1];  const float* bq  = (const float*)d_in[2];
    const float* wk  = (const float*)d_in[3];  const float* bk  = (const float*)d_in[4];
    const float* wv  = (const float*)d_in[5];  const float* bv  = (const float*)d_in[6];
    const float* dw  = (const float*)d_in[7];
    const float* pw  = (const float*)d_in[8];  const float* sep_b = (const float*)d_in[9];
    const float* wck = (const float*)d_in[10]; const float* bck = (const float*)d_in[11];
    const float* wco = (const float*)d_in[12]; const float* bco = (const float*)d_in[13];
    const float* wso = (const float*)d_in[14]; const float* bso = (const float*)d_in[15];
    const float* ln1_g = (const float*)d_in[16]; const float* ln1_b = (const float*)d_in[17];
    const float* wi  = (const float*)d_in[18]; const float* bi  = (const float*)d_in[19];
    const float* wo  = (const float*)d_in[20]; const float* bo  = (const float*)d_in[21];
    const float* ln2_g = (const float*)d_in[22]; const float* ln2_b = (const float*)d_in[23];
    const float* wd  = (const float*)d_in[24]; const float* bd  = (const float*)d_in[25];
    float* out = (float*)d_out;

    cudaFuncSetAttribute(gemm_bf16s, cudaFuncAttributeMaxDynamicSharedMemorySize, GSMEM);
    cudaFuncSetAttribute(flash_attn, cudaFuncAttributeMaxDynamicSharedMemorySize, FA_SMEM);

    #define SYM(p, s) void* p##_; cudaGetSymbolAddress(&p##_, s); auto p = (decltype(&s[0]))p##_
    SYM(psep, g_sep); SYM(pck, g_ck); SYM(pattn, g_attn);
    SYM(ppre, g_pre); SYM(plo, g_lo);
    SYM(p4f, g_p4f); SYM(p4hi, g_p4hi); SYM(p4lo, g_p4lo);
    SYM(ehi, g_ehi); SYM(elo, g_elo);
    SYM(vThi, g_vThi); SYM(vTlo, g_vTlo);
    SYM(dchi, g_dchi); SYM(dclo, g_dclo);
    SYM(cahi, g_cahi); SYM(calo, g_calo);
    SYM(cthi, g_cthi); SYM(ctlo, g_ctlo);
    SYM(athi, g_athi); SYM(atlo, g_atlo);
    SYM(inhi, g_inhi); SYM(inlo, g_inlo);
    SYM(w4Thi, g_w4Thi); SYM(w4Tlo, g_w4Tlo);
    SYM(pwThi, g_pwThi); SYM(pwTlo, g_pwTlo);
    SYM(wckThi, g_wckThi); SYM(wckTlo, g_wckTlo);
    SYM(wsoThi, g_wsoThi); SYM(wsoTlo, g_wsoTlo);
    SYM(wiThi, g_wiThi); SYM(wiTlo, g_wiTlo);
    SYM(woThi, g_woThi); SYM(woTlo, g_woTlo);
    #undef SYM

    dim3 blk(256);
    auto gemm = [&](const bf16* Ah, const bf16* Al, const bf16* Bh, const bf16* Bl,
                    Ptr4 bs, int nbias, const float* resid,
                    float* Cf, bf16* Chi, bf16* Clo,
                    int M, int N, int K, int lda, int ldb, int ldc,
                    long long iA, long long iB, long long iC, int z,
                    float scale, int gelu) {
        dim3 grid((N + 127) / 128, M / 128, z);
        gemm_bf16s<<<grid, blk, GSMEM>>>(Ah, Al, Bh, Bl, bs, nbias, resid, Cf, Chi, Clo,
                                         N, K, lda, ldb, ldc, iA, iB, iC, scale, gelu);
    };
    auto tcvt = [&](const float* src, bf16* hiT, bf16* loT, int R, int C,
                    long long sS, long long sD, int z) {
        dim3 g((C + 31) / 32, (R + 31) / 32, z);
        transpose_cvt<<<g, dim3(32, 8)>>>(src, hiT, loT, R, C, sS, sD);
    };

    const long long WSL = (long long)AHh * Hh;

    cvt_pair<<<(Tt * Hh) / 1024, blk>>>(embed, ehi, elo, (long long)Tt * Hh);
    tcvt(wq, w4Thi + 0 * WSL, w4Tlo + 0 * WSL, Hh, AHh, 0, 0, 1);
    tcvt(wk, w4Thi + 1 * WSL, w4Tlo + 1 * WSL, Hh, AHh, 0, 0, 1);
    tcvt(wv, w4Thi + 2 * WSL, w4Tlo + 2 * WSL, Hh, AHh, 0, 0, 1);
    tcvt(wco, w4Thi + 3 * WSL, w4Tlo + 3 * WSL, Hh, AHh, 0, 0, 1);
    // merged q/k/v/co projection GEMM
    gemm(ehi, elo, w4Thi, w4Tlo, Ptr4{{bq, bk, bv, bco}}, 4, nullptr,
         p4f, p4hi, p4lo, Tt, AHh, Hh, Hh, Hh, AHh,
         0, WSL, SLICE, 4, 1.f, 0);
    tcvt(pw, pwThi, pwTlo, Hh, AHh, 0, 0, 1);
    tcvt(wck, wckThi, wckTlo, AHh, NHh * KW, 0, 0, 1);
    tcvt(wso, wsoThi, wsoTlo, Hh, Hh, 0, 0, 1);
    tcvt(wi, wiThi, wiTlo, Hh, IMm, 0, 0, 1);
    tcvt(wo, woThi, woTlo, IMm, Hh, 0, 0, 1);

    // separable conv
    dconv_kernel<<<(Tt * Hh + 255) / 256, blk>>>(embed, dw, dchi, dclo);
    gemm(dchi, dclo, pwThi, pwTlo, Ptr4{{sep_b}}, 1, nullptr,
         psep, nullptr, nullptr, Tt, AHh, Hh, Hh, Hh, AHh, 0, 0, 0, 1, 1.f, 0);

    // span dynamic conv
    mul_cvt<<<(Tt * AHh) / 1024, blk>>>(psep, p4f + 0 * SLICE, cahi, calo);
    gemm(cahi, calo, wckThi, wckTlo, Ptr4{{bck}}, 1, nullptr,
         pck, nullptr, nullptr, Tt, NHh * KW, AHh, AHh, AHh, NHh * KW, 0, 0, 0, 1, 1.f, 0);
    ck_softmax<<<(Tt * NHh + 255) / 256, blk>>>(pck);
    conv_out_kernel<<<(Tt * AHh + 255) / 256, blk>>>(p4f + 3 * SLICE, pck, cthi, ctlo);

    // attention
    tcvt(p4f + 2 * SLICE, vThi, vTlo, Ss, AHh, (long long)Ss * AHh, (long long)AHh * Ss, Bb);
    flash_attn<<<dim3(Ss / 128, Bb * NHh), blk, FA_SMEM>>>(
        p4hi + 0 * SLICE, p4lo + 0 * SLICE, p4hi + 1 * SLICE, p4lo + 1 * SLICE,
        vThi, vTlo, cthi, ctlo);

    // self output + LN1
    gemm(cthi, ctlo, wsoThi, wsoTlo, Ptr4{{bso}}, 1, embed,
         ppre, nullptr, nullptr, Tt, Hh, Hh, Hh, Hh, Hh, 0, 0, 0, 1, 1.f, 0);
    layernorm<<<Tt, blk>>>(ppre, ln1_g, ln1_b, pattn, athi, atlo);

    // FFN
    gemm(athi, atlo, wiThi, wiTlo, Ptr4{{bi}}, 1, nullptr,
         nullptr, inhi, inlo, Tt, IMm, Hh, Hh, Hh, IMm, 0, 0, 0, 1, 1.f, 1);
    gemm(inhi, inlo, woThi, woTlo, Ptr4{{bo}}, 1, pattn,
         ppre, nullptr, nullptr, Tt, Hh, IMm, IMm, IMm, Hh, 0, 0, 0, 1, 1.f, 0);
    layernorm<<<Tt, blk>>>(ppre, ln2_g, ln2_b, plo, nullptr, nullptr);

    // pool + decode
    maxpool_kernel<<<(Bb * Hh + 255) / 256, blk>>>();
    decoder_kernel<<<Bb, blk>>>(wd, bd, out);
}

// round 7
// speedup vs baseline: 3.4593x; 1.0342x over previous
#include <cuda_runtime.h>
#include <cuda_bf16.h>
#include <math.h>
#include <stdint.h>

#define Bb 8
#define Ss 1024
#define Hh 1536
#define NHh 8
#define HDd 96
#define AHh 768
#define KW 7
#define IMm 3072
#define Tt (Bb*Ss)

typedef __nv_bfloat16 bf16;
typedef __nv_bfloat162 bf162;

#define SLICE ((long long)Tt*AHh)

// ======================= device scratch (no runtime alloc) ==================
#define DEVARR(ty, nm, sz) __device__ __align__(256) ty nm[sz]
DEVARR(float, g_ck, Tt*NHh*KW);
DEVARR(float, g_attn, Tt*Hh);
DEVARR(float, g_pre, Tt*Hh);
DEVARR(float, g_lo, Tt*Hh);
DEVARR(float, g_poolp, Bb*8*Hh);
DEVARR(float, g_pool, Bb*Hh);
__device__ __align__(256) float g_p4f[4ll*Tt*AHh];
__device__ __align__(256) bf16 g_p4hi[4ll*Tt*AHh];
__device__ __align__(256) bf16 g_p4lo[4ll*Tt*AHh];
DEVARR(bf16, g_ehi, Tt*Hh);  DEVARR(bf16, g_elo, Tt*Hh);
DEVARR(bf16, g_vThi, Tt*AHh); DEVARR(bf16, g_vTlo, Tt*AHh);   // [B][AH][S]
DEVARR(bf16, g_dchi, Tt*Hh); DEVARR(bf16, g_dclo, Tt*Hh);
DEVARR(bf16, g_cahi, Tt*AHh); DEVARR(bf16, g_calo, Tt*AHh);
DEVARR(bf16, g_cthi, Tt*Hh); DEVARR(bf16, g_ctlo, Tt*Hh);
DEVARR(bf16, g_athi, Tt*Hh); DEVARR(bf16, g_atlo, Tt*Hh);
DEVARR(bf16, g_inhi, Tt*IMm); DEVARR(bf16, g_inlo, Tt*IMm);
__device__ __align__(256) bf16 g_w4Thi[4*AHh*Hh];
__device__ __align__(256) bf16 g_w4Tlo[4*AHh*Hh];
DEVARR(bf16, g_pwThi, AHh*Hh); DEVARR(bf16, g_pwTlo, AHh*Hh);
DEVARR(bf16, g_wckThi, (NHh*KW)*AHh); DEVARR(bf16, g_wckTlo, (NHh*KW)*AHh);
DEVARR(bf16, g_wsoThi, Hh*Hh); DEVARR(bf16, g_wsoTlo, Hh*Hh);
__device__ __align__(256) bf16 g_wiThi[(long long)IMm*Hh];
__device__ __align__(256) bf16 g_wiTlo[(long long)IMm*Hh];
__device__ __align__(256) bf16 g_woThi[(long long)Hh*IMm];
__device__ __align__(256) bf16 g_woTlo[(long long)Hh*IMm];

// ============================ helpers ====================================
__device__ __forceinline__ uint32_t smem_u32(const void* p) {
    uint32_t a;
    asm("{ .reg .u64 t; cvta.to.shared.u64 t, %1; cvt.u32.u64 %0, t; }" : "=r"(a) : "l"(p));
    return a;
}
__device__ __forceinline__ void cpasync16(uint32_t saddr, const void* g) {
    asm volatile("cp.async.cg.shared.global [%0], [%1], 16;" :: "r"(saddr), "l"(g));
}
__device__ __forceinline__ void ldm_x4(uint32_t* r, uint32_t addr) {
    asm volatile("ldmatrix.sync.aligned.m8n8.x4.shared.b16 {%0,%1,%2,%3}, [%4];"
                 : "=r"(r[0]), "=r"(r[1]), "=r"(r[2]), "=r"(r[3]) : "r"(addr));
}
__device__ __forceinline__ void mma_bf16(float* c, const uint32_t* a, const uint32_t* b) {
    asm volatile("mma.sync.aligned.m16n8k16.row.col.f32.bf16.bf16.f32 "
                 "{%0,%1,%2,%3}, {%4,%5,%6,%7}, {%8,%9}, {%0,%1,%2,%3};"
                 : "+f"(c[0]), "+f"(c[1]), "+f"(c[2]), "+f"(c[3])
                 : "r"(a[0]), "r"(a[1]), "r"(a[2]), "r"(a[3]), "r"(b[0]), "r"(b[1]));
}
__device__ __forceinline__ void split_bf(float v, bf16& h, bf16& l) {
    h = __float2bfloat16(v);
    l = __float2bfloat16(v - __bfloat162float(h));
}

struct Ptr4 { const float* p[4]; };

// =================== fused bf16x3-split mma.sync GEMM ========================
#define ASTR 40
#define TILE_B (128*ASTR*2)      // 10240
#define STG_B  (4*TILE_B)        // 40960
#define GSMEM  (2*STG_B)         // 81920

__global__ void __launch_bounds__(256, 2)
gemm_bf16s(const bf16* __restrict__ Ahi, const bf16* __restrict__ Alo,
           const bf16* __restrict__ Bhi, const bf16* __restrict__ Blo,
           Ptr4 bs, int nbias, const float* __restrict__ resid,
           const float* __restrict__ qmul,
           float* __restrict__ Cf, bf16* __restrict__ Chi, bf16* __restrict__ Clo,
           int N, int Kd, int lda, int ldb, int ldc,
           long long iA, long long iB, long long iC,
           float scale, int gelu)
{
    extern __shared__ __align__(16) char dsm[];
    uint32_t s0 = smem_u32(dsm);

    int tid = threadIdx.x, lane = tid & 31, warp = tid >> 5;
    int wm = warp >> 2, wn = warp & 3;
    int row0 = blockIdx.y * 128, col0 = blockIdx.x * 128;
    int z = blockIdx.z;
    const bf16* Ah = Ahi + (long long)z * iA; const bf16* Al = Alo + (long long)z * iA;
    const bf16* Bh = Bhi + (long long)z * iB; const bf16* Bl = Blo + (long long)z * iB;
    long long offC = (long long)z * iC;
    const float* bias = bs.p[nbias > 1 ? z : 0];

    if (N - col0 < 128) {
        const uint4 zz = make_uint4(0, 0, 0, 0);
        for (int c = tid; c < 2 * (2 * TILE_B / 16); c += 256) {
            int stg = c / (2 * TILE_B / 16);
            int idx = c % (2 * TILE_B / 16);
            *(uint4*)(dsm + stg * STG_B + 2 * TILE_B + idx * 16) = zz;
        }
        __syncthreads();
    }

    int c0i = tid * 2, c1i = tid * 2 + 1;
    int ar0 = c0i >> 2, ac0 = (c0i & 3) * 8;
    int ar1 = c1i >> 2, ac1 = (c1i & 3) * 8;
    int nkb = Kd >> 5;

    auto ld_stage = [&](int stg, int ks) {
        int k0 = ks << 5;
        uint32_t base = s0 + stg * STG_B;
        long long a0 = (long long)(row0 + ar0) * lda + k0;
        long long a1 = (long long)(row0 + ar1) * lda + k0;
        cpasync16(base + (ar0 * ASTR + ac0) * 2, Ah + a0 + ac0);
        cpasync16(base + (ar1 * ASTR + ac1) * 2, Ah + a1 + ac1);
        cpasync16(base + TILE_B + (ar0 * ASTR + ac0) * 2, Al + a0 + ac0);
        cpasync16(base + TILE_B + (ar1 * ASTR + ac1) * 2, Al + a1 + ac1);
        if (col0 + ar0 < N) {
            long long b0 = (long long)(col0 + ar0) * ldb + k0;
            cpasync16(base + 2 * TILE_B + (ar0 * ASTR + ac0) * 2, Bh + b0 + ac0);
            cpasync16(base + 3 * TILE_B + (ar0 * ASTR + ac0) * 2, Bl + b0 + ac0);
        }
        if (col0 + ar1 < N) {
            long long b1 = (long long)(col0 + ar1) * ldb + k0;
            cpasync16(base + 2 * TILE_B + (ar1 * ASTR + ac1) * 2, Bh + b1 + ac1);
            cpasync16(base + 3 * TILE_B + (ar1 * ASTR + ac1) * 2, Bl + b1 + ac1);
        }
    };

    float acc[4][4][4] = {};

    ld_stage(0, 0);
    asm volatile("cp.async.commit_group;");

    for (int s = 0; s < nkb; s++) {
        if (s + 1 < nkb) {
            ld_stage((s + 1) & 1, s + 1);
            asm volatile("cp.async.commit_group;");
            asm volatile("cp.async.wait_group 1;");
        } else {
            asm volatile("cp.async.wait_group 0;");
        }
        __syncthreads();

        uint32_t aH = s0 + (s & 1) * STG_B;
        uint32_t aL = aH + TILE_B;
        uint32_t bH = aH + 2 * TILE_B;
        uint32_t bL = aH + 3 * TILE_B;

        #pragma unroll
        for (int kf = 0; kf < 2; kf++) {
            int arow = wm * 64 + (lane & 15);
            int acol = ((lane >> 4) << 3) + kf * 16;
            uint32_t ah[4][4], al[4][4];
            #pragma unroll
            for (int mi = 0; mi < 4; mi++) {
                uint32_t aoff = ((arow + mi * 16) * ASTR + acol) * 2;
                ldm_x4(ah[mi], aH + aoff);
                ldm_x4(al[mi], aL + aoff);
            }
            int brow = wn * 32 + ((lane >> 4) & 1) * 8 + (lane & 7);
            int bcol = (((lane >> 3) & 1) << 3) + kf * 16;
            #pragma unroll
            for (int nq = 0; nq < 2; nq++) {
                uint32_t boff = ((brow + nq * 16) * ASTR + bcol) * 2;
                uint32_t r[4];
                ldm_x4(r, bH + boff);
                #pragma unroll
                for (int mi = 0; mi < 4; mi++) {
                    mma_bf16(acc[mi][nq * 2],     ah[mi], r);
                    mma_bf16(acc[mi][nq * 2],     al[mi], r);
                    mma_bf16(acc[mi][nq * 2 + 1], ah[mi], r + 2);
                    mma_bf16(acc[mi][nq * 2 + 1], al[mi], r + 2);
                }
                ldm_x4(r, bL + boff);
                #pragma unroll
                for (int mi = 0; mi < 4; mi++) {
                    mma_bf16(acc[mi][nq * 2],     ah[mi], r);
                    mma_bf16(acc[mi][nq * 2 + 1], ah[mi], r + 2);
                }
            }
        }
        __syncthreads();
    }

    int g4 = lane >> 2, t4 = lane & 3;
    #pragma unroll
    for (int mi = 0; mi < 4; mi++) {
        #pragma unroll
        for (int half = 0; half < 2; half++) {
            int r = row0 + wm * 64 + mi * 16 + g4 + half * 8;
            long long crow = offC + (long long)r * ldc;
            #pragma unroll
            for (int ni = 0; ni < 4; ni++) {
                int col = col0 + wn * 32 + ni * 8 + t4 * 2;
                if (col >= N) continue;
                float v0 = acc[mi][ni][half * 2 + 0] * scale;
                float v1 = acc[mi][ni][half * 2 + 1] * scale;
                if (bias) {
                    float2 bb = *(const float2*)(bias + col);
                    v0 += bb.x; v1 += bb.y;
                }
                if (qmul) {
                    float2 qq = *(const float2*)(qmul + crow + col);
                    v0 *= qq.x; v1 *= qq.y;
                }
                if (resid) {
                    float2 rr = *(const float2*)(resid + crow + col);
                    v0 += rr.x; v1 += rr.y;
                }
                if (gelu) { v0 *= normcdff(v0); v1 *= normcdff(v1); }
                if (Cf) *(float2*)(Cf + crow + col) = make_float2(v0, v1);
                if (Chi) {
                    bf16 h0, h1, l0, l1;
                    split_bf(v0, h0, l0); split_bf(v1, h1, l1);
                    bf162 hp; hp.x = h0; hp.y = h1;
                    bf162 lp; lp.x = l0; lp.y = l1;
                    *(bf162*)(Chi + crow + col) = hp;
                    *(bf162*)(Clo + crow + col) = lp;
                }
            }
        }
    }
}

// =================== fused flash attention (bf16x3 split) ====================
#define FA_KSZ 5120
#define FA_VSZ 7680
#define FA_STAGE (6*FA_KSZ + 4*FA_VSZ)   // 61440
#define FA_SMEM (2*FA_STAGE)             // 122880

__global__ void __launch_bounds__(256)
flash_attn(const bf16* __restrict__ Qh, const bf16* __restrict__ Ql,
           const bf16* __restrict__ Kh, const bf16* __restrict__ Kl,
           const bf16* __restrict__ Vth, const bf16* __restrict__ Vtl,
           bf16* __restrict__ Ohi, bf16* __restrict__ Olo)
{
    extern __shared__ __align__(16) char dsm[];
    uint32_t s0 = smem_u32(dsm);
    int tid = threadIdx.x, lane = tid & 31, warp = tid >> 5;
    int q0 = blockIdx.x * 128;
    int bh = blockIdx.y; int b = bh >> 3, h = bh & 7;
    long long qkbase = (long long)b * Ss * AHh + h * HDd;
    long long vbase  = (long long)b * AHh * Ss + (long long)h * HDd * Ss;

    #pragma unroll
    for (int i = 0; i < 12; i++) {
        int v = tid + i * 256;
        int sub = v >> 9, idx = v & 511;
        int chunk = sub >> 1, hl = sub & 1;
        int row = idx >> 2, cv = idx & 3;
        const bf16* src = (hl ? Ql : Qh) + qkbase + (long long)(q0 + row) * AHh + chunk * 32 + cv * 8;
        cpasync16(s0 + sub * 10240 + (row * ASTR + cv * 8) * 2, src);
    }
    asm volatile("cp.async.commit_group;");
    asm volatile("cp.async.wait_group 0;");
    __syncthreads();

    uint32_t qfh[6][4], qfl[6][4];
    {
        int arow = warp * 16 + (lane & 15);
        int acolb = (lane >> 4) << 3;
        #pragma unroll
        for (int kf = 0; kf < 6; kf++) {
            int chunk = kf >> 1, f = kf & 1;
            uint32_t off = (arow * ASTR + acolb + f * 16) * 2;
            ldm_x4(qfh[kf], s0 + (chunk * 2 + 0) * 10240 + off);
            ldm_x4(qfl[kf], s0 + (chunk * 2 + 1) * 10240 + off);
        }
    }
    __syncthreads();

    auto ld_kv = [&](int stg, int it) {
        int sq = it * 64;
        uint32_t base = s0 + stg * FA_STAGE;
        #pragma unroll
        for (int i = 0; i < 12; i++) {
            int v = tid + i * 256;
            if (v < 1536) {
                int sub = v >> 8, idx = v & 255;
                int hl = sub & 1, chunk = sub >> 1;
                int row = idx >> 2, cv = idx & 3;
                const bf16* src = (hl ? Kl : Kh) + qkbase + (long long)(sq + row) * AHh + chunk * 32 + cv * 8;
                cpasync16(base + sub * FA_KSZ + (row * ASTR + cv * 8) * 2, src);
            } else {
                int v2 = v - 1536;
                int sub = v2 / 384, idx = v2 % 384;
                int hl = sub & 1, chunk = sub >> 1;
                int row = idx >> 2, cv = idx & 3;
                const bf16* src = (hl ? Vtl : Vth) + vbase + (long long)row * Ss + sq + chunk * 32 + cv * 8;
                cpasync16(base + 6 * FA_KSZ + sub * FA_VSZ + (row * ASTR + cv * 8) * 2, src);
            }
        }
    };

    float m_[2] = {-1e30f, -1e30f};
    float l_[2] = {0.f, 0.f};
    float acc_o[12][4] = {};
    const float isq = rsqrtf(96.f);

    ld_kv(0, 0);
    asm volatile("cp.async.commit_group;");
    ld_kv(1, 1);
    asm volatile("cp.async.commit_group;");

    int brow = ((lane >> 4) & 1) * 8 + (lane & 7);
    int bcol = ((lane >> 3) & 1) * 8;

    for (int it = 0; it < 16; it++) {
        if (it + 1 < 16) asm volatile("cp.async.wait_group 1;");
        else             asm volatile("cp.async.wait_group 0;");
        __syncthreads();
        uint32_t kb = s0 + (it & 1) * FA_STAGE;
        uint32_t vb = kb + 6 * FA_KSZ;

        float s_[8][4] = {};
        #pragma unroll
        for (int kf = 0; kf < 6; kf++) {
            int chunk = kf >> 1, f = kf & 1;
            uint32_t bo = (brow * ASTR + bcol + f * 16) * 2;
            #pragma unroll
            for (int nq = 0; nq < 4; nq++) {
                uint32_t rh[4], rl[4];
                ldm_x4(rh, kb + (chunk * 2 + 0) * FA_KSZ + bo + nq * 16 * ASTR * 2);
                ldm_x4(rl, kb + (chunk * 2 + 1) * FA_KSZ + bo + nq * 16 * ASTR * 2);
                mma_bf16(s_[nq * 2],     qfh[kf], rh);
                mma_bf16(s_[nq * 2],     qfh[kf], rl);
                mma_bf16(s_[nq * 2],     qfl[kf], rh);
                mma_bf16(s_[nq * 2 + 1], qfh[kf], rh + 2);
                mma_bf16(s_[nq * 2 + 1], qfh[kf], rl + 2);
                mma_bf16(s_[nq * 2 + 1], qfl[kf], rh + 2);
            }
        }
        #pragma unroll
        for (int ni = 0; ni < 8; ni++)
            #pragma unroll
            for (int j = 0; j < 4; j++) s_[ni][j] *= isq;

        #pragma unroll
        for (int rh = 0; rh < 2; rh++) {
            float mx = -1e30f;
            #pragma unroll
            for (int ni = 0; ni < 8; ni++)
                mx = fmaxf(mx, fmaxf(s_[ni][rh * 2], s_[ni][rh * 2 + 1]));
            mx = fmaxf(mx, __shfl_xor_sync(0xffffffffu, mx, 1));
            mx = fmaxf(mx, __shfl_xor_sync(0xffffffffu, mx, 2));
            float mnew = fmaxf(m_[rh], mx);
            float a = __expf(m_[rh] - mnew);
            m_[rh] = mnew;
            float rs = 0.f;
            #pragma unroll
            for (int ni = 0; ni < 8; ni++) {
                float p0 = __expf(s_[ni][rh * 2] - mnew);
                float p1 = __expf(s_[ni][rh * 2 + 1] - mnew);
                s_[ni][rh * 2] = p0; s_[ni][rh * 2 + 1] = p1;
                rs += p0 + p1;
            }
            rs += __shfl_xor_sync(0xffffffffu, rs, 1);
            rs += __shfl_xor_sync(0xffffffffu, rs, 2);
            l_[rh] = l_[rh] * a + rs;
            #pragma unroll
            for (int ni = 0; ni < 12; ni++) {
                acc_o[ni][rh * 2] *= a; acc_o[ni][rh * 2 + 1] *= a;
            }
        }

        uint32_t pfh[4][4], pfl[4][4];
        #pragma unroll
        for (int kp = 0; kp < 4; kp++) {
            #pragma unroll
            for (int q = 0; q < 2; q++) {
                int ni = kp * 2 + q;
                float x0 = s_[ni][0], x1 = s_[ni][1], x2 = s_[ni][2], x3 = s_[ni][3];
                bf16 h0, l0, h1, l1, h2, l2, h3, l3;
                split_bf(x0, h0, l0); split_bf(x1, h1, l1);
                split_bf(x2, h2, l2); split_bf(x3, h3, l3);
                bf162 t;
                t.x = h0; t.y = h1; pfh[kp][q * 2 + 0] = *(uint32_t*)&t;
                t.x = h2; t.y = h3; pfh[kp][q * 2 + 1] = *(uint32_t*)&t;
                t.x = l0; t.y = l1; pfl[kp][q * 2 + 0] = *(uint32_t*)&t;
                t.x = l2; t.y = l3; pfl[kp][q * 2 + 1] = *(uint32_t*)&t;
            }
        }

        #pragma unroll
        for (int kp = 0; kp < 4; kp++) {
            int chunk = kp >> 1, f = kp & 1;
            uint32_t bo = (brow * ASTR + bcol + f * 16) * 2;
            #pragma unroll
            for (int nq = 0; nq < 6; nq++) {
                uint32_t rh[4], rl[4];
                ldm_x4(rh, vb + (chunk * 2 + 0) * FA_VSZ + bo + nq * 16 * ASTR * 2);
                ldm_x4(rl, vb + (chunk * 2 + 1) * FA_VSZ + bo + nq * 16 * ASTR * 2);
                mma_bf16(acc_o[nq * 2],     pfh[kp], rh);
                mma_bf16(acc_o[nq * 2],     pfh[kp], rl);
                mma_bf16(acc_o[nq * 2],     pfl[kp], rh);
                mma_bf16(acc_o[nq * 2 + 1], pfh[kp], rh + 2);
                mma_bf16(acc_o[nq * 2 + 1], pfh[kp], rl + 2);
                mma_bf16(acc_o[nq * 2 + 1], pfl[kp], rh + 2);
            }
        }
        __syncthreads();
        if (it + 2 < 16) {
            ld_kv(it & 1, it + 2);
            asm volatile("cp.async.commit_group;");
        }
    }

    int g4 = lane >> 2, t4 = lane & 3;
    #pragma unroll
    for (int rh = 0; rh < 2; rh++) {
        float inv = 1.f / l_[rh];
        int r = q0 + warp * 16 + g4 + rh * 8;
        long long orow = ((long long)b * Ss + r) * Hh + h * HDd;
        #pragma unroll
        for (int ni = 0; ni < 12; ni++) {
            int col = ni * 8 + t4 * 2;
            float v0 = acc_o[ni][rh * 2] * inv;
            float v1 = acc_o[ni][rh * 2 + 1] * inv;
            bf16 h0, l0, h1, l1;
            split_bf(v0, h0, l0); split_bf(v1, h1, l1);
            bf162 hp; hp.x = h0; hp.y = h1;
            bf162 lp; lp.x = l0; lp.y = l1;
            *(bf162*)(Ohi + orow + col) = hp;
            *(bf162*)(Olo + orow + col) = lp;
        }
    }
}

// ===================== conversion / transpose kernels ========================
__global__ void cvt_pair(const float* __restrict__ x, bf16* __restrict__ hi,
                         bf16* __restrict__ lo, long long n)
{
    long long i = ((long long)blockIdx.x * 256 + threadIdx.x) * 4;
    if (i >= n) return;
    float4 v = *(const float4*)(x + i);
    bf16 h0, h1, h2, h3, l0, l1, l2, l3;
    split_bf(v.x, h0, l0); split_bf(v.y, h1, l1);
    split_bf(v.z, h2, l2); split_bf(v.w, h3, l3);
    bf162 a; a.x = h0; a.y = h1;
    bf162 b; b.x = h2; b.y = h3;
    bf162 c; c.x = l0; c.y = l1;
    bf162 d; d.x = l2; d.y = l3;
    *(bf162*)(hi + i) = a; *(bf162*)(hi + i + 2) = b;
    *(bf162*)(lo + i) = c; *(bf162*)(lo + i + 2) = d;
}

__global__ void transpose_cvt(const float* __restrict__ src, bf16* __restrict__ hiT,
                              bf16* __restrict__ loT, int R, int C,
                              long long sSrc, long long sDst)
{
    __shared__ float t[32][33];
    src += (long long)blockIdx.z * sSrc;
    hiT += (long long)blockIdx.z * sDst;
    loT += (long long)blockIdx.z * sDst;
    int r0 = blockIdx.y * 32, c0 = blockIdx.x * 32;
    #pragma unroll
    for (int j = 0; j < 4; j++) {
        int rr = r0 + threadIdx.y + j * 8, cc = c0 + threadIdx.x;
        t[threadIdx.y + j * 8][threadIdx.x] =
            (rr < R && cc < C) ? src[(long long)rr * C + cc] : 0.f;
    }
    __syncthreads();
    #pragma unroll
    for (int j = 0; j < 4; j++) {
        int cc = c0 + threadIdx.y + j * 8, rr = r0 + threadIdx.x;
        if (cc < C && rr < R) {
            float v = t[threadIdx.x][threadIdx.y + j * 8];
            bf16 h, l; split_bf(v, h, l);
            hiT[(long long)cc * R + rr] = h;
            loT[(long long)cc * R + rr] = l;
        }
    }
}

// ======================= elementwise / reduction kernels =====================
__global__ void dconv_kernel(const float* __restrict__ e, const float* __restrict__ dw,
                             bf16* __restrict__ dh, bf16* __restrict__ dl)
{
    int i = blockIdx.x * blockDim.x + threadIdx.x;
    if (i >= Tt * Hh) return;
    int c = i % Hh, t = i / Hh;
    int s = t % Ss, b = t / Ss;
    float acc = 0.f;
    #pragma unroll
    for (int j = 0; j < KW; j++) {
        int ss = s + j - 3;
        if (ss >= 0 && ss < Ss)
            acc = fmaf(e[((long long)(b * Ss + ss)) * Hh + c], dw[c * KW + j], acc);
    }
    bf16 h, l; split_bf(acc, h, l);
    dh[i] = h; dl[i] = l;
}

__global__ void ck_softmax(float* __restrict__ ck)
{
    int r = blockIdx.x * blockDim.x + threadIdx.x;
    if (r >= Tt * NHh) return;
    float* p = ck + (long long)r * KW;
    float m = p[0];
    #pragma unroll
    for (int j = 1; j < KW; j++) m = fmaxf(m, p[j]);
    float s = 0.f, e[KW];
    #pragma unroll
    for (int j = 0; j < KW; j++) { e[j] = expf(p[j] - m); s += e[j]; }
    float inv = 1.f / s;
    #pragma unroll
    for (int j = 0; j < KW; j++) p[j] = e[j] * inv;
}

__global__ void conv_out_kernel(const float* __restrict__ co, const float* __restrict__ ck,
                                bf16* __restrict__ cthi, bf16* __restrict__ ctlo)
{
    int i = blockIdx.x * blockDim.x + threadIdx.x;
    if (i >= Tt * AHh) return;
    int c = i % AHh, t = i / AHh;
    int h = c / HDd;
    int s = t % Ss, b = t / Ss;
    const float* ckp = ck + (long long)t * (NHh * KW) + h * KW;
    float acc = 0.f;
    #pragma unroll
    for (int j = 0; j < KW; j++) {
        int ss = s + j - 3;
        if (ss >= 0 && ss < Ss)
            acc = fmaf(co[((long long)(b * Ss + ss)) * AHh + c], ckp[j], acc);
    }
    bf16 h_, l_; split_bf(acc, h_, l_);
    cthi[(long long)t * Hh + AHh + c] = h_;
    ctlo[(long long)t * Hh + AHh + c] = l_;
}

__global__ void layernorm(const float* __restrict__ x, const float* __restrict__ g,
                          const float* __restrict__ bb, float* __restrict__ y,
                          bf16* __restrict__ hi, bf16* __restrict__ lo)
{
    long long row = blockIdx.x;
    const float* p = x + row * Hh;
    __shared__ float red[256];
    int tid = threadIdx.x;
    float s = 0.f;
    for (int i = tid; i < Hh; i += 256) s += p[i];
    red[tid] = s; __syncthreads();
    for (int o = 128; o > 0; o >>= 1) { if (tid < o) red[tid] += red[tid + o]; __syncthreads(); }
    float m = red[0] / Hh; __syncthreads();
    float v = 0.f;
    for (int i = tid; i < Hh; i += 256) { float d = p[i] - m; v += d * d; }
    red[tid] = v; __syncthreads();
    for (int o = 128; o > 0; o >>= 1) { if (tid < o) red[tid] += red[tid + o]; __syncthreads(); }
    float inv = rsqrtf(red[0] / Hh + 1e-12f);
    for (int i = tid; i < Hh; i += 256) {
        float o = (p[i] - m) * inv * g[i] + bb[i];
        y[row * Hh + i] = o;
        if (hi) { bf16 h, l; split_bf(o, h, l); hi[row * Hh + i] = h; lo[row * Hh + i] = l; }
    }
}

// two-stage maxpool
__global__ void maxpool_part()
{
    int i = blockIdx.x * blockDim.x + threadIdx.x;
    if (i >= Bb * 8 * Hh) return;
    int c = i % Hh, rest = i / Hh;
    int chunk = rest & 7, b = rest >> 3;
    float m = -3.4e38f;
    int sbase = chunk * 128;
    for (int s = 0; s < 128; s++)
        m = fmaxf(m, g_lo[((long long)(b * Ss + sbase + s)) * Hh + c]);
    g_poolp[i] = m;
}
__global__ void maxpool_final()
{
    int i = blockIdx.x * blockDim.x + threadIdx.x;
    if (i >= Bb * Hh) return;
    int c = i % Hh, b = i / Hh;
    float m = -3.4e38f;
    #pragma unroll
    for (int ch = 0; ch < 8; ch++)
        m = fmaxf(m, g_poolp[(b * 8 + ch) * Hh + c]);
    g_pool[i] = m;
}

__global__ void decoder_kernel(const float* __restrict__ wd, const float* __restrict__ bd,
                               float* __restrict__ out)
{
    int b = blockIdx.x;
    __shared__ float red[256];
    int tid = threadIdx.x;
    float s = 0.f;
    for (int i = tid; i < Hh; i += 256) s += g_pool[b * Hh + i] * wd[i];
    red[tid] = s; __syncthreads();
    for (int o = 128; o > 0; o >>= 1) { if (tid < o) red[tid] += red[tid + o]; __syncthreads(); }
    if (tid == 0) out[b] = red[0] + bd[0];
}

// =============================================================================
extern "C" void kernel_launch(void* const* d_in, const int* in_sizes, int n_in,
                              void* d_out, int out_size)
{
    const float* embed = (const float*)d_in[0];
    const float* wq  = (const float*)d_in[1];  const float* bq  = (const float*)d_in[2];
    const float* wk  = (const float*)d_in[3];  const float* bk  = (const float*)d_in[4];
    const float* wv  = (const float*)d_in[5];  const float* bv  = (const float*)d_in[6];
    const float* dw  = (const float*)d_in[7];
    const float* pw  = (const float*)d_in[8];  const float* sep_b = (const float*)d_in[9];
    const float* wck = (const float*)d_in[10]; const float* bck = (const float*)d_in[11];
    const float* wco = (const float*)d_in[12]; const float* bco = (const float*)d_in[13];
    const float* wso = (const float*)d_in[14]; const float* bso = (const float*)d_in[15];
    const float* ln1_g = (const float*)d_in[16]; const float* ln1_b = (const float*)d_in[17];
    const float* wi  = (const float*)d_in[18]; const float* bi  = (const float*)d_in[19];
    const float* wo  = (const float*)d_in[20]; const float* bo  = (const float*)d_in[21];
    const float* ln2_g = (const float*)d_in[22]; const float* ln2_b = (const float*)d_in[23];
    const float* wd  = (const float*)d_in[24]; const float* bd  = (const float*)d_in[25];
    float* out = (float*)d_out;

    cudaFuncSetAttribute(gemm_bf16s, cudaFuncAttributeMaxDynamicSharedMemorySize, GSMEM);
    cudaFuncSetAttribute(flash_attn, cudaFuncAttributeMaxDynamicSharedMemorySize, FA_SMEM);

    #define SYM(p, s) void* p##_; cudaGetSymbolAddress(&p##_, s); auto p = (decltype(&s[0]))p##_
    SYM(pck, g_ck); SYM(pattn, g_attn);
    SYM(ppre, g_pre); SYM(plo, g_lo);
    SYM(p4f, g_p4f); SYM(p4hi, g_p4hi); SYM(p4lo, g_p4lo);
    SYM(ehi, g_ehi); SYM(elo, g_elo);
    SYM(vThi, g_vThi); SYM(vTlo, g_vTlo);
    SYM(dchi, g_dchi); SYM(dclo, g_dclo);
    SYM(cahi, g_cahi); SYM(calo, g_calo);
    SYM(cthi, g_cthi); SYM(ctlo, g_ctlo);
    SYM(athi, g_athi); SYM(atlo, g_atlo);
    SYM(inhi, g_inhi); SYM(inlo, g_inlo);
    SYM(w4Thi, g_w4Thi); SYM(w4Tlo, g_w4Tlo);
    SYM(pwThi, g_pwThi); SYM(pwTlo, g_pwTlo);
    SYM(wckThi, g_wckThi); SYM(wckTlo, g_wckTlo);
    SYM(wsoThi, g_wsoThi); SYM(wsoTlo, g_wsoTlo);
    SYM(wiThi, g_wiThi); SYM(wiTlo, g_wiTlo);
    SYM(woThi, g_woThi); SYM(woTlo, g_woTlo);
    #undef SYM

    // fork/join side stream for glue overlap (host objects; no device alloc)
    cudaStream_t s2;
    cudaStreamCreateWithFlags(&s2, cudaStreamNonBlocking);
    cudaEvent_t evFork, evProj, evConv;
    cudaEventCreateWithFlags(&evFork, cudaEventDisableTiming);
    cudaEventCreateWithFlags(&evProj, cudaEventDisableTiming);
    cudaEventCreateWithFlags(&evConv, cudaEventDisableTiming);

    dim3 blk(256);
    auto gemm = [&](cudaStream_t st,
                    const bf16* Ah, const bf16* Al, const bf16* Bh, const bf16* Bl,
                    Ptr4 bs, int nbias, const float* resid, const float* qmul,
                    float* Cf, bf16* Chi, bf16* Clo,
                    int M, int N, int K, int lda, int ldb, int ldc,
                    long long iA, long long iB, long long iC, int z,
                    float scale, int gelu) {
        dim3 grid((N + 127) / 128, M / 128, z);
        gemm_bf16s<<<grid, blk, GSMEM, st>>>(Ah, Al, Bh, Bl, bs, nbias, resid, qmul,
                                             Cf, Chi, Clo, N, K, lda, ldb, ldc,
                                             iA, iB, iC, scale, gelu);
    };
    auto tcvt = [&](cudaStream_t st, const float* src, bf16* hiT, bf16* loT,
                    int R, int C, long long sS, long long sD, int z) {
        dim3 g((C + 31) / 32, (R + 31) / 32, z);
        transpose_cvt<<<g, dim3(32, 8), 0, st>>>(src, hiT, loT, R, C, sS, sD);
    };

    const long long WSL = (long long)AHh * Hh;

    // ---- fork ----
    cudaEventRecord(evFork, 0);
    cudaStreamWaitEvent(s2, evFork, 0);

    // ===== main stream: projections -> attention path =====
    cvt_pair<<<(Tt * Hh) / 1024, blk>>>(embed, ehi, elo, (long long)Tt * Hh);
    tcvt(0, wq, w4Thi + 0 * WSL, w4Tlo + 0 * WSL, Hh, AHh, 0, 0, 1);
    tcvt(0, wk, w4Thi + 1 * WSL, w4Tlo + 1 * WSL, Hh, AHh, 0, 0, 1);
    tcvt(0, wv, w4Thi + 2 * WSL, w4Tlo + 2 * WSL, Hh, AHh, 0, 0, 1);
    tcvt(0, wco, w4Thi + 3 * WSL, w4Tlo + 3 * WSL, Hh, AHh, 0, 0, 1);
    gemm(0, ehi, elo, w4Thi, w4Tlo, Ptr4{{bq, bk, bv, bco}}, 4, nullptr, nullptr,
         p4f, p4hi, p4lo, Tt, AHh, Hh, Hh, Hh, AHh, 0, WSL, SLICE, 4, 1.f, 0);
    cudaEventRecord(evProj, 0);
    tcvt(0, p4f + 2 * SLICE, vThi, vTlo, Ss, AHh, (long long)Ss * AHh, (long long)AHh * Ss, Bb);
    flash_attn<<<dim3(Ss / 128, Bb * NHh), blk, FA_SMEM>>>(
        p4hi + 0 * SLICE, p4lo + 0 * SLICE, p4hi + 1 * SLICE, p4lo + 1 * SLICE,
        vThi, vTlo, cthi, ctlo);

    // ===== side stream: weight transposes + depthwise + dynamic conv path =====
    tcvt(s2, pw, pwThi, pwTlo, Hh, AHh, 0, 0, 1);
    tcvt(s2, wck, wckThi, wckTlo, AHh, NHh * KW, 0, 0, 1);
    tcvt(s2, wso, wsoThi, wsoTlo, Hh, Hh, 0, 0, 1);
    tcvt(s2, wi, wiThi, wiTlo, Hh, IMm, 0, 0, 1);
    tcvt(s2, wo, woThi, woTlo, IMm, Hh, 0, 0, 1);
    dconv_kernel<<<(Tt * Hh + 255) / 256, blk, 0, s2>>>(embed, dw, dchi, dclo);
    cudaStreamWaitEvent(s2, evProj, 0);
    // pw GEMM with fused conv_attn epilogue: (dconv@pw + sep_b) * q -> pairs
    gemm(s2, dchi, dclo, pwThi, pwTlo, Ptr4{{sep_b}}, 1, nullptr, p4f + 0 * SLICE,
         nullptr, cahi, calo, Tt, AHh, Hh, Hh, Hh, AHh, 0, 0, 0, 1, 1.f, 0);
    gemm(s2, cahi, calo, wckThi, wckTlo, Ptr4{{bck}}, 1, nullptr, nullptr,
         pck, nullptr, nullptr, Tt, NHh * KW, AHh, AHh, AHh, NHh * KW, 0, 0, 0, 1, 1.f, 0);
    ck_softmax<<<(Tt * NHh + 255) / 256, blk, 0, s2>>>(pck);
    conv_out_kernel<<<(Tt * AHh + 255) / 256, blk, 0, s2>>>(p4f + 3 * SLICE, pck, cthi, ctlo);
    cudaEventRecord(evConv, s2);

    // ---- join ----
    cudaStreamWaitEvent(0, evConv, 0);

    // self output + LN1
    gemm(0, cthi, ctlo, wsoThi, wsoTlo, Ptr4{{bso}}, 1, embed, nullptr,
         ppre, nullptr, nullptr, Tt, Hh, Hh, Hh, Hh, Hh, 0, 0, 0, 1, 1.f, 0);
    layernorm<<<Tt, blk>>>(ppre, ln1_g, ln1_b, pattn, athi, atlo);

    // FFN
    gemm(0, athi, atlo, wiThi, wiTlo, Ptr4{{bi}}, 1, nullptr, nullptr,
         nullptr, inhi, inlo, Tt, IMm, Hh, Hh, Hh, IMm, 0, 0, 0, 1, 1.f, 1);
    gemm(0, inhi, inlo, woThi, woTlo, Ptr4{{bo}}, 1, pattn, nullptr,
         ppre, nullptr, nullptr, Tt, Hh, IMm, IMm, IMm, Hh, 0, 0, 0, 1, 1.f, 0);
    layernorm<<<Tt, blk>>>(ppre, ln2_g, ln2_b, plo, nullptr, nullptr);

    // pool + decode
    maxpool_part<<<(Bb * 8 * Hh + 255) / 256, blk>>>();
    maxpool_final<<<(Bb * Hh + 255) / 256, blk>>>();
    decoder_kernel<<<Bb, blk>>>(wd, bd, out);
}

// round 8
// speedup vs baseline: 3.6130x; 1.0444x over previous
#include <cuda_runtime.h>
#include <cuda_bf16.h>
#include <math.h>
#include <stdint.h>

#define Bb 8
#define Ss 1024
#define Hh 1536
#define NHh 8
#define HDd 96
#define AHh 768
#define KW 7
#define IMm 3072
#define Tt (Bb*Ss)

typedef __nv_bfloat16 bf16;
typedef __nv_bfloat162 bf162;

#define SLICE ((long long)Tt*AHh)

// ======================= device scratch (no runtime alloc) ==================
#define DEVARR(ty, nm, sz) __device__ __align__(256) ty nm[sz]
DEVARR(float, g_sep, Tt*AHh);
DEVARR(float, g_ck, Tt*NHh*KW);
DEVARR(float, g_attn, Tt*Hh);
DEVARR(float, g_pre, Tt*Hh);
DEVARR(float, g_lo, Tt*Hh);
DEVARR(float, g_poolp, Bb*8*Hh);
DEVARR(float, g_pool, Bb*Hh);
__device__ __align__(256) float g_p4f[4ll*Tt*AHh];
__device__ __align__(256) bf16 g_p4hi[4ll*Tt*AHh];
__device__ __align__(256) bf16 g_p4lo[4ll*Tt*AHh];
DEVARR(bf16, g_ehi, Tt*Hh);  DEVARR(bf16, g_elo, Tt*Hh);
DEVARR(bf16, g_vThi, Tt*AHh); DEVARR(bf16, g_vTlo, Tt*AHh);   // [B][AH][S]
DEVARR(bf16, g_dchi, Tt*Hh); DEVARR(bf16, g_dclo, Tt*Hh);
DEVARR(bf16, g_cahi, Tt*AHh); DEVARR(bf16, g_calo, Tt*AHh);
DEVARR(bf16, g_cthi, Tt*Hh); DEVARR(bf16, g_ctlo, Tt*Hh);
DEVARR(bf16, g_athi, Tt*Hh); DEVARR(bf16, g_atlo, Tt*Hh);
DEVARR(bf16, g_inhi, Tt*IMm); DEVARR(bf16, g_inlo, Tt*IMm);
__device__ __align__(256) bf16 g_w4Thi[4*AHh*Hh];
__device__ __align__(256) bf16 g_w4Tlo[4*AHh*Hh];
DEVARR(bf16, g_pwThi, AHh*Hh); DEVARR(bf16, g_pwTlo, AHh*Hh);
DEVARR(bf16, g_wckThi, (NHh*KW)*AHh); DEVARR(bf16, g_wckTlo, (NHh*KW)*AHh);
DEVARR(bf16, g_wsoThi, Hh*Hh); DEVARR(bf16, g_wsoTlo, Hh*Hh);
__device__ __align__(256) bf16 g_wiThi[(long long)IMm*Hh];
__device__ __align__(256) bf16 g_wiTlo[(long long)IMm*Hh];
__device__ __align__(256) bf16 g_woThi[(long long)Hh*IMm];
__device__ __align__(256) bf16 g_woTlo[(long long)Hh*IMm];

// ============================ helpers ====================================
__device__ __forceinline__ uint32_t smem_u32(const void* p) {
    uint32_t a;
    asm("{ .reg .u64 t; cvta.to.shared.u64 t, %1; cvt.u32.u64 %0, t; }" : "=r"(a) : "l"(p));
    return a;
}
__device__ __forceinline__ void cpasync16(uint32_t saddr, const void* g) {
    asm volatile("cp.async.cg.shared.global [%0], [%1], 16;" :: "r"(saddr), "l"(g));
}
__device__ __forceinline__ void ldm_x4(uint32_t* r, uint32_t addr) {
    asm volatile("ldmatrix.sync.aligned.m8n8.x4.shared.b16 {%0,%1,%2,%3}, [%4];"
                 : "=r"(r[0]), "=r"(r[1]), "=r"(r[2]), "=r"(r[3]) : "r"(addr));
}
__device__ __forceinline__ void mma_bf16(float* c, const uint32_t* a, const uint32_t* b) {
    asm volatile("mma.sync.aligned.m16n8k16.row.col.f32.bf16.bf16.f32 "
                 "{%0,%1,%2,%3}, {%4,%5,%6,%7}, {%8,%9}, {%0,%1,%2,%3};"
                 : "+f"(c[0]), "+f"(c[1]), "+f"(c[2]), "+f"(c[3])
                 : "r"(a[0]), "r"(a[1]), "r"(a[2]), "r"(a[3]), "r"(b[0]), "r"(b[1]));
}
__device__ __forceinline__ void split_bf(float v, bf16& h, bf16& l) {
    h = __float2bfloat16(v);
    l = __float2bfloat16(v - __bfloat162float(h));
}

#define MAXZ 5
struct GArgs {
    const bf16* Ah[MAXZ]; const bf16* Al[MAXZ];
    const bf16* Bh[MAXZ]; const bf16* Bl[MAXZ];
    const float* bias[MAXZ];
    float* Cf[MAXZ]; bf16* Chi[MAXZ]; bf16* Clo[MAXZ];
    const float* resid;
};

// =================== fused bf16x3-split mma.sync GEMM ========================
#define ASTR 40
#define TILE_B (128*ASTR*2)      // 10240
#define STG_B  (4*TILE_B)        // 40960
#define GSMEM  (2*STG_B)         // 81920

__global__ void __launch_bounds__(256, 2)
gemm_bf16s(GArgs ga, int N, int Kd, int lda, int ldb, int ldc,
           float scale, int gelu)
{
    extern __shared__ __align__(16) char dsm[];
    uint32_t s0 = smem_u32(dsm);

    int tid = threadIdx.x, lane = tid & 31, warp = tid >> 5;
    int wm = warp >> 2, wn = warp & 3;
    int row0 = blockIdx.y * 128, col0 = blockIdx.x * 128;
    int z = blockIdx.z;
    const bf16* Ah = ga.Ah[z]; const bf16* Al = ga.Al[z];
    const bf16* Bh = ga.Bh[z]; const bf16* Bl = ga.Bl[z];
    const float* bias = ga.bias[z];
    float* Cf = ga.Cf[z]; bf16* Chi = ga.Chi[z]; bf16* Clo = ga.Clo[z];
    const float* resid = ga.resid;

    if (N - col0 < 128) {
        const uint4 zz = make_uint4(0, 0, 0, 0);
        for (int c = tid; c < 2 * (2 * TILE_B / 16); c += 256) {
            int stg = c / (2 * TILE_B / 16);
            int idx = c % (2 * TILE_B / 16);
            *(uint4*)(dsm + stg * STG_B + 2 * TILE_B + idx * 16) = zz;
        }
        __syncthreads();
    }

    int c0i = tid * 2, c1i = tid * 2 + 1;
    int ar0 = c0i >> 2, ac0 = (c0i & 3) * 8;
    int ar1 = c1i >> 2, ac1 = (c1i & 3) * 8;
    int nkb = Kd >> 5;

    auto ld_stage = [&](int stg, int ks) {
        int k0 = ks << 5;
        uint32_t base = s0 + stg * STG_B;
        long long a0 = (long long)(row0 + ar0) * lda + k0;
        long long a1 = (long long)(row0 + ar1) * lda + k0;
        cpasync16(base + (ar0 * ASTR + ac0) * 2, Ah + a0 + ac0);
        cpasync16(base + (ar1 * ASTR + ac1) * 2, Ah + a1 + ac1);
        cpasync16(base + TILE_B + (ar0 * ASTR + ac0) * 2, Al + a0 + ac0);
        cpasync16(base + TILE_B + (ar1 * ASTR + ac1) * 2, Al + a1 + ac1);
        if (col0 + ar0 < N) {
            long long b0 = (long long)(col0 + ar0) * ldb + k0;
            cpasync16(base + 2 * TILE_B + (ar0 * ASTR + ac0) * 2, Bh + b0 + ac0);
            cpasync16(base + 3 * TILE_B + (ar0 * ASTR + ac0) * 2, Bl + b0 + ac0);
        }
        if (col0 + ar1 < N) {
            long long b1 = (long long)(col0 + ar1) * ldb + k0;
            cpasync16(base + 2 * TILE_B + (ar1 * ASTR + ac1) * 2, Bh + b1 + ac1);
            cpasync16(base + 3 * TILE_B + (ar1 * ASTR + ac1) * 2, Bl + b1 + ac1);
        }
    };

    float acc[4][4][4] = {};

    ld_stage(0, 0);
    asm volatile("cp.async.commit_group;");

    for (int s = 0; s < nkb; s++) {
        if (s + 1 < nkb) {
            ld_stage((s + 1) & 1, s + 1);
            asm volatile("cp.async.commit_group;");
            asm volatile("cp.async.wait_group 1;");
        } else {
            asm volatile("cp.async.wait_group 0;");
        }
        __syncthreads();

        uint32_t aH = s0 + (s & 1) * STG_B;
        uint32_t aL = aH + TILE_B;
        uint32_t bH = aH + 2 * TILE_B;
        uint32_t bL = aH + 3 * TILE_B;

        #pragma unroll
        for (int kf = 0; kf < 2; kf++) {
            int arow = wm * 64 + (lane & 15);
            int acol = ((lane >> 4) << 3) + kf * 16;
            uint32_t ah[4][4], al[4][4];
            #pragma unroll
            for (int mi = 0; mi < 4; mi++) {
                uint32_t aoff = ((arow + mi * 16) * ASTR + acol) * 2;
                ldm_x4(ah[mi], aH + aoff);
                ldm_x4(al[mi], aL + aoff);
            }
            int brow = wn * 32 + ((lane >> 4) & 1) * 8 + (lane & 7);
            int bcol = (((lane >> 3) & 1) << 3) + kf * 16;
            #pragma unroll
            for (int nq = 0; nq < 2; nq++) {
                uint32_t boff = ((brow + nq * 16) * ASTR + bcol) * 2;
                uint32_t r[4];
                ldm_x4(r, bH + boff);
                #pragma unroll
                for (int mi = 0; mi < 4; mi++) {
                    mma_bf16(acc[mi][nq * 2],     ah[mi], r);
                    mma_bf16(acc[mi][nq * 2],     al[mi], r);
                    mma_bf16(acc[mi][nq * 2 + 1], ah[mi], r + 2);
                    mma_bf16(acc[mi][nq * 2 + 1], al[mi], r + 2);
                }
                ldm_x4(r, bL + boff);
                #pragma unroll
                for (int mi = 0; mi < 4; mi++) {
                    mma_bf16(acc[mi][nq * 2],     ah[mi], r);
                    mma_bf16(acc[mi][nq * 2 + 1], ah[mi], r + 2);
                }
            }
        }
        __syncthreads();
    }

    int g4 = lane >> 2, t4 = lane & 3;
    #pragma unroll
    for (int mi = 0; mi < 4; mi++) {
        #pragma unroll
        for (int half = 0; half < 2; half++) {
            int r = row0 + wm * 64 + mi * 16 + g4 + half * 8;
            long long crow = (long long)r * ldc;
            #pragma unroll
            for (int ni = 0; ni < 4; ni++) {
                int col = col0 + wn * 32 + ni * 8 + t4 * 2;
                if (col >= N) continue;
                float v0 = acc[mi][ni][half * 2 + 0] * scale;
                float v1 = acc[mi][ni][half * 2 + 1] * scale;
                if (bias) {
                    float2 bb = *(const float2*)(bias + col);
                    v0 += bb.x; v1 += bb.y;
                }
                if (resid) {
                    float2 rr = *(const float2*)(resid + crow + col);
                    v0 += rr.x; v1 += rr.y;
                }
                if (gelu) { v0 *= normcdff(v0); v1 *= normcdff(v1); }
                if (Cf) *(float2*)(Cf + crow + col) = make_float2(v0, v1);
                if (Chi) {
                    bf16 h0, h1, l0, l1;
                    split_bf(v0, h0, l0); split_bf(v1, h1, l1);
                    bf162 hp; hp.x = h0; hp.y = h1;
                    bf162 lp; lp.x = l0; lp.y = l1;
                    *(bf162*)(Chi + crow + col) = hp;
                    *(bf162*)(Clo + crow + col) = lp;
                }
            }
        }
    }
}

// =================== fused flash attention (bf16x3 split) ====================
#define FA_KSZ 5120
#define FA_VSZ 7680
#define FA_STAGE (6*FA_KSZ + 4*FA_VSZ)   // 61440
#define FA_SMEM (2*FA_STAGE)             // 122880

__global__ void __launch_bounds__(256)
flash_attn(const bf16* __restrict__ Qh, const bf16* __restrict__ Ql,
           const bf16* __restrict__ Kh, const bf16* __restrict__ Kl,
           const bf16* __restrict__ Vth, const bf16* __restrict__ Vtl,
           bf16* __restrict__ Ohi, bf16* __restrict__ Olo)
{
    extern __shared__ __align__(16) char dsm[];
    uint32_t s0 = smem_u32(dsm);
    int tid = threadIdx.x, lane = tid & 31, warp = tid >> 5;
    int q0 = blockIdx.x * 128;
    int bh = blockIdx.y; int b = bh >> 3, h = bh & 7;
    long long qkbase = (long long)b * Ss * AHh + h * HDd;
    long long vbase  = (long long)b * AHh * Ss + (long long)h * HDd * Ss;

    #pragma unroll
    for (int i = 0; i < 12; i++) {
        int v = tid + i * 256;
        int sub = v >> 9, idx = v & 511;
        int chunk = sub >> 1, hl = sub & 1;
        int row = idx >> 2, cv = idx & 3;
        const bf16* src = (hl ? Ql : Qh) + qkbase + (long long)(q0 + row) * AHh + chunk * 32 + cv * 8;
        cpasync16(s0 + sub * 10240 + (row * ASTR + cv * 8) * 2, src);
    }
    asm volatile("cp.async.commit_group;");
    asm volatile("cp.async.wait_group 0;");
    __syncthreads();

    uint32_t qfh[6][4], qfl[6][4];
    {
        int arow = warp * 16 + (lane & 15);
        int acolb = (lane >> 4) << 3;
        #pragma unroll
        for (int kf = 0; kf < 6; kf++) {
            int chunk = kf >> 1, f = kf & 1;
            uint32_t off = (arow * ASTR + acolb + f * 16) * 2;
            ldm_x4(qfh[kf], s0 + (chunk * 2 + 0) * 10240 + off);
            ldm_x4(qfl[kf], s0 + (chunk * 2 + 1) * 10240 + off);
        }
    }
    __syncthreads();

    auto ld_kv = [&](int stg, int it) {
        int sq = it * 64;
        uint32_t base = s0 + stg * FA_STAGE;
        #pragma unroll
        for (int i = 0; i < 12; i++) {
            int v = tid + i * 256;
            if (v < 1536) {
                int sub = v >> 8, idx = v & 255;
                int hl = sub & 1, chunk = sub >> 1;
                int row = idx >> 2, cv = idx & 3;
                const bf16* src = (hl ? Kl : Kh) + qkbase + (long long)(sq + row) * AHh + chunk * 32 + cv * 8;
                cpasync16(base + sub * FA_KSZ + (row * ASTR + cv * 8) * 2, src);
            } else {
                int v2 = v - 1536;
                int sub = v2 / 384, idx = v2 % 384;
                int hl = sub & 1, chunk = sub >> 1;
                int row = idx >> 2, cv = idx & 3;
                const bf16* src = (hl ? Vtl : Vth) + vbase + (long long)row * Ss + sq + chunk * 32 + cv * 8;
                cpasync16(base + 6 * FA_KSZ + sub * FA_VSZ + (row * ASTR + cv * 8) * 2, src);
            }
        }
    };

    float m_[2] = {-1e30f, -1e30f};
    float l_[2] = {0.f, 0.f};
    float acc_o[12][4] = {};
    const float isq = rsqrtf(96.f);

    ld_kv(0, 0);
    asm volatile("cp.async.commit_group;");
    ld_kv(1, 1);
    asm volatile("cp.async.commit_group;");

    int brow = ((lane >> 4) & 1) * 8 + (lane & 7);
    int bcol = ((lane >> 3) & 1) * 8;

    for (int it = 0; it < 16; it++) {
        if (it + 1 < 16) asm volatile("cp.async.wait_group 1;");
        else             asm volatile("cp.async.wait_group 0;");
        __syncthreads();
        uint32_t kb = s0 + (it & 1) * FA_STAGE;
        uint32_t vb = kb + 6 * FA_KSZ;

        float s_[8][4] = {};
        #pragma unroll
        for (int kf = 0; kf < 6; kf++) {
            int chunk = kf >> 1, f = kf & 1;
            uint32_t bo = (brow * ASTR + bcol + f * 16) * 2;
            #pragma unroll
            for (int nq = 0; nq < 4; nq++) {
                uint32_t rh[4], rl[4];
                ldm_x4(rh, kb + (chunk * 2 + 0) * FA_KSZ + bo + nq * 16 * ASTR * 2);
                ldm_x4(rl, kb + (chunk * 2 + 1) * FA_KSZ + bo + nq * 16 * ASTR * 2);
                mma_bf16(s_[nq * 2],     qfh[kf], rh);
                mma_bf16(s_[nq * 2],     qfh[kf], rl);
                mma_bf16(s_[nq * 2],     qfl[kf], rh);
                mma_bf16(s_[nq * 2 + 1], qfh[kf], rh + 2);
                mma_bf16(s_[nq * 2 + 1], qfh[kf], rl + 2);
                mma_bf16(s_[nq * 2 + 1], qfl[kf], rh + 2);
            }
        }
        #pragma unroll
        for (int ni = 0; ni < 8; ni++)
            #pragma unroll
            for (int j = 0; j < 4; j++) s_[ni][j] *= isq;

        #pragma unroll
        for (int rh = 0; rh < 2; rh++) {
            float mx = -1e30f;
            #pragma unroll
            for (int ni = 0; ni < 8; ni++)
                mx = fmaxf(mx, fmaxf(s_[ni][rh * 2], s_[ni][rh * 2 + 1]));
            mx = fmaxf(mx, __shfl_xor_sync(0xffffffffu, mx, 1));
            mx = fmaxf(mx, __shfl_xor_sync(0xffffffffu, mx, 2));
            float mnew = fmaxf(m_[rh], mx);
            float a = __expf(m_[rh] - mnew);
            m_[rh] = mnew;
            float rs = 0.f;
            #pragma unroll
            for (int ni = 0; ni < 8; ni++) {
                float p0 = __expf(s_[ni][rh * 2] - mnew);
                float p1 = __expf(s_[ni][rh * 2 + 1] - mnew);
                s_[ni][rh * 2] = p0; s_[ni][rh * 2 + 1] = p1;
                rs += p0 + p1;
            }
            rs += __shfl_xor_sync(0xffffffffu, rs, 1);
            rs += __shfl_xor_sync(0xffffffffu, rs, 2);
            l_[rh] = l_[rh] * a + rs;
            #pragma unroll
            for (int ni = 0; ni < 12; ni++) {
                acc_o[ni][rh * 2] *= a; acc_o[ni][rh * 2 + 1] *= a;
            }
        }

        uint32_t pfh[4][4], pfl[4][4];
        #pragma unroll
        for (int kp = 0; kp < 4; kp++) {
            #pragma unroll
            for (int q = 0; q < 2; q++) {
                int ni = kp * 2 + q;
                float x0 = s_[ni][0], x1 = s_[ni][1], x2 = s_[ni][2], x3 = s_[ni][3];
                bf16 h0, l0, h1, l1, h2, l2, h3, l3;
                split_bf(x0, h0, l0); split_bf(x1, h1, l1);
                split_bf(x2, h2, l2); split_bf(x3, h3, l3);
                bf162 t;
                t.x = h0; t.y = h1; pfh[kp][q * 2 + 0] = *(uint32_t*)&t;
                t.x = h2; t.y = h3; pfh[kp][q * 2 + 1] = *(uint32_t*)&t;
                t.x = l0; t.y = l1; pfl[kp][q * 2 + 0] = *(uint32_t*)&t;
                t.x = l2; t.y = l3; pfl[kp][q * 2 + 1] = *(uint32_t*)&t;
            }
        }

        #pragma unroll
        for (int kp = 0; kp < 4; kp++) {
            int chunk = kp >> 1, f = kp & 1;
            uint32_t bo = (brow * ASTR + bcol + f * 16) * 2;
            #pragma unroll
            for (int nq = 0; nq < 6; nq++) {
                uint32_t rh[4], rl[4];
                ldm_x4(rh, vb + (chunk * 2 + 0) * FA_VSZ + bo + nq * 16 * ASTR * 2);
                ldm_x4(rl, vb + (chunk * 2 + 1) * FA_VSZ + bo + nq * 16 * ASTR * 2);
                mma_bf16(acc_o[nq * 2],     pfh[kp], rh);
                mma_bf16(acc_o[nq * 2],     pfh[kp], rl);
                mma_bf16(acc_o[nq * 2],     pfl[kp], rh);
                mma_bf16(acc_o[nq * 2 + 1], pfh[kp], rh + 2);
                mma_bf16(acc_o[nq * 2 + 1], pfh[kp], rl + 2);
                mma_bf16(acc_o[nq * 2 + 1], pfl[kp], rh + 2);
            }
        }
        __syncthreads();
        if (it + 2 < 16) {
            ld_kv(it & 1, it + 2);
            asm volatile("cp.async.commit_group;");
        }
    }

    int g4 = lane >> 2, t4 = lane & 3;
    #pragma unroll
    for (int rh = 0; rh < 2; rh++) {
        float inv = 1.f / l_[rh];
        int r = q0 + warp * 16 + g4 + rh * 8;
        long long orow = ((long long)b * Ss + r) * Hh + h * HDd;
        #pragma unroll
        for (int ni = 0; ni < 12; ni++) {
            int col = ni * 8 + t4 * 2;
            float v0 = acc_o[ni][rh * 2] * inv;
            float v1 = acc_o[ni][rh * 2 + 1] * inv;
            bf16 h0, l0, h1, l1;
            split_bf(v0, h0, l0); split_bf(v1, h1, l1);
            bf162 hp; hp.x = h0; hp.y = h1;
            bf162 lp; lp.x = l0; lp.y = l1;
            *(bf162*)(Ohi + orow + col) = hp;
            *(bf162*)(Olo + orow + col) = lp;
        }
    }
}

// ===================== conversion / transpose kernels ========================
__global__ void cvt_pair(const float* __restrict__ x, bf16* __restrict__ hi,
                         bf16* __restrict__ lo, long long n)
{
    long long i = ((long long)blockIdx.x * 256 + threadIdx.x) * 4;
    if (i >= n) return;
    float4 v = *(const float4*)(x + i);
    bf16 h0, h1, h2, h3, l0, l1, l2, l3;
    split_bf(v.x, h0, l0); split_bf(v.y, h1, l1);
    split_bf(v.z, h2, l2); split_bf(v.w, h3, l3);
    bf162 a; a.x = h0; a.y = h1;
    bf162 b; b.x = h2; b.y = h3;
    bf162 c; c.x = l0; c.y = l1;
    bf162 d; d.x = l2; d.y = l3;
    *(bf162*)(hi + i) = a; *(bf162*)(hi + i + 2) = b;
    *(bf162*)(lo + i) = c; *(bf162*)(lo + i + 2) = d;
}

__global__ void transpose_cvt(const float* __restrict__ src, bf16* __restrict__ hiT,
                              bf16* __restrict__ loT, int R, int C,
                              long long sSrc, long long sDst)
{
    __shared__ float t[32][33];
    src += (long long)blockIdx.z * sSrc;
    hiT += (long long)blockIdx.z * sDst;
    loT += (long long)blockIdx.z * sDst;
    int r0 = blockIdx.y * 32, c0 = blockIdx.x * 32;
    #pragma unroll
    for (int j = 0; j < 4; j++) {
        int rr = r0 + threadIdx.y + j * 8, cc = c0 + threadIdx.x;
        t[threadIdx.y + j * 8][threadIdx.x] =
            (rr < R && cc < C) ? src[(long long)rr * C + cc] : 0.f;
    }
    __syncthreads();
    #pragma unroll
    for (int j = 0; j < 4; j++) {
        int cc = c0 + threadIdx.y + j * 8, rr = r0 + threadIdx.x;
        if (cc < C && rr < R) {
            float v = t[threadIdx.x][threadIdx.y + j * 8];
            bf16 h, l; split_bf(v, h, l);
            hiT[(long long)cc * R + rr] = h;
            loT[(long long)cc * R + rr] = l;
        }
    }
}

__global__ void mul_cvt(const float* __restrict__ sep, const float* __restrict__ q,
                        bf16* __restrict__ chi, bf16* __restrict__ clo)
{
    long long i = ((long long)blockIdx.x * 256 + threadIdx.x) * 4;
    if (i >= (long long)Tt * AHh) return;
    float4 s = *(const float4*)(sep + i);
    float4 qq = *(const float4*)(q + i);
    float m0 = s.x * qq.x, m1 = s.y * qq.y, m2 = s.z * qq.z, m3 = s.w * qq.w;
    bf16 h0, h1, h2, h3, l0, l1, l2, l3;
    split_bf(m0, h0, l0); split_bf(m1, h1, l1);
    split_bf(m2, h2, l2); split_bf(m3, h3, l3);
    bf162 a; a.x = h0; a.y = h1;
    bf162 b; b.x = h2; b.y = h3;
    bf162 c; c.x = l0; c.y = l1;
    bf162 d; d.x = l2; d.y = l3;
    *(bf162*)(chi + i) = a; *(bf162*)(chi + i + 2) = b;
    *(bf162*)(clo + i) = c; *(bf162*)(clo + i + 2) = d;
}

// ======================= elementwise / reduction kernels =====================
__global__ void dconv_kernel(const float* __restrict__ e, const float* __restrict__ dw,
                             bf16* __restrict__ dh, bf16* __restrict__ dl)
{
    int i = blockIdx.x * blockDim.x + threadIdx.x;
    if (i >= Tt * Hh) return;
    int c = i % Hh, t = i / Hh;
    int s = t % Ss, b = t / Ss;
    float acc = 0.f;
    #pragma unroll
    for (int j = 0; j < KW; j++) {
        int ss = s + j - 3;
        if (ss >= 0 && ss < Ss)
            acc = fmaf(e[((long long)(b * Ss + ss)) * Hh + c], dw[c * KW + j], acc);
    }
    bf16 h, l; split_bf(acc, h, l);
    dh[i] = h; dl[i] = l;
}

__global__ void ck_softmax(float* __restrict__ ck)
{
    int r = blockIdx.x * blockDim.x + threadIdx.x;
    if (r >= Tt * NHh) return;
    float* p = ck + (long long)r * KW;
    float m = p[0];
    #pragma unroll
    for (int j = 1; j < KW; j++) m = fmaxf(m, p[j]);
    float s = 0.f, e[KW];
    #pragma unroll
    for (int j = 0; j < KW; j++) { e[j] = expf(p[j] - m); s += e[j]; }
    float inv = 1.f / s;
    #pragma unroll
    for (int j = 0; j < KW; j++) p[j] = e[j] * inv;
}

__global__ void conv_out_kernel(const float* __restrict__ co, const float* __restrict__ ck,
                                bf16* __restrict__ cthi, bf16* __restrict__ ctlo)
{
    int i = blockIdx.x * blockDim.x + threadIdx.x;
    if (i >= Tt * AHh) return;
    int c = i % AHh, t = i / AHh;
    int h = c / HDd;
    int s = t % Ss, b = t / Ss;
    const float* ckp = ck + (long long)t * (NHh * KW) + h * KW;
    float acc = 0.f;
    #pragma unroll
    for (int j = 0; j < KW; j++) {
        int ss = s + j - 3;
        if (ss >= 0 && ss < Ss)
            acc = fmaf(co[((long long)(b * Ss + ss)) * AHh + c], ckp[j], acc);
    }
    bf16 h_, l_; split_bf(acc, h_, l_);
    cthi[(long long)t * Hh + AHh + c] = h_;
    ctlo[(long long)t * Hh + AHh + c] = l_;
}

__global__ void layernorm(const float* __restrict__ x, const float* __restrict__ g,
                          const float* __restrict__ bb, float* __restrict__ y,
                          bf16* __restrict__ hi, bf16* __restrict__ lo)
{
    long long row = blockIdx.x;
    const float* p = x + row * Hh;
    __shared__ float red[256];
    int tid = threadIdx.x;
    float s = 0.f;
    for (int i = tid; i < Hh; i += 256) s += p[i];
    red[tid] = s; __syncthreads();
    for (int o = 128; o > 0; o >>= 1) { if (tid < o) red[tid] += red[tid + o]; __syncthreads(); }
    float m = red[0] / Hh; __syncthreads();
    float v = 0.f;
    for (int i = tid; i < Hh; i += 256) { float d = p[i] - m; v += d * d; }
    red[tid] = v; __syncthreads();
    for (int o = 128; o > 0; o >>= 1) { if (tid < o) red[tid] += red[tid + o]; __syncthreads(); }
    float inv = rsqrtf(red[0] / Hh + 1e-12f);
    for (int i = tid; i < Hh; i += 256) {
        float o = (p[i] - m) * inv * g[i] + bb[i];
        y[row * Hh + i] = o;
        if (hi) { bf16 h, l; split_bf(o, h, l); hi[row * Hh + i] = h; lo[row * Hh + i] = l; }
    }
}

__global__ void maxpool_part()
{
    int i = blockIdx.x * blockDim.x + threadIdx.x;
    if (i >= Bb * 8 * Hh) return;
    int c = i % Hh, rest = i / Hh;
    int chunk = rest & 7, b = rest >> 3;
    float m = -3.4e38f;
    int sbase = chunk * 128;
    for (int s = 0; s < 128; s++)
        m = fmaxf(m, g_lo[((long long)(b * Ss + sbase + s)) * Hh + c]);
    g_poolp[i] = m;
}
__global__ void maxpool_final()
{
    int i = blockIdx.x * blockDim.x + threadIdx.x;
    if (i >= Bb * Hh) return;
    int c = i % Hh, b = i / Hh;
    float m = -3.4e38f;
    #pragma unroll
    for (int ch = 0; ch < 8; ch++)
        m = fmaxf(m, g_poolp[(b * 8 + ch) * Hh + c]);
    g_pool[i] = m;
}

__global__ void decoder_kernel(const float* __restrict__ wd, const float* __restrict__ bd,
                               float* __restrict__ out)
{
    int b = blockIdx.x;
    __shared__ float red[256];
    int tid = threadIdx.x;
    float s = 0.f;
    for (int i = tid; i < Hh; i += 256) s += g_pool[b * Hh + i] * wd[i];
    red[tid] = s; __syncthreads();
    for (int o = 128; o > 0; o >>= 1) { if (tid < o) red[tid] += red[tid + o]; __syncthreads(); }
    if (tid == 0) out[b] = red[0] + bd[0];
}

// =============================================================================
extern "C" void kernel_launch(void* const* d_in, const int* in_sizes, int n_in,
                              void* d_out, int out_size)
{
    const float* embed = (const float*)d_in[0];
    const float* wq  = (const float*)d_in[1];  const float* bq  = (const float*)d_in[2];
    const float* wk  = (const float*)d_in[3];  const float* bk  = (const float*)d_in[4];
    const float* wv  = (const float*)d_in[5];  const float* bv  = (const float*)d_in[6];
    const float* dw  = (const float*)d_in[7];
    const float* pw  = (const float*)d_in[8];  const float* sep_b = (const float*)d_in[9];
    const float* wck = (const float*)d_in[10]; const float* bck = (const float*)d_in[11];
    const float* wco = (const float*)d_in[12]; const float* bco = (const float*)d_in[13];
    const float* wso = (const float*)d_in[14]; const float* bso = (const float*)d_in[15];
    const float* ln1_g = (const float*)d_in[16]; const float* ln1_b = (const float*)d_in[17];
    const float* wi  = (const float*)d_in[18]; const float* bi  = (const float*)d_in[19];
    const float* wo  = (const float*)d_in[20]; const float* bo  = (const float*)d_in[21];
    const float* ln2_g = (const float*)d_in[22]; const float* ln2_b = (const float*)d_in[23];
    const float* wd  = (const float*)d_in[24]; const float* bd  = (const float*)d_in[25];
    float* out = (float*)d_out;

    cudaFuncSetAttribute(gemm_bf16s, cudaFuncAttributeMaxDynamicSharedMemorySize, GSMEM);
    cudaFuncSetAttribute(flash_attn, cudaFuncAttributeMaxDynamicSharedMemorySize, FA_SMEM);

    #define SYM(p, s) void* p##_; cudaGetSymbolAddress(&p##_, s); auto p = (decltype(&s[0]))p##_
    SYM(psep, g_sep); SYM(pck, g_ck); SYM(pattn, g_attn);
    SYM(ppre, g_pre); SYM(plo, g_lo);
    SYM(p4f, g_p4f); SYM(p4hi, g_p4hi); SYM(p4lo, g_p4lo);
    SYM(ehi, g_ehi); SYM(elo, g_elo);
    SYM(vThi, g_vThi); SYM(vTlo, g_vTlo);
    SYM(dchi, g_dchi); SYM(dclo, g_dclo);
    SYM(cahi, g_cahi); SYM(calo, g_calo);
    SYM(cthi, g_cthi); SYM(ctlo, g_ctlo);
    SYM(athi, g_athi); SYM(atlo, g_atlo);
    SYM(inhi, g_inhi); SYM(inlo, g_inlo);
    SYM(w4Thi, g_w4Thi); SYM(w4Tlo, g_w4Tlo);
    SYM(pwThi, g_pwThi); SYM(pwTlo, g_pwTlo);
    SYM(wckThi, g_wckThi); SYM(wckTlo, g_wckTlo);
    SYM(wsoThi, g_wsoThi); SYM(wsoTlo, g_wsoTlo);
    SYM(wiThi, g_wiThi); SYM(wiTlo, g_wiTlo);
    SYM(woThi, g_woThi); SYM(woTlo, g_woTlo);
    #undef SYM

    cudaStream_t s2;
    cudaStreamCreateWithFlags(&s2, cudaStreamNonBlocking);
    cudaEvent_t evFork, evPre, evProj, evConv;
    cudaEventCreateWithFlags(&evFork, cudaEventDisableTiming);
    cudaEventCreateWithFlags(&evPre, cudaEventDisableTiming);
    cudaEventCreateWithFlags(&evProj, cudaEventDisableTiming);
    cudaEventCreateWithFlags(&evConv, cudaEventDisableTiming);

    dim3 blk(256);
    // single-z GEMM helper
    auto gemm1 = [&](cudaStream_t st,
                     const bf16* Ah, const bf16* Al, const bf16* Bh, const bf16* Bl,
                     const float* bias, const float* resid,
                     float* Cf, bf16* Chi, bf16* Clo,
                     int M, int N, int K, int lda, int ldb, int ldc,
                     float scale, int gelu) {
        GArgs ga = {};
        ga.Ah[0] = Ah; ga.Al[0] = Al; ga.Bh[0] = Bh; ga.Bl[0] = Bl;
        ga.bias[0] = bias; ga.Cf[0] = Cf; ga.Chi[0] = Chi; ga.Clo[0] = Clo;
        ga.resid = resid;
        dim3 grid((N + 127) / 128, M / 128, 1);
        gemm_bf16s<<<grid, blk, GSMEM, st>>>(ga, N, K, lda, ldb, ldc, scale, gelu);
    };
    auto tcvt = [&](cudaStream_t st, const float* src, bf16* hiT, bf16* loT,
                    int R, int C, long long sS, long long sD, int z) {
        dim3 g((C + 31) / 32, (R + 31) / 32, z);
        transpose_cvt<<<g, dim3(32, 8), 0, st>>>(src, hiT, loT, R, C, sS, sD);
    };

    const long long WSL = (long long)AHh * Hh;

    // ---- fork ----
    cudaEventRecord(evFork, 0);
    cudaStreamWaitEvent(s2, evFork, 0);

    // ===== main stream: embed pairs + qkvco weight transposes =====
    cvt_pair<<<(Tt * Hh) / 1024, blk>>>(embed, ehi, elo, (long long)Tt * Hh);
    tcvt(0, wq, w4Thi + 0 * WSL, w4Tlo + 0 * WSL, Hh, AHh, 0, 0, 1);
    tcvt(0, wk, w4Thi + 1 * WSL, w4Tlo + 1 * WSL, Hh, AHh, 0, 0, 1);
    tcvt(0, wv, w4Thi + 2 * WSL, w4Tlo + 2 * WSL, Hh, AHh, 0, 0, 1);
    tcvt(0, wco, w4Thi + 3 * WSL, w4Tlo + 3 * WSL, Hh, AHh, 0, 0, 1);

    // ===== side stream: pw/wck transposes + depthwise conv (pre-GEMM deps) ====
    tcvt(s2, pw, pwThi, pwTlo, Hh, AHh, 0, 0, 1);
    tcvt(s2, wck, wckThi, wckTlo, AHh, NHh * KW, 0, 0, 1);
    dconv_kernel<<<(Tt * Hh + 255) / 256, blk, 0, s2>>>(embed, dw, dchi, dclo);
    cudaEventRecord(evPre, s2);
    // remaining weight transposes overlap the big GEMM
    tcvt(s2, wso, wsoThi, wsoTlo, Hh, Hh, 0, 0, 1);
    tcvt(s2, wi, wiThi, wiTlo, Hh, IMm, 0, 0, 1);
    tcvt(s2, wo, woThi, woTlo, IMm, Hh, 0, 0, 1);

    // ===== main: merged z=5 GEMM (q,k,v,co projections + pointwise conv) =====
    cudaStreamWaitEvent(0, evPre, 0);
    {
        GArgs ga = {};
        for (int z = 0; z < 4; z++) {
            ga.Ah[z] = ehi; ga.Al[z] = elo;
            ga.Bh[z] = w4Thi + z * WSL; ga.Bl[z] = w4Tlo + z * WSL;
            ga.Cf[z] = p4f + z * SLICE; ga.Chi[z] = p4hi + z * SLICE; ga.Clo[z] = p4lo + z * SLICE;
        }
        ga.bias[0] = bq; ga.bias[1] = bk; ga.bias[2] = bv; ga.bias[3] = bco;
        ga.Ah[4] = dchi; ga.Al[4] = dclo;
        ga.Bh[4] = pwThi; ga.Bl[4] = pwTlo;
        ga.bias[4] = sep_b; ga.Cf[4] = psep;
        ga.resid = nullptr;
        dim3 grid(AHh / 128, Tt / 128, 5);
        gemm_bf16s<<<grid, blk, GSMEM>>>(ga, AHh, Hh, Hh, Hh, AHh, 1.f, 0);
    }
    cudaEventRecord(evProj, 0);

    // main: attention path
    tcvt(0, p4f + 2 * SLICE, vThi, vTlo, Ss, AHh, (long long)Ss * AHh, (long long)AHh * Ss, Bb);
    flash_attn<<<dim3(Ss / 128, Bb * NHh), blk, FA_SMEM>>>(
        p4hi + 0 * SLICE, p4lo + 0 * SLICE, p4hi + 1 * SLICE, p4lo + 1 * SLICE,
        vThi, vTlo, cthi, ctlo);

    // side: dynamic conv path
    cudaStreamWaitEvent(s2, evProj, 0);
    mul_cvt<<<(Tt * AHh) / 1024, blk, 0, s2>>>(psep, p4f + 0 * SLICE, cahi, calo);
    gemm1(s2, cahi, calo, wckThi, wckTlo, bck, nullptr,
          pck, nullptr, nullptr, Tt, NHh * KW, AHh, AHh, AHh, NHh * KW, 1.f, 0);
    ck_softmax<<<(Tt * NHh + 255) / 256, blk, 0, s2>>>(pck);
    conv_out_kernel<<<(Tt * AHh + 255) / 256, blk, 0, s2>>>(p4f + 3 * SLICE, pck, cthi, ctlo);
    cudaEventRecord(evConv, s2);

    // ---- join ----
    cudaStreamWaitEvent(0, evConv, 0);

    // self output + LN1
    gemm1(0, cthi, ctlo, wsoThi, wsoTlo, bso, embed,
          ppre, nullptr, nullptr, Tt, Hh, Hh, Hh, Hh, Hh, 1.f, 0);
    layernorm<<<Tt, blk>>>(ppre, ln1_g, ln1_b, pattn, athi, atlo);

    // FFN
    gemm1(0, athi, atlo, wiThi, wiTlo, bi, nullptr,
          nullptr, inhi, inlo, Tt, IMm, Hh, Hh, Hh, IMm, 1.f, 1);
    gemm1(0, inhi, inlo, woThi, woTlo, bo, pattn,
          ppre, nullptr, nullptr, Tt, Hh, IMm, IMm, IMm, Hh, 1.f, 0);
    layernorm<<<Tt, blk>>>(ppre, ln2_g, ln2_b, plo, nullptr, nullptr);

    // pool + decode
    maxpool_part<<<(Bb * 8 * Hh + 255) / 256, blk>>>();
    maxpool_final<<<(Bb * Hh + 255) / 256, blk>>>();
    decoder_kernel<<<Bb, blk>>>(wd, bd, out);
}